// round 4
// baseline (speedup 1.0000x reference)
#include <cuda_runtime.h>
#include <cuda_bf16.h>
#include <math_constants.h>
#include <cstdint>

// Problem shape (fixed): B=4, S=4096, D=1024
#define PB 4
#define PS 4096
#define PD 1024
#define MROWS (PB * PS)   // 16384

// ---------------------------------------------------------------------------
// Global scratch (allocation-guard-safe __device__ arrays)
// ---------------------------------------------------------------------------
__device__ __nv_bfloat16 g_xh[(size_t)MROWS * PD], g_xl[(size_t)MROWS * PD];
__device__ __nv_bfloat16 g_Wqh[PD * PD], g_Wql[PD * PD];
__device__ __nv_bfloat16 g_Wkh[PD * PD], g_Wkl[PD * PD];
__device__ __nv_bfloat16 g_Wvh[PD * PD], g_Wvl[PD * PD];
__device__ __nv_bfloat16 g_Qh[(size_t)MROWS * PD], g_Ql[(size_t)MROWS * PD];
__device__ __nv_bfloat16 g_Kh[(size_t)MROWS * PD], g_Kl[(size_t)MROWS * PD];
__device__ __nv_bfloat16 g_Vh[(size_t)MROWS * PD], g_Vl[(size_t)MROWS * PD];
__device__ float         g_P [(size_t)PB * PS * PS];
__device__ __nv_bfloat16 g_Ph[(size_t)PB * PS * PS], g_Pl[(size_t)PB * PS * PS];

// ---------------------------------------------------------------------------
// PTX helpers (baseline sm_80+ features only: compile-safe under compute_103)
// ---------------------------------------------------------------------------
__device__ __forceinline__ uint32_t smem_u32(const void* p) {
    uint32_t a;
    asm("{ .reg .u64 t; cvta.to.shared.u64 t, %1; cvt.u32.u64 %0, t; }"
        : "=r"(a) : "l"(p));
    return a;
}

__device__ __forceinline__ void cp16(uint32_t s, const void* g) {
    asm volatile("cp.async.cg.shared.global [%0], [%1], 16;" :: "r"(s), "l"(g));
}
__device__ __forceinline__ void cp_commit() {
    asm volatile("cp.async.commit_group;" ::: "memory");
}
template<int N>
__device__ __forceinline__ void cp_wait() {
    asm volatile("cp.async.wait_group %0;" :: "n"(N) : "memory");
}

__device__ __forceinline__ void ldsm_x4(uint32_t a, uint32_t* r) {
    asm volatile("ldmatrix.sync.aligned.m8n8.x4.shared.b16 {%0,%1,%2,%3}, [%4];"
                 : "=r"(r[0]), "=r"(r[1]), "=r"(r[2]), "=r"(r[3]) : "r"(a));
}
__device__ __forceinline__ void ldsm_x4_t(uint32_t a, uint32_t* r) {
    asm volatile("ldmatrix.sync.aligned.m8n8.x4.trans.shared.b16 {%0,%1,%2,%3}, [%4];"
                 : "=r"(r[0]), "=r"(r[1]), "=r"(r[2]), "=r"(r[3]) : "r"(a));
}

__device__ __forceinline__ void mma_bf16(float* c, const uint32_t* a,
                                         const uint32_t* b) {
    asm volatile(
        "mma.sync.aligned.m16n8k16.row.col.f32.bf16.bf16.f32 "
        "{%0,%1,%2,%3},{%4,%5,%6,%7},{%8,%9},{%0,%1,%2,%3};"
        : "+f"(c[0]), "+f"(c[1]), "+f"(c[2]), "+f"(c[3])
        : "r"(a[0]), "r"(a[1]), "r"(a[2]), "r"(a[3]), "r"(b[0]), "r"(b[1]));
}

__device__ __forceinline__ void split1(float v, __nv_bfloat16& h, __nv_bfloat16& l) {
    h = __float2bfloat16(v);
    l = __float2bfloat16(v - __bfloat162float(h));
}

// ---------------------------------------------------------------------------
// Tiling: block 128x128, BK=32, 8 warps each 32(M) x 64(N).
// SMEM per stage: A hi/lo 128x80B = 2*10240; B (NT) same, or B (BT) 2*8704.
// 3 stages, cp.async wait_group<1> -> two chunk loads in flight.
// ---------------------------------------------------------------------------
#define STAGE_STRIDE 40960
#define NSTAGE 3
#define SMEM_BYTES (NSTAGE * STAGE_STRIDE)   // 122880

// Per-z operand set for the merged projection launch.
struct ProjSet {
    const __nv_bfloat16* Bh;
    const __nv_bfloat16* Bl;
    const float* bias;
    __nv_bfloat16* Ch;
    __nv_bfloat16* Cl;
};
struct ProjArgs { ProjSet s[3]; };

// MODE 0: C = split bf16 + bias (projections; z selects W via ProjArgs)
// MODE 2: C = fp32 * scale      (scores, PV output)
// BT: B stored [K,N] row-major -> ldmatrix.trans path.
template<int MODE, bool BT>
__global__ void __launch_bounds__(256, 1)
gemm_mma(const __nv_bfloat16* __restrict__ Ah, const __nv_bfloat16* __restrict__ Al,
         const __nv_bfloat16* __restrict__ Bh_, const __nv_bfloat16* __restrict__ Bl_,
         ProjArgs pa,
         float* __restrict__ Cf,
         int K, int ldb, int ldc, float scale,
         size_t sA, size_t sB, size_t sC)
{
    extern __shared__ char smem[];
    const uint32_t sb0 = smem_u32(smem);
    const int tid  = threadIdx.x;
    const int lane = tid & 31;
    const int wid  = tid >> 5;
    const int warp_m = wid & 3;
    const int warp_n = wid >> 2;

    const __nv_bfloat16* Bh;
    const __nv_bfloat16* Bl;
    const float* bias = nullptr;
    __nv_bfloat16 *Ch = nullptr, *Cl = nullptr;
    if (MODE == 0) {
        const ProjSet& s = pa.s[blockIdx.z];
        Bh = s.Bh; Bl = s.Bl; bias = s.bias; Ch = s.Ch; Cl = s.Cl;
    } else {
        Bh = Bh_ + (size_t)blockIdx.z * sB;
        Bl = Bl_ + (size_t)blockIdx.z * sB;
        Ah += (size_t)blockIdx.z * sA;
        Al += (size_t)blockIdx.z * sA;
    }

    const int row0 = blockIdx.y * 128;
    const int col0 = blockIdx.x * 128;

    float acc[2][8][4];
#pragma unroll
    for (int i = 0; i < 2; i++)
#pragma unroll
        for (int n = 0; n < 8; n++)
#pragma unroll
            for (int j = 0; j < 4; j++) acc[i][n][j] = 0.0f;

    const int nk = K >> 5;   // BK = 32

    // ---------------- stage loader ----------------
    auto load_stage = [&](int stage, int ki) {
        const uint32_t sb = sb0 + stage * STAGE_STRIDE;
        const int k0 = ki << 5;
        // A: 1024 x 16B chunks (hi 512 + lo 512), 4 per thread
#pragma unroll
        for (int it = 0; it < 4; it++) {
            int idx = tid + (it << 8);
            int hl  = idx >> 9;
            int e   = idx & 511;
            int r   = e >> 2;
            int c4  = e & 3;
            const __nv_bfloat16* src = hl ? Al : Ah;
            cp16(sb + hl * 10240 + r * 80 + c4 * 16,
                 src + (size_t)(row0 + r) * K + k0 + c4 * 8);
        }
        if (!BT) {
#pragma unroll
            for (int it = 0; it < 4; it++) {
                int idx = tid + (it << 8);
                int hl  = idx >> 9;
                int e   = idx & 511;
                int r   = e >> 2;
                int c4  = e & 3;
                const __nv_bfloat16* src = hl ? Bl : Bh;
                cp16(sb + 20480 + hl * 10240 + r * 80 + c4 * 16,
                     src + (size_t)(col0 + r) * ldb + k0 + c4 * 8);
            }
        } else {
#pragma unroll
            for (int it = 0; it < 4; it++) {
                int idx = tid + (it << 8);
                int hl  = idx >> 9;
                int e   = idx & 511;
                int r   = e >> 4;
                int c16 = e & 15;
                const __nv_bfloat16* src = hl ? Bl : Bh;
                cp16(sb + 20480 + hl * 8704 + r * 272 + c16 * 16,
                     src + (size_t)(k0 + r) * ldb + col0 + c16 * 8);
            }
        }
        cp_commit();
    };

    // ---------------- mainloop (3-stage, 2 loads in flight) ----------------
    load_stage(0, 0);
    if (nk > 1) load_stage(1, 1);
    cp_wait<1>();
    __syncthreads();

    int s_cur = 0;
    for (int i = 0; i < nk; i++) {
        if (i + 2 < nk) {
            int s_nxt = s_cur + 2;
            if (s_nxt >= NSTAGE) s_nxt -= NSTAGE;
            load_stage(s_nxt, i + 2);
        }

        const uint32_t sA0 = sb0 + s_cur * STAGE_STRIDE;
        const uint32_t sB0 = sA0 + 20480;

#pragma unroll
        for (int kk = 0; kk < 2; kk++) {
            const int k16 = kk << 4;

            uint32_t ah[2][4], al[2][4];
#pragma unroll
            for (int mi = 0; mi < 2; mi++) {
                int m = warp_m * 32 + mi * 16 + (lane & 15);
                int k = k16 + ((lane & 16) ? 8 : 0);
                ldsm_x4(sA0 +         m * 80 + k * 2, ah[mi]);
                ldsm_x4(sA0 + 10240 + m * 80 + k * 2, al[mi]);
            }

            uint32_t bh[8][2], bl[8][2];
#pragma unroll
            for (int nt = 0; nt < 4; nt++) {
                uint32_t r4[4];
                if (!BT) {
                    int n = warp_n * 64 + nt * 16 + ((lane & 16) ? 8 : 0) + (lane & 7);
                    int k = k16 + (lane & 8);
                    ldsm_x4(sB0 +         n * 80 + k * 2, r4);
                    bh[2 * nt][0] = r4[0]; bh[2 * nt][1] = r4[1];
                    bh[2 * nt + 1][0] = r4[2]; bh[2 * nt + 1][1] = r4[3];
                    ldsm_x4(sB0 + 10240 + n * 80 + k * 2, r4);
                    bl[2 * nt][0] = r4[0]; bl[2 * nt][1] = r4[1];
                    bl[2 * nt + 1][0] = r4[2]; bl[2 * nt + 1][1] = r4[3];
                } else {
                    int k = k16 + (lane & 15);
                    int n = warp_n * 64 + nt * 16 + ((lane & 16) ? 8 : 0);
                    ldsm_x4_t(sB0 +        k * 272 + n * 2, r4);
                    bh[2 * nt][0] = r4[0]; bh[2 * nt][1] = r4[1];
                    bh[2 * nt + 1][0] = r4[2]; bh[2 * nt + 1][1] = r4[3];
                    ldsm_x4_t(sB0 + 8704 + k * 272 + n * 2, r4);
                    bl[2 * nt][0] = r4[0]; bl[2 * nt][1] = r4[1];
                    bl[2 * nt + 1][0] = r4[2]; bl[2 * nt + 1][1] = r4[3];
                }
            }

#pragma unroll
            for (int mi = 0; mi < 2; mi++)
#pragma unroll
                for (int n = 0; n < 8; n++) {
                    mma_bf16(acc[mi][n], ah[mi], bh[n]);
                    mma_bf16(acc[mi][n], ah[mi], bl[n]);
                    mma_bf16(acc[mi][n], al[mi], bh[n]);
                }
        }

        if (i + 1 < nk) {
            cp_wait<1>();
            __syncthreads();
        }
        s_cur++;
        if (s_cur == NSTAGE) s_cur = 0;
    }

    // ---------------- epilogue ----------------
#pragma unroll
    for (int mi = 0; mi < 2; mi++) {
        const int rbase = row0 + warp_m * 32 + mi * 16 + (lane >> 2);
#pragma unroll
        for (int n = 0; n < 8; n++) {
            const int cb = col0 + warp_n * 64 + n * 8 + 2 * (lane & 3);
            if (MODE == 2) {
                float* base = Cf + (size_t)blockIdx.z * sC;
                float2 v0 = make_float2(acc[mi][n][0] * scale, acc[mi][n][1] * scale);
                float2 v1 = make_float2(acc[mi][n][2] * scale, acc[mi][n][3] * scale);
                *reinterpret_cast<float2*>(base + (size_t)rbase * ldc + cb) = v0;
                *reinterpret_cast<float2*>(base + (size_t)(rbase + 8) * ldc + cb) = v1;
            } else {
                float b0 = bias[cb], b1 = bias[cb + 1];
                __nv_bfloat16 h0, l0, h1, l1, h2, l2, h3, l3;
                split1(acc[mi][n][0] + b0, h0, l0);
                split1(acc[mi][n][1] + b1, h1, l1);
                split1(acc[mi][n][2] + b0, h2, l2);
                split1(acc[mi][n][3] + b1, h3, l3);
                *reinterpret_cast<__nv_bfloat162*>(Ch + (size_t)rbase * ldc + cb)
                    = __nv_bfloat162(h0, h1);
                *reinterpret_cast<__nv_bfloat162*>(Cl + (size_t)rbase * ldc + cb)
                    = __nv_bfloat162(l0, l1);
                *reinterpret_cast<__nv_bfloat162*>(Ch + (size_t)(rbase + 8) * ldc + cb)
                    = __nv_bfloat162(h2, h3);
                *reinterpret_cast<__nv_bfloat162*>(Cl + (size_t)(rbase + 8) * ldc + cb)
                    = __nv_bfloat162(l2, l3);
            }
        }
    }
}

// ---------------------------------------------------------------------------
// fp32 -> bf16 hi/lo split (elementwise)
// ---------------------------------------------------------------------------
__global__ void __launch_bounds__(256)
split_kernel(const float* __restrict__ in, __nv_bfloat16* __restrict__ hi,
             __nv_bfloat16* __restrict__ lo, size_t n4)
{
    size_t i = (size_t)blockIdx.x * blockDim.x + threadIdx.x;
    if (i >= n4) return;
    float4 v = reinterpret_cast<const float4*>(in)[i];
    float vv[4] = { v.x, v.y, v.z, v.w };
    uint32_t H[2], L[2];
#pragma unroll
    for (int j = 0; j < 2; j++) {
        __nv_bfloat16 h0, l0, h1, l1;
        split1(vv[2 * j],     h0, l0);
        split1(vv[2 * j + 1], h1, l1);
        H[j] = (uint32_t)__bfloat16_as_ushort(h0) |
               ((uint32_t)__bfloat16_as_ushort(h1) << 16);
        L[j] = (uint32_t)__bfloat16_as_ushort(l0) |
               ((uint32_t)__bfloat16_as_ushort(l1) << 16);
    }
    reinterpret_cast<uint2*>(hi)[i] = make_uint2(H[0], H[1]);
    reinterpret_cast<uint2*>(lo)[i] = make_uint2(L[0], L[1]);
}

// ---------------------------------------------------------------------------
// Row softmax: fp32 in -> split bf16 out. One block per row of 4096.
// ---------------------------------------------------------------------------
__global__ void __launch_bounds__(256)
softmax_kernel(const float* __restrict__ P, __nv_bfloat16* __restrict__ Ph,
               __nv_bfloat16* __restrict__ Pl)
{
    const float* row = P + (size_t)blockIdx.x * PS;
    __nv_bfloat16* oh = Ph + (size_t)blockIdx.x * PS;
    __nv_bfloat16* ol = Pl + (size_t)blockIdx.x * PS;
    const int tid  = threadIdx.x;
    const int lane = tid & 31;
    const int warp = tid >> 5;

    float v[16];
    float m = -CUDART_INF_F;
#pragma unroll
    for (int i = 0; i < 16; i++) {
        v[i] = row[tid + i * 256];
        m = fmaxf(m, v[i]);
    }
    __shared__ float red[8];
#pragma unroll
    for (int o = 16; o > 0; o >>= 1)
        m = fmaxf(m, __shfl_xor_sync(0xffffffffu, m, o));
    if (lane == 0) red[warp] = m;
    __syncthreads();
    float bm = red[0];
#pragma unroll
    for (int w = 1; w < 8; w++) bm = fmaxf(bm, red[w]);
    __syncthreads();

    float s = 0.0f;
#pragma unroll
    for (int i = 0; i < 16; i++) {
        v[i] = __expf(v[i] - bm);
        s += v[i];
    }
#pragma unroll
    for (int o = 16; o > 0; o >>= 1)
        s += __shfl_xor_sync(0xffffffffu, s, o);
    if (lane == 0) red[warp] = s;
    __syncthreads();
    float bs = red[0];
#pragma unroll
    for (int w = 1; w < 8; w++) bs += red[w];

    float inv = 1.0f / bs;
#pragma unroll
    for (int i = 0; i < 16; i++) {
        float o = v[i] * inv;
        __nv_bfloat16 h, l;
        split1(o, h, l);
        oh[tid + i * 256] = h;
        ol[tid + i * 256] = l;
    }
}

// ---------------------------------------------------------------------------
// Launcher
// ---------------------------------------------------------------------------
extern "C" void kernel_launch(void* const* d_in, const int* in_sizes, int n_in,
                              void* d_out, int out_size)
{
    (void)in_sizes; (void)n_in; (void)out_size;
    const float* x  = (const float*)d_in[0];
    const float* Wq = (const float*)d_in[1];
    const float* bq = (const float*)d_in[2];
    const float* Wk = (const float*)d_in[3];
    const float* bk = (const float*)d_in[4];
    const float* Wv = (const float*)d_in[5];
    const float* bv = (const float*)d_in[6];
    float* out = (float*)d_out;

    __nv_bfloat16 *xh, *xl, *Wqh, *Wql, *Wkh, *Wkl, *Wvh, *Wvl;
    __nv_bfloat16 *Qh, *Ql, *Kh, *Kl, *Vh, *Vl, *Ph, *Pl;
    float* P;
    cudaGetSymbolAddress((void**)&xh,  g_xh);
    cudaGetSymbolAddress((void**)&xl,  g_xl);
    cudaGetSymbolAddress((void**)&Wqh, g_Wqh);
    cudaGetSymbolAddress((void**)&Wql, g_Wql);
    cudaGetSymbolAddress((void**)&Wkh, g_Wkh);
    cudaGetSymbolAddress((void**)&Wkl, g_Wkl);
    cudaGetSymbolAddress((void**)&Wvh, g_Wvh);
    cudaGetSymbolAddress((void**)&Wvl, g_Wvl);
    cudaGetSymbolAddress((void**)&Qh,  g_Qh);
    cudaGetSymbolAddress((void**)&Ql,  g_Ql);
    cudaGetSymbolAddress((void**)&Kh,  g_Kh);
    cudaGetSymbolAddress((void**)&Kl,  g_Kl);
    cudaGetSymbolAddress((void**)&Vh,  g_Vh);
    cudaGetSymbolAddress((void**)&Vl,  g_Vl);
    cudaGetSymbolAddress((void**)&P,   g_P);
    cudaGetSymbolAddress((void**)&Ph,  g_Ph);
    cudaGetSymbolAddress((void**)&Pl,  g_Pl);

    cudaFuncSetAttribute((const void*)gemm_mma<0, false>,
                         cudaFuncAttributeMaxDynamicSharedMemorySize, SMEM_BYTES);
    cudaFuncSetAttribute((const void*)gemm_mma<2, false>,
                         cudaFuncAttributeMaxDynamicSharedMemorySize, SMEM_BYTES);
    cudaFuncSetAttribute((const void*)gemm_mma<2, true>,
                         cudaFuncAttributeMaxDynamicSharedMemorySize, SMEM_BYTES);

    const size_t SD = (size_t)PS * PD;   // 4M elems per batch
    const size_t SS = (size_t)PS * PS;   // 16M elems per batch

    // 1) splits
    split_kernel<<<16384, 256>>>(x,  xh,  xl,  (size_t)MROWS * PD / 4);
    split_kernel<<<1024,  256>>>(Wq, Wqh, Wql, (size_t)PD * PD / 4);
    split_kernel<<<1024,  256>>>(Wk, Wkh, Wkl, (size_t)PD * PD / 4);
    split_kernel<<<1024,  256>>>(Wv, Wvh, Wvl, (size_t)PD * PD / 4);

    // 2) merged projections: z=0/1/2 -> Q/K/V
    ProjArgs pa;
    pa.s[0] = { Wqh, Wql, bq, Qh, Ql };
    pa.s[1] = { Wkh, Wkl, bk, Kh, Kl };
    pa.s[2] = { Wvh, Wvl, bv, Vh, Vl };
    dim3 gp(PD / 128, MROWS / 128, 3);
    gemm_mma<0, false><<<gp, 256, SMEM_BYTES>>>(
        xh, xl, nullptr, nullptr, pa, nullptr, PD, PD, PD, 1.0f, 0, 0, 0);

    // 3) scores: P[b] = Q[b] @ K[b]^T / 32  (NT)
    ProjArgs dummy = {};
    dim3 gs(PS / 128, PS / 128, PB);
    gemm_mma<2, false><<<gs, 256, SMEM_BYTES>>>(
        Qh, Ql, Kh, Kl, dummy, P, PD, PD, PS, 0.03125f, SD, SD, SS);

    // 4) softmax -> split bf16 P
    softmax_kernel<<<PB * PS, 256>>>(P, Ph, Pl);

    // 5) out[b] = P[b] @ V[b]  (NN: B is [K=S, N=D] row-major -> BT path)
    dim3 go(PD / 128, PS / 128, PB);
    gemm_mma<2, true><<<go, 256, SMEM_BYTES>>>(
        Ph, Pl, Vh, Vl, dummy, out, PS, PD, PD, 1.0f, SS, SD, SD);
}

// round 5
// speedup vs baseline: 1.1832x; 1.1832x over previous
#include <cuda_runtime.h>
#include <cuda_bf16.h>
#include <math_constants.h>
#include <cstdint>

// Problem shape (fixed): B=4, S=4096, D=1024
#define PB 4
#define PS 4096
#define PD 1024
#define MROWS (PB * PS)   // 16384

// ---------------------------------------------------------------------------
// Global scratch (allocation-guard-safe __device__ arrays)
// ---------------------------------------------------------------------------
__device__ __nv_bfloat16 g_xh[(size_t)MROWS * PD], g_xl[(size_t)MROWS * PD];
__device__ __nv_bfloat16 g_Wqh[PD * PD], g_Wql[PD * PD];
__device__ __nv_bfloat16 g_Wkh[PD * PD], g_Wkl[PD * PD];
__device__ __nv_bfloat16 g_Wvh[PD * PD], g_Wvl[PD * PD];
__device__ __nv_bfloat16 g_Qh[(size_t)MROWS * PD], g_Ql[(size_t)MROWS * PD];
__device__ __nv_bfloat16 g_Kh[(size_t)MROWS * PD], g_Kl[(size_t)MROWS * PD];
__device__ __nv_bfloat16 g_Vh[(size_t)MROWS * PD], g_Vl[(size_t)MROWS * PD];
__device__ float         g_P [(size_t)PB * PS * PS];
__device__ __nv_bfloat16 g_Ph[(size_t)PB * PS * PS], g_Pl[(size_t)PB * PS * PS];

// ---------------------------------------------------------------------------
// PTX helpers (baseline sm_80+ features only: compile-safe under compute_103)
// ---------------------------------------------------------------------------
__device__ __forceinline__ uint32_t smem_u32(const void* p) {
    uint32_t a;
    asm("{ .reg .u64 t; cvta.to.shared.u64 t, %1; cvt.u32.u64 %0, t; }"
        : "=r"(a) : "l"(p));
    return a;
}

__device__ __forceinline__ void cp16(uint32_t s, const void* g) {
    asm volatile("cp.async.cg.shared.global [%0], [%1], 16;" :: "r"(s), "l"(g));
}
__device__ __forceinline__ void cp_commit() {
    asm volatile("cp.async.commit_group;" ::: "memory");
}
template<int N>
__device__ __forceinline__ void cp_wait() {
    asm volatile("cp.async.wait_group %0;" :: "n"(N) : "memory");
}

__device__ __forceinline__ void ldsm_x4(uint32_t a, uint32_t* r) {
    asm volatile("ldmatrix.sync.aligned.m8n8.x4.shared.b16 {%0,%1,%2,%3}, [%4];"
                 : "=r"(r[0]), "=r"(r[1]), "=r"(r[2]), "=r"(r[3]) : "r"(a));
}
__device__ __forceinline__ void ldsm_x4_t(uint32_t a, uint32_t* r) {
    asm volatile("ldmatrix.sync.aligned.m8n8.x4.trans.shared.b16 {%0,%1,%2,%3}, [%4];"
                 : "=r"(r[0]), "=r"(r[1]), "=r"(r[2]), "=r"(r[3]) : "r"(a));
}

__device__ __forceinline__ void mma_bf16(float* c, const uint32_t* a,
                                         const uint32_t* b) {
    asm volatile(
        "mma.sync.aligned.m16n8k16.row.col.f32.bf16.bf16.f32 "
        "{%0,%1,%2,%3},{%4,%5,%6,%7},{%8,%9},{%0,%1,%2,%3};"
        : "+f"(c[0]), "+f"(c[1]), "+f"(c[2]), "+f"(c[3])
        : "r"(a[0]), "r"(a[1]), "r"(a[2]), "r"(a[3]), "r"(b[0]), "r"(b[1]));
}

__device__ __forceinline__ void split1(float v, __nv_bfloat16& h, __nv_bfloat16& l) {
    h = __float2bfloat16(v);
    l = __float2bfloat16(v - __bfloat162float(h));
}

// ---------------------------------------------------------------------------
// Tiling: block 128x128, BK=32, 8 warps each 32(M) x 64(N).
// SMEM per stage: A hi/lo 128x80B = 2*10240; B (NT) same, or B (BT) 2*8704.
// 2 stages x 40960B = 80KB/CTA -> 2 CTAs per SM (the point of this round).
// ---------------------------------------------------------------------------
#define STAGE_STRIDE 40960
#define NSTAGE 2
#define SMEM_BYTES (NSTAGE * STAGE_STRIDE)   // 81920

// Per-z operand set for the merged projection launch.
struct ProjSet {
    const __nv_bfloat16* Bh;
    const __nv_bfloat16* Bl;
    const float* bias;
    __nv_bfloat16* Ch;
    __nv_bfloat16* Cl;
};
struct ProjArgs { ProjSet s[3]; };

// MODE 0: C = split bf16 + bias (projections; z selects W via ProjArgs)
// MODE 2: C = fp32 * scale      (scores, PV output)
// BT: B stored [K,N] row-major -> ldmatrix.trans path.
template<int MODE, bool BT>
__global__ void __launch_bounds__(256, 2)
gemm_mma(const __nv_bfloat16* __restrict__ Ah, const __nv_bfloat16* __restrict__ Al,
         const __nv_bfloat16* __restrict__ Bh_, const __nv_bfloat16* __restrict__ Bl_,
         ProjArgs pa,
         float* __restrict__ Cf,
         int K, int ldb, int ldc, float scale,
         size_t sA, size_t sB, size_t sC)
{
    extern __shared__ char smem[];
    const uint32_t sb0 = smem_u32(smem);
    const int tid  = threadIdx.x;
    const int lane = tid & 31;
    const int wid  = tid >> 5;
    const int warp_m = wid & 3;
    const int warp_n = wid >> 2;

    const __nv_bfloat16* Bh;
    const __nv_bfloat16* Bl;
    const float* bias = nullptr;
    __nv_bfloat16 *Ch = nullptr, *Cl = nullptr;
    if (MODE == 0) {
        const ProjSet& s = pa.s[blockIdx.z];
        Bh = s.Bh; Bl = s.Bl; bias = s.bias; Ch = s.Ch; Cl = s.Cl;
    } else {
        Bh = Bh_ + (size_t)blockIdx.z * sB;
        Bl = Bl_ + (size_t)blockIdx.z * sB;
        Ah += (size_t)blockIdx.z * sA;
        Al += (size_t)blockIdx.z * sA;
    }

    const int row0 = blockIdx.y * 128;
    const int col0 = blockIdx.x * 128;

    float acc[2][8][4];
#pragma unroll
    for (int i = 0; i < 2; i++)
#pragma unroll
        for (int n = 0; n < 8; n++)
#pragma unroll
            for (int j = 0; j < 4; j++) acc[i][n][j] = 0.0f;

    const int nk = K >> 5;   // BK = 32

    // ---------------- stage loader ----------------
    auto load_stage = [&](int stage, int ki) {
        const uint32_t sb = sb0 + stage * STAGE_STRIDE;
        const int k0 = ki << 5;
        // A: 1024 x 16B chunks (hi 512 + lo 512), 4 per thread
#pragma unroll
        for (int it = 0; it < 4; it++) {
            int idx = tid + (it << 8);
            int hl  = idx >> 9;
            int e   = idx & 511;
            int r   = e >> 2;
            int c4  = e & 3;
            const __nv_bfloat16* src = hl ? Al : Ah;
            cp16(sb + hl * 10240 + r * 80 + c4 * 16,
                 src + (size_t)(row0 + r) * K + k0 + c4 * 8);
        }
        if (!BT) {
#pragma unroll
            for (int it = 0; it < 4; it++) {
                int idx = tid + (it << 8);
                int hl  = idx >> 9;
                int e   = idx & 511;
                int r   = e >> 2;
                int c4  = e & 3;
                const __nv_bfloat16* src = hl ? Bl : Bh;
                cp16(sb + 20480 + hl * 10240 + r * 80 + c4 * 16,
                     src + (size_t)(col0 + r) * ldb + k0 + c4 * 8);
            }
        } else {
#pragma unroll
            for (int it = 0; it < 4; it++) {
                int idx = tid + (it << 8);
                int hl  = idx >> 9;
                int e   = idx & 511;
                int r   = e >> 4;
                int c16 = e & 15;
                const __nv_bfloat16* src = hl ? Bl : Bh;
                cp16(sb + 20480 + hl * 8704 + r * 272 + c16 * 16,
                     src + (size_t)(k0 + r) * ldb + col0 + c16 * 8);
            }
        }
        cp_commit();
    };

    // ---------------- mainloop (2-stage; cross-CTA overlap via occupancy) ---
    load_stage(0, 0);
    cp_wait<0>();
    __syncthreads();

    for (int i = 0; i < nk; i++) {
        if (i + 1 < nk) load_stage((i + 1) & 1, i + 1);

        const uint32_t sA0 = sb0 + (i & 1) * STAGE_STRIDE;
        const uint32_t sB0 = sA0 + 20480;

#pragma unroll
        for (int kk = 0; kk < 2; kk++) {
            const int k16 = kk << 4;

            uint32_t ah[2][4], al[2][4];
#pragma unroll
            for (int mi = 0; mi < 2; mi++) {
                int m = warp_m * 32 + mi * 16 + (lane & 15);
                int k = k16 + ((lane & 16) ? 8 : 0);
                ldsm_x4(sA0 +         m * 80 + k * 2, ah[mi]);
                ldsm_x4(sA0 + 10240 + m * 80 + k * 2, al[mi]);
            }

            // B fragments in 4 groups of 2 n8-tiles: keeps live B regs at 8
#pragma unroll
            for (int nt = 0; nt < 4; nt++) {
                uint32_t bh2[4], bl2[4];
                if (!BT) {
                    int n = warp_n * 64 + nt * 16 + ((lane & 16) ? 8 : 0) + (lane & 7);
                    int k = k16 + (lane & 8);
                    ldsm_x4(sB0 +         n * 80 + k * 2, bh2);
                    ldsm_x4(sB0 + 10240 + n * 80 + k * 2, bl2);
                } else {
                    int k = k16 + (lane & 15);
                    int n = warp_n * 64 + nt * 16 + ((lane & 16) ? 8 : 0);
                    ldsm_x4_t(sB0 +        k * 272 + n * 2, bh2);
                    ldsm_x4_t(sB0 + 8704 + k * 272 + n * 2, bl2);
                }
#pragma unroll
                for (int mi = 0; mi < 2; mi++)
#pragma unroll
                    for (int nn = 0; nn < 2; nn++) {
                        float* a = acc[mi][2 * nt + nn];
                        mma_bf16(a, ah[mi], bh2 + 2 * nn);
                        mma_bf16(a, ah[mi], bl2 + 2 * nn);
                        mma_bf16(a, al[mi], bh2 + 2 * nn);
                    }
            }
        }

        if (i + 1 < nk) {
            cp_wait<0>();
            __syncthreads();
        }
    }

    // ---------------- epilogue ----------------
#pragma unroll
    for (int mi = 0; mi < 2; mi++) {
        const int rbase = row0 + warp_m * 32 + mi * 16 + (lane >> 2);
#pragma unroll
        for (int n = 0; n < 8; n++) {
            const int cb = col0 + warp_n * 64 + n * 8 + 2 * (lane & 3);
            if (MODE == 2) {
                float* base = Cf + (size_t)blockIdx.z * sC;
                float2 v0 = make_float2(acc[mi][n][0] * scale, acc[mi][n][1] * scale);
                float2 v1 = make_float2(acc[mi][n][2] * scale, acc[mi][n][3] * scale);
                *reinterpret_cast<float2*>(base + (size_t)rbase * ldc + cb) = v0;
                *reinterpret_cast<float2*>(base + (size_t)(rbase + 8) * ldc + cb) = v1;
            } else {
                float b0 = bias[cb], b1 = bias[cb + 1];
                __nv_bfloat16 h0, l0, h1, l1, h2, l2, h3, l3;
                split1(acc[mi][n][0] + b0, h0, l0);
                split1(acc[mi][n][1] + b1, h1, l1);
                split1(acc[mi][n][2] + b0, h2, l2);
                split1(acc[mi][n][3] + b1, h3, l3);
                *reinterpret_cast<__nv_bfloat162*>(Ch + (size_t)rbase * ldc + cb)
                    = __nv_bfloat162(h0, h1);
                *reinterpret_cast<__nv_bfloat162*>(Cl + (size_t)rbase * ldc + cb)
                    = __nv_bfloat162(l0, l1);
                *reinterpret_cast<__nv_bfloat162*>(Ch + (size_t)(rbase + 8) * ldc + cb)
                    = __nv_bfloat162(h2, h3);
                *reinterpret_cast<__nv_bfloat162*>(Cl + (size_t)(rbase + 8) * ldc + cb)
                    = __nv_bfloat162(l2, l3);
            }
        }
    }
}

// ---------------------------------------------------------------------------
// fp32 -> bf16 hi/lo split (elementwise)
// ---------------------------------------------------------------------------
__global__ void __launch_bounds__(256)
split_kernel(const float* __restrict__ in, __nv_bfloat16* __restrict__ hi,
             __nv_bfloat16* __restrict__ lo, size_t n4)
{
    size_t i = (size_t)blockIdx.x * blockDim.x + threadIdx.x;
    if (i >= n4) return;
    float4 v = reinterpret_cast<const float4*>(in)[i];
    float vv[4] = { v.x, v.y, v.z, v.w };
    uint32_t H[2], L[2];
#pragma unroll
    for (int j = 0; j < 2; j++) {
        __nv_bfloat16 h0, l0, h1, l1;
        split1(vv[2 * j],     h0, l0);
        split1(vv[2 * j + 1], h1, l1);
        H[j] = (uint32_t)__bfloat16_as_ushort(h0) |
               ((uint32_t)__bfloat16_as_ushort(h1) << 16);
        L[j] = (uint32_t)__bfloat16_as_ushort(l0) |
               ((uint32_t)__bfloat16_as_ushort(l1) << 16);
    }
    reinterpret_cast<uint2*>(hi)[i] = make_uint2(H[0], H[1]);
    reinterpret_cast<uint2*>(lo)[i] = make_uint2(L[0], L[1]);
}

// ---------------------------------------------------------------------------
// Row softmax: fp32 in -> split bf16 out. One block per row of 4096.
// ---------------------------------------------------------------------------
__global__ void __launch_bounds__(256)
softmax_kernel(const float* __restrict__ P, __nv_bfloat16* __restrict__ Ph,
               __nv_bfloat16* __restrict__ Pl)
{
    const float* row = P + (size_t)blockIdx.x * PS;
    __nv_bfloat16* oh = Ph + (size_t)blockIdx.x * PS;
    __nv_bfloat16* ol = Pl + (size_t)blockIdx.x * PS;
    const int tid  = threadIdx.x;
    const int lane = tid & 31;
    const int warp = tid >> 5;

    float v[16];
    float m = -CUDART_INF_F;
#pragma unroll
    for (int i = 0; i < 16; i++) {
        v[i] = row[tid + i * 256];
        m = fmaxf(m, v[i]);
    }
    __shared__ float red[8];
#pragma unroll
    for (int o = 16; o > 0; o >>= 1)
        m = fmaxf(m, __shfl_xor_sync(0xffffffffu, m, o));
    if (lane == 0) red[warp] = m;
    __syncthreads();
    float bm = red[0];
#pragma unroll
    for (int w = 1; w < 8; w++) bm = fmaxf(bm, red[w]);
    __syncthreads();

    float s = 0.0f;
#pragma unroll
    for (int i = 0; i < 16; i++) {
        v[i] = __expf(v[i] - bm);
        s += v[i];
    }
#pragma unroll
    for (int o = 16; o > 0; o >>= 1)
        s += __shfl_xor_sync(0xffffffffu, s, o);
    if (lane == 0) red[warp] = s;
    __syncthreads();
    float bs = red[0];
#pragma unroll
    for (int w = 1; w < 8; w++) bs += red[w];

    float inv = 1.0f / bs;
#pragma unroll
    for (int i = 0; i < 16; i++) {
        float o = v[i] * inv;
        __nv_bfloat16 h, l;
        split1(o, h, l);
        oh[tid + i * 256] = h;
        ol[tid + i * 256] = l;
    }
}

// ---------------------------------------------------------------------------
// Launcher
// ---------------------------------------------------------------------------
extern "C" void kernel_launch(void* const* d_in, const int* in_sizes, int n_in,
                              void* d_out, int out_size)
{
    (void)in_sizes; (void)n_in; (void)out_size;
    const float* x  = (const float*)d_in[0];
    const float* Wq = (const float*)d_in[1];
    const float* bq = (const float*)d_in[2];
    const float* Wk = (const float*)d_in[3];
    const float* bk = (const float*)d_in[4];
    const float* Wv = (const float*)d_in[5];
    const float* bv = (const float*)d_in[6];
    float* out = (float*)d_out;

    __nv_bfloat16 *xh, *xl, *Wqh, *Wql, *Wkh, *Wkl, *Wvh, *Wvl;
    __nv_bfloat16 *Qh, *Ql, *Kh, *Kl, *Vh, *Vl, *Ph, *Pl;
    float* P;
    cudaGetSymbolAddress((void**)&xh,  g_xh);
    cudaGetSymbolAddress((void**)&xl,  g_xl);
    cudaGetSymbolAddress((void**)&Wqh, g_Wqh);
    cudaGetSymbolAddress((void**)&Wql, g_Wql);
    cudaGetSymbolAddress((void**)&Wkh, g_Wkh);
    cudaGetSymbolAddress((void**)&Wkl, g_Wkl);
    cudaGetSymbolAddress((void**)&Wvh, g_Wvh);
    cudaGetSymbolAddress((void**)&Wvl, g_Wvl);
    cudaGetSymbolAddress((void**)&Qh,  g_Qh);
    cudaGetSymbolAddress((void**)&Ql,  g_Ql);
    cudaGetSymbolAddress((void**)&Kh,  g_Kh);
    cudaGetSymbolAddress((void**)&Kl,  g_Kl);
    cudaGetSymbolAddress((void**)&Vh,  g_Vh);
    cudaGetSymbolAddress((void**)&Vl,  g_Vl);
    cudaGetSymbolAddress((void**)&P,   g_P);
    cudaGetSymbolAddress((void**)&Ph,  g_Ph);
    cudaGetSymbolAddress((void**)&Pl,  g_Pl);

    cudaFuncSetAttribute((const void*)gemm_mma<0, false>,
                         cudaFuncAttributeMaxDynamicSharedMemorySize, SMEM_BYTES);
    cudaFuncSetAttribute((const void*)gemm_mma<2, false>,
                         cudaFuncAttributeMaxDynamicSharedMemorySize, SMEM_BYTES);
    cudaFuncSetAttribute((const void*)gemm_mma<2, true>,
                         cudaFuncAttributeMaxDynamicSharedMemorySize, SMEM_BYTES);

    const size_t SD = (size_t)PS * PD;   // 4M elems per batch
    const size_t SS = (size_t)PS * PS;   // 16M elems per batch

    // 1) splits
    split_kernel<<<16384, 256>>>(x,  xh,  xl,  (size_t)MROWS * PD / 4);
    split_kernel<<<1024,  256>>>(Wq, Wqh, Wql, (size_t)PD * PD / 4);
    split_kernel<<<1024,  256>>>(Wk, Wkh, Wkl, (size_t)PD * PD / 4);
    split_kernel<<<1024,  256>>>(Wv, Wvh, Wvl, (size_t)PD * PD / 4);

    // 2) merged projections: z=0/1/2 -> Q/K/V
    ProjArgs pa;
    pa.s[0] = { Wqh, Wql, bq, Qh, Ql };
    pa.s[1] = { Wkh, Wkl, bk, Kh, Kl };
    pa.s[2] = { Wvh, Wvl, bv, Vh, Vl };
    dim3 gp(PD / 128, MROWS / 128, 3);
    gemm_mma<0, false><<<gp, 256, SMEM_BYTES>>>(
        xh, xl, nullptr, nullptr, pa, nullptr, PD, PD, PD, 1.0f, 0, 0, 0);

    // 3) scores: P[b] = Q[b] @ K[b]^T / 32  (NT)
    ProjArgs dummy = {};
    dim3 gs(PS / 128, PS / 128, PB);
    gemm_mma<2, false><<<gs, 256, SMEM_BYTES>>>(
        Qh, Ql, Kh, Kl, dummy, P, PD, PD, PS, 0.03125f, SD, SD, SS);

    // 4) softmax -> split bf16 P
    softmax_kernel<<<PB * PS, 256>>>(P, Ph, Pl);

    // 5) out[b] = P[b] @ V[b]  (NN: B is [K=S, N=D] row-major -> BT path)
    dim3 go(PD / 128, PS / 128, PB);
    gemm_mma<2, true><<<go, 256, SMEM_BYTES>>>(
        Ph, Pl, Vh, Vl, dummy, out, PS, PD, PD, 1.0f, SS, SD, SD);
}

// round 6
// speedup vs baseline: 1.2036x; 1.0172x over previous
#include <cuda_runtime.h>
#include <cuda_bf16.h>
#include <math_constants.h>
#include <cstdint>

// Problem shape (fixed): B=4, S=4096, D=1024
#define PB 4
#define PS 4096
#define PD 1024
#define MROWS (PB * PS)   // 16384

// ---------------------------------------------------------------------------
// Global scratch (allocation-guard-safe __device__ arrays)
// ---------------------------------------------------------------------------
__device__ __nv_bfloat16 g_xh[(size_t)MROWS * PD], g_xl[(size_t)MROWS * PD];
__device__ __nv_bfloat16 g_Wqh[PD * PD], g_Wql[PD * PD];
__device__ __nv_bfloat16 g_Wkh[PD * PD], g_Wkl[PD * PD];
__device__ __nv_bfloat16 g_Wvh[PD * PD], g_Wvl[PD * PD];
__device__ __nv_bfloat16 g_Qh[(size_t)MROWS * PD], g_Ql[(size_t)MROWS * PD];
__device__ __nv_bfloat16 g_Kh[(size_t)MROWS * PD], g_Kl[(size_t)MROWS * PD];
__device__ __nv_bfloat16 g_Vh[(size_t)MROWS * PD], g_Vl[(size_t)MROWS * PD];
__device__ __nv_bfloat16 g_Ph[(size_t)PB * PS * PS], g_Pl[(size_t)PB * PS * PS];
__device__ float g_psum[(size_t)PB * PS * 64];   // per-row partial expsums
__device__ float g_inv [(size_t)PB * PS];        // 1 / rowsum

// ---------------------------------------------------------------------------
// PTX helpers (baseline sm_80+ features only: compile-safe under compute_103)
// ---------------------------------------------------------------------------
__device__ __forceinline__ uint32_t smem_u32(const void* p) {
    uint32_t a;
    asm("{ .reg .u64 t; cvta.to.shared.u64 t, %1; cvt.u32.u64 %0, t; }"
        : "=r"(a) : "l"(p));
    return a;
}

__device__ __forceinline__ void cp16(uint32_t s, const void* g) {
    asm volatile("cp.async.cg.shared.global [%0], [%1], 16;" :: "r"(s), "l"(g));
}
__device__ __forceinline__ void cp_commit() {
    asm volatile("cp.async.commit_group;" ::: "memory");
}
template<int N>
__device__ __forceinline__ void cp_wait() {
    asm volatile("cp.async.wait_group %0;" :: "n"(N) : "memory");
}

__device__ __forceinline__ void ldsm_x4(uint32_t a, uint32_t* r) {
    asm volatile("ldmatrix.sync.aligned.m8n8.x4.shared.b16 {%0,%1,%2,%3}, [%4];"
                 : "=r"(r[0]), "=r"(r[1]), "=r"(r[2]), "=r"(r[3]) : "r"(a));
}
__device__ __forceinline__ void ldsm_x4_t(uint32_t a, uint32_t* r) {
    asm volatile("ldmatrix.sync.aligned.m8n8.x4.trans.shared.b16 {%0,%1,%2,%3}, [%4];"
                 : "=r"(r[0]), "=r"(r[1]), "=r"(r[2]), "=r"(r[3]) : "r"(a));
}

__device__ __forceinline__ void mma_bf16(float* c, const uint32_t* a,
                                         const uint32_t* b) {
    asm volatile(
        "mma.sync.aligned.m16n8k16.row.col.f32.bf16.bf16.f32 "
        "{%0,%1,%2,%3},{%4,%5,%6,%7},{%8,%9},{%0,%1,%2,%3};"
        : "+f"(c[0]), "+f"(c[1]), "+f"(c[2]), "+f"(c[3])
        : "r"(a[0]), "r"(a[1]), "r"(a[2]), "r"(a[3]), "r"(b[0]), "r"(b[1]));
}

__device__ __forceinline__ void split1(float v, __nv_bfloat16& h, __nv_bfloat16& l) {
    h = __float2bfloat16(v);
    l = __float2bfloat16(v - __bfloat162float(h));
}

// ---------------------------------------------------------------------------
// Tiling: block 128x128, BK=32, 8 warps each 32(M) x 64(N).
// 2 stages x 40960B = 80KB/CTA -> 2 CTAs/SM (proved decisive in round 5).
// ---------------------------------------------------------------------------
#define STAGE_STRIDE 40960
#define NSTAGE 2
#define SMEM_BYTES (NSTAGE * STAGE_STRIDE)   // 81920

struct ProjSet {
    const __nv_bfloat16* Bh;
    const __nv_bfloat16* Bl;
    const float* bias;
    __nv_bfloat16* Ch;
    __nv_bfloat16* Cl;
};
struct ProjArgs { ProjSet s[3]; };

// MODE 0: C = split bf16 + bias              (merged Q/K/V projections)
// MODE 3: C = split bf16 of exp(acc*scale), partial rowsums -> psum (scores)
// MODE 4: C = fp32 * inv[row]                (PV output)
// BT: B stored [K,N] row-major -> ldmatrix.trans path.
template<int MODE, bool BT>
__global__ void __launch_bounds__(256, 2)
gemm_mma(const __nv_bfloat16* __restrict__ Ah, const __nv_bfloat16* __restrict__ Al,
         const __nv_bfloat16* __restrict__ Bh_, const __nv_bfloat16* __restrict__ Bl_,
         ProjArgs pa,
         float* __restrict__ Cf,
         __nv_bfloat16* __restrict__ Ch_, __nv_bfloat16* __restrict__ Cl_,
         float* __restrict__ psum, const float* __restrict__ inv,
         int K, int ldb, int ldc, float scale,
         size_t sA, size_t sB, size_t sC)
{
    extern __shared__ char smem[];
    const uint32_t sb0 = smem_u32(smem);
    const int tid  = threadIdx.x;
    const int lane = tid & 31;
    const int wid  = tid >> 5;
    const int warp_m = wid & 3;
    const int warp_n = wid >> 2;

    const __nv_bfloat16* Bh;
    const __nv_bfloat16* Bl;
    const float* bias = nullptr;
    __nv_bfloat16 *Ch = nullptr, *Cl = nullptr;
    if (MODE == 0) {
        const ProjSet& s = pa.s[blockIdx.z];
        Bh = s.Bh; Bl = s.Bl; bias = s.bias; Ch = s.Ch; Cl = s.Cl;
    } else {
        Bh = Bh_ + (size_t)blockIdx.z * sB;
        Bl = Bl_ + (size_t)blockIdx.z * sB;
        Ah += (size_t)blockIdx.z * sA;
        Al += (size_t)blockIdx.z * sA;
        if (MODE == 3) {
            Ch = Ch_ + (size_t)blockIdx.z * sC;
            Cl = Cl_ + (size_t)blockIdx.z * sC;
        }
    }

    const int row0 = blockIdx.y * 128;
    const int col0 = blockIdx.x * 128;

    float acc[2][8][4];
#pragma unroll
    for (int i = 0; i < 2; i++)
#pragma unroll
        for (int n = 0; n < 8; n++)
#pragma unroll
            for (int j = 0; j < 4; j++) acc[i][n][j] = 0.0f;

    const int nk = K >> 5;   // BK = 32

    // ---------------- stage loader ----------------
    auto load_stage = [&](int stage, int ki) {
        const uint32_t sb = sb0 + stage * STAGE_STRIDE;
        const int k0 = ki << 5;
#pragma unroll
        for (int it = 0; it < 4; it++) {
            int idx = tid + (it << 8);
            int hl  = idx >> 9;
            int e   = idx & 511;
            int r   = e >> 2;
            int c4  = e & 3;
            const __nv_bfloat16* src = hl ? Al : Ah;
            cp16(sb + hl * 10240 + r * 80 + c4 * 16,
                 src + (size_t)(row0 + r) * K + k0 + c4 * 8);
        }
        if (!BT) {
#pragma unroll
            for (int it = 0; it < 4; it++) {
                int idx = tid + (it << 8);
                int hl  = idx >> 9;
                int e   = idx & 511;
                int r   = e >> 2;
                int c4  = e & 3;
                const __nv_bfloat16* src = hl ? Bl : Bh;
                cp16(sb + 20480 + hl * 10240 + r * 80 + c4 * 16,
                     src + (size_t)(col0 + r) * ldb + k0 + c4 * 8);
            }
        } else {
#pragma unroll
            for (int it = 0; it < 4; it++) {
                int idx = tid + (it << 8);
                int hl  = idx >> 9;
                int e   = idx & 511;
                int r   = e >> 4;
                int c16 = e & 15;
                const __nv_bfloat16* src = hl ? Bl : Bh;
                cp16(sb + 20480 + hl * 8704 + r * 272 + c16 * 16,
                     src + (size_t)(k0 + r) * ldb + col0 + c16 * 8);
            }
        }
        cp_commit();
    };

    // B-group fragment loader (2 n8-tiles, hi+lo)
    auto load_b = [&](uint32_t sB0, int k16, int nt, uint32_t* bh2, uint32_t* bl2) {
        if (!BT) {
            int n = warp_n * 64 + nt * 16 + ((lane & 16) ? 8 : 0) + (lane & 7);
            int k = k16 + (lane & 8);
            ldsm_x4(sB0 +         n * 80 + k * 2, bh2);
            ldsm_x4(sB0 + 10240 + n * 80 + k * 2, bl2);
        } else {
            int k = k16 + (lane & 15);
            int n = warp_n * 64 + nt * 16 + ((lane & 16) ? 8 : 0);
            ldsm_x4_t(sB0 +        k * 272 + n * 2, bh2);
            ldsm_x4_t(sB0 + 8704 + k * 272 + n * 2, bl2);
        }
    };

    // ---------------- mainloop (2-stage; cross-CTA overlap via occupancy) ---
    load_stage(0, 0);
    cp_wait<0>();
    __syncthreads();

    for (int i = 0; i < nk; i++) {
        if (i + 1 < nk) load_stage((i + 1) & 1, i + 1);

        const uint32_t sA0 = sb0 + (i & 1) * STAGE_STRIDE;
        const uint32_t sB0 = sA0 + 20480;

#pragma unroll
        for (int kk = 0; kk < 2; kk++) {
            const int k16 = kk << 4;

            uint32_t ah[2][4], al[2][4];
#pragma unroll
            for (int mi = 0; mi < 2; mi++) {
                int m = warp_m * 32 + mi * 16 + (lane & 15);
                int k = k16 + ((lane & 16) ? 8 : 0);
                ldsm_x4(sA0 +         m * 80 + k * 2, ah[mi]);
                ldsm_x4(sA0 + 10240 + m * 80 + k * 2, al[mi]);
            }

            // B double-buffered: prefetch group nt+1 before MMAs of group nt
            uint32_t bh[2][4], bl[2][4];
            load_b(sB0, k16, 0, bh[0], bl[0]);
#pragma unroll
            for (int nt = 0; nt < 4; nt++) {
                const int cur = nt & 1;
                if (nt < 3) load_b(sB0, k16, nt + 1, bh[cur ^ 1], bl[cur ^ 1]);
#pragma unroll
                for (int mi = 0; mi < 2; mi++)
#pragma unroll
                    for (int nn = 0; nn < 2; nn++) {
                        float* a = acc[mi][2 * nt + nn];
                        mma_bf16(a, ah[mi], bh[cur] + 2 * nn);
                        mma_bf16(a, ah[mi], bl[cur] + 2 * nn);
                        mma_bf16(a, al[mi], bh[cur] + 2 * nn);
                    }
            }
        }

        if (i + 1 < nk) {
            cp_wait<0>();
            __syncthreads();
        }
    }

    // ---------------- epilogue ----------------
    float rs[2][2] = {{0.0f, 0.0f}, {0.0f, 0.0f}};   // MODE 3 partial rowsums

#pragma unroll
    for (int mi = 0; mi < 2; mi++) {
        const int rbase = row0 + warp_m * 32 + mi * 16 + (lane >> 2);
        float iv0 = 0.0f, iv1 = 0.0f;
        if (MODE == 4) {
            iv0 = inv[(size_t)blockIdx.z * PS + rbase];
            iv1 = inv[(size_t)blockIdx.z * PS + rbase + 8];
        }
#pragma unroll
        for (int n = 0; n < 8; n++) {
            const int cb = col0 + warp_n * 64 + n * 8 + 2 * (lane & 3);
            if (MODE == 4) {
                float* base = Cf + (size_t)blockIdx.z * sC;
                float2 v0 = make_float2(acc[mi][n][0] * iv0, acc[mi][n][1] * iv0);
                float2 v1 = make_float2(acc[mi][n][2] * iv1, acc[mi][n][3] * iv1);
                *reinterpret_cast<float2*>(base + (size_t)rbase * ldc + cb) = v0;
                *reinterpret_cast<float2*>(base + (size_t)(rbase + 8) * ldc + cb) = v1;
            } else if (MODE == 3) {
                float e0 = __expf(acc[mi][n][0] * scale);
                float e1 = __expf(acc[mi][n][1] * scale);
                float e2 = __expf(acc[mi][n][2] * scale);
                float e3 = __expf(acc[mi][n][3] * scale);
                rs[mi][0] += e0 + e1;
                rs[mi][1] += e2 + e3;
                __nv_bfloat16 h0, l0, h1, l1, h2, l2, h3, l3;
                split1(e0, h0, l0); split1(e1, h1, l1);
                split1(e2, h2, l2); split1(e3, h3, l3);
                *reinterpret_cast<__nv_bfloat162*>(Ch + (size_t)rbase * ldc + cb)
                    = __nv_bfloat162(h0, h1);
                *reinterpret_cast<__nv_bfloat162*>(Cl + (size_t)rbase * ldc + cb)
                    = __nv_bfloat162(l0, l1);
                *reinterpret_cast<__nv_bfloat162*>(Ch + (size_t)(rbase + 8) * ldc + cb)
                    = __nv_bfloat162(h2, h3);
                *reinterpret_cast<__nv_bfloat162*>(Cl + (size_t)(rbase + 8) * ldc + cb)
                    = __nv_bfloat162(l2, l3);
            } else {  // MODE 0
                float b0 = bias[cb], b1 = bias[cb + 1];
                __nv_bfloat16 h0, l0, h1, l1, h2, l2, h3, l3;
                split1(acc[mi][n][0] + b0, h0, l0);
                split1(acc[mi][n][1] + b1, h1, l1);
                split1(acc[mi][n][2] + b0, h2, l2);
                split1(acc[mi][n][3] + b1, h3, l3);
                *reinterpret_cast<__nv_bfloat162*>(Ch + (size_t)rbase * ldc + cb)
                    = __nv_bfloat162(h0, h1);
                *reinterpret_cast<__nv_bfloat162*>(Cl + (size_t)rbase * ldc + cb)
                    = __nv_bfloat162(l0, l1);
                *reinterpret_cast<__nv_bfloat162*>(Ch + (size_t)(rbase + 8) * ldc + cb)
                    = __nv_bfloat162(h2, h3);
                *reinterpret_cast<__nv_bfloat162*>(Cl + (size_t)(rbase + 8) * ldc + cb)
                    = __nv_bfloat162(l2, l3);
            }
        }
    }

    if (MODE == 3) {
        // reduce partial rowsums across the 4 lanes of each row-quad
#pragma unroll
        for (int mi = 0; mi < 2; mi++)
#pragma unroll
            for (int h = 0; h < 2; h++) {
                rs[mi][h] += __shfl_xor_sync(0xffffffffu, rs[mi][h], 1);
                rs[mi][h] += __shfl_xor_sync(0xffffffffu, rs[mi][h], 2);
            }
        if ((lane & 3) == 0) {
            const int q = lane >> 2;
            const int t = blockIdx.x * 2 + warp_n;   // 64 col-spans per row
#pragma unroll
            for (int mi = 0; mi < 2; mi++) {
                const int rl = row0 + warp_m * 32 + mi * 16 + q;
                const size_t rb = (size_t)blockIdx.z * PS;
                psum[(rb + rl) * 64 + t]     = rs[mi][0];
                psum[(rb + rl + 8) * 64 + t] = rs[mi][1];
            }
        }
    }
}

// ---------------------------------------------------------------------------
// Merged fp32 -> bf16 hi/lo splits for x, Wq, Wk, Wv (one launch)
// ---------------------------------------------------------------------------
struct SplitArgs {
    const float* src[4];
    __nv_bfloat16* dh[4];
    __nv_bfloat16* dl[4];
};

__global__ void __launch_bounds__(256)
split_all(SplitArgs sa)
{
    int bid = blockIdx.x;
    int which, boff;
    if (bid < 16384) { which = 0; boff = bid; }
    else { which = 1 + ((bid - 16384) >> 10); boff = (bid - 16384) & 1023; }

    size_t i = (size_t)boff * 256 + threadIdx.x;
    float4 v = reinterpret_cast<const float4*>(sa.src[which])[i];
    float vv[4] = { v.x, v.y, v.z, v.w };
    uint32_t H[2], L[2];
#pragma unroll
    for (int j = 0; j < 2; j++) {
        __nv_bfloat16 h0, l0, h1, l1;
        split1(vv[2 * j],     h0, l0);
        split1(vv[2 * j + 1], h1, l1);
        H[j] = (uint32_t)__bfloat16_as_ushort(h0) |
               ((uint32_t)__bfloat16_as_ushort(h1) << 16);
        L[j] = (uint32_t)__bfloat16_as_ushort(l0) |
               ((uint32_t)__bfloat16_as_ushort(l1) << 16);
    }
    reinterpret_cast<uint2*>(sa.dh[which])[i] = make_uint2(H[0], H[1]);
    reinterpret_cast<uint2*>(sa.dl[which])[i] = make_uint2(L[0], L[1]);
}

// ---------------------------------------------------------------------------
// Rowsum reduce: one warp per row sums 64 partials -> 1/sum
// ---------------------------------------------------------------------------
__global__ void __launch_bounds__(256)
rowsum_inv(const float* __restrict__ psum, float* __restrict__ inv)
{
    const int row  = (blockIdx.x * blockDim.x + threadIdx.x) >> 5;
    const int lane = threadIdx.x & 31;
    float2 v = reinterpret_cast<const float2*>(psum + (size_t)row * 64)[lane];
    float s = v.x + v.y;
#pragma unroll
    for (int o = 16; o > 0; o >>= 1)
        s += __shfl_xor_sync(0xffffffffu, s, o);
    if (lane == 0) inv[row] = 1.0f / s;
}

// ---------------------------------------------------------------------------
// Launcher
// ---------------------------------------------------------------------------
extern "C" void kernel_launch(void* const* d_in, const int* in_sizes, int n_in,
                              void* d_out, int out_size)
{
    (void)in_sizes; (void)n_in; (void)out_size;
    const float* x  = (const float*)d_in[0];
    const float* Wq = (const float*)d_in[1];
    const float* bq = (const float*)d_in[2];
    const float* Wk = (const float*)d_in[3];
    const float* bk = (const float*)d_in[4];
    const float* Wv = (const float*)d_in[5];
    const float* bv = (const float*)d_in[6];
    float* out = (float*)d_out;

    __nv_bfloat16 *xh, *xl, *Wqh, *Wql, *Wkh, *Wkl, *Wvh, *Wvl;
    __nv_bfloat16 *Qh, *Ql, *Kh, *Kl, *Vh, *Vl, *Ph, *Pl;
    float *psum, *inv;
    cudaGetSymbolAddress((void**)&xh,  g_xh);
    cudaGetSymbolAddress((void**)&xl,  g_xl);
    cudaGetSymbolAddress((void**)&Wqh, g_Wqh);
    cudaGetSymbolAddress((void**)&Wql, g_Wql);
    cudaGetSymbolAddress((void**)&Wkh, g_Wkh);
    cudaGetSymbolAddress((void**)&Wkl, g_Wkl);
    cudaGetSymbolAddress((void**)&Wvh, g_Wvh);
    cudaGetSymbolAddress((void**)&Wvl, g_Wvl);
    cudaGetSymbolAddress((void**)&Qh,  g_Qh);
    cudaGetSymbolAddress((void**)&Ql,  g_Ql);
    cudaGetSymbolAddress((void**)&Kh,  g_Kh);
    cudaGetSymbolAddress((void**)&Kl,  g_Kl);
    cudaGetSymbolAddress((void**)&Vh,  g_Vh);
    cudaGetSymbolAddress((void**)&Vl,  g_Vl);
    cudaGetSymbolAddress((void**)&Ph,  g_Ph);
    cudaGetSymbolAddress((void**)&Pl,  g_Pl);
    cudaGetSymbolAddress((void**)&psum, g_psum);
    cudaGetSymbolAddress((void**)&inv,  g_inv);

    cudaFuncSetAttribute((const void*)gemm_mma<0, false>,
                         cudaFuncAttributeMaxDynamicSharedMemorySize, SMEM_BYTES);
    cudaFuncSetAttribute((const void*)gemm_mma<3, false>,
                         cudaFuncAttributeMaxDynamicSharedMemorySize, SMEM_BYTES);
    cudaFuncSetAttribute((const void*)gemm_mma<4, true>,
                         cudaFuncAttributeMaxDynamicSharedMemorySize, SMEM_BYTES);

    const size_t SD = (size_t)PS * PD;   // 4M elems per batch
    const size_t SS = (size_t)PS * PS;   // 16M elems per batch

    // 1) merged splits: x (16384 blocks) + Wq/Wk/Wv (1024 each)
    SplitArgs sa;
    sa.src[0] = x;  sa.dh[0] = xh;  sa.dl[0] = xl;
    sa.src[1] = Wq; sa.dh[1] = Wqh; sa.dl[1] = Wql;
    sa.src[2] = Wk; sa.dh[2] = Wkh; sa.dl[2] = Wkl;
    sa.src[3] = Wv; sa.dh[3] = Wvh; sa.dl[3] = Wvl;
    split_all<<<16384 + 3 * 1024, 256>>>(sa);

    // 2) merged projections: z=0/1/2 -> Q/K/V
    ProjArgs pa;
    pa.s[0] = { Wqh, Wql, bq, Qh, Ql };
    pa.s[1] = { Wkh, Wkl, bk, Kh, Kl };
    pa.s[2] = { Wvh, Wvl, bv, Vh, Vl };
    ProjArgs dummy = {};
    dim3 gp(PD / 128, MROWS / 128, 3);
    gemm_mma<0, false><<<gp, 256, SMEM_BYTES>>>(
        xh, xl, nullptr, nullptr, pa, nullptr, nullptr, nullptr,
        nullptr, nullptr, PD, PD, PD, 1.0f, 0, 0, 0);

    // 3) scores + fused exp: Ph/Pl[b] = exp(Q[b] @ K[b]^T / 32), psum partials
    dim3 gs(PS / 128, PS / 128, PB);
    gemm_mma<3, false><<<gs, 256, SMEM_BYTES>>>(
        Qh, Ql, Kh, Kl, dummy, nullptr, Ph, Pl, psum, nullptr,
        PD, PD, PS, 0.03125f, SD, SD, SS);

    // 4) rowsum -> 1/sum  (one warp per row; 16384 rows)
    rowsum_inv<<<(PB * PS * 32) / 256, 256>>>(psum, inv);

    // 5) out[b] = (expP[b] @ V[b]) * inv[row]  (NN: BT path)
    dim3 go(PD / 128, PS / 128, PB);
    gemm_mma<4, true><<<go, 256, SMEM_BYTES>>>(
        Ph, Pl, Vh, Vl, dummy, out, nullptr, nullptr, nullptr, inv,
        PS, PD, PD, 1.0f, SS, SD, SD);
}

// round 7
// speedup vs baseline: 1.3268x; 1.1024x over previous
#include <cuda_runtime.h>
#include <cuda_bf16.h>
#include <cuda_fp16.h>
#include <math_constants.h>
#include <cstdint>

// Problem shape (fixed): B=4, S=4096, D=1024
#define PB 4
#define PS 4096
#define PD 1024
#define MROWS (PB * PS)   // 16384

// ---------------------------------------------------------------------------
// Global scratch (allocation-guard-safe __device__ arrays)
// ---------------------------------------------------------------------------
__device__ __nv_bfloat16 g_xh[(size_t)MROWS * PD], g_xl[(size_t)MROWS * PD];
__device__ __nv_bfloat16 g_Wqh[PD * PD], g_Wql[PD * PD];
__device__ __nv_bfloat16 g_Wkh[PD * PD], g_Wkl[PD * PD];
__device__ __nv_bfloat16 g_Wvh[PD * PD], g_Wvl[PD * PD];
__device__ __nv_bfloat16 g_Qh[(size_t)MROWS * PD], g_Ql[(size_t)MROWS * PD];
__device__ __nv_bfloat16 g_Kh[(size_t)MROWS * PD], g_Kl[(size_t)MROWS * PD];
__device__ __half        g_V16h[(size_t)MROWS * PD], g_V16l[(size_t)MROWS * PD];
__device__ __half        g_Pf[(size_t)PB * PS * PS];   // exp scores, fp16
__device__ float g_psum[(size_t)PB * PS * 64];   // per-row partial expsums
__device__ float g_inv [(size_t)PB * PS];        // 1 / rowsum

// ---------------------------------------------------------------------------
// PTX helpers (baseline sm_80+ features only: compile-safe under compute_103)
// ---------------------------------------------------------------------------
__device__ __forceinline__ uint32_t smem_u32(const void* p) {
    uint32_t a;
    asm("{ .reg .u64 t; cvta.to.shared.u64 t, %1; cvt.u32.u64 %0, t; }"
        : "=r"(a) : "l"(p));
    return a;
}

__device__ __forceinline__ void cp16(uint32_t s, const void* g) {
    asm volatile("cp.async.cg.shared.global [%0], [%1], 16;" :: "r"(s), "l"(g));
}
__device__ __forceinline__ void cp_commit() {
    asm volatile("cp.async.commit_group;" ::: "memory");
}
template<int N>
__device__ __forceinline__ void cp_wait() {
    asm volatile("cp.async.wait_group %0;" :: "n"(N) : "memory");
}

__device__ __forceinline__ void ldsm_x4(uint32_t a, uint32_t* r) {
    asm volatile("ldmatrix.sync.aligned.m8n8.x4.shared.b16 {%0,%1,%2,%3}, [%4];"
                 : "=r"(r[0]), "=r"(r[1]), "=r"(r[2]), "=r"(r[3]) : "r"(a));
}
__device__ __forceinline__ void ldsm_x4_t(uint32_t a, uint32_t* r) {
    asm volatile("ldmatrix.sync.aligned.m8n8.x4.trans.shared.b16 {%0,%1,%2,%3}, [%4];"
                 : "=r"(r[0]), "=r"(r[1]), "=r"(r[2]), "=r"(r[3]) : "r"(a));
}

__device__ __forceinline__ void mma_bf16(float* c, const uint32_t* a,
                                         const uint32_t* b) {
    asm volatile(
        "mma.sync.aligned.m16n8k16.row.col.f32.bf16.bf16.f32 "
        "{%0,%1,%2,%3},{%4,%5,%6,%7},{%8,%9},{%0,%1,%2,%3};"
        : "+f"(c[0]), "+f"(c[1]), "+f"(c[2]), "+f"(c[3])
        : "r"(a[0]), "r"(a[1]), "r"(a[2]), "r"(a[3]), "r"(b[0]), "r"(b[1]));
}

__device__ __forceinline__ void mma_f16(float* c, const uint32_t* a,
                                        const uint32_t* b) {
    asm volatile(
        "mma.sync.aligned.m16n8k16.row.col.f32.f16.f16.f32 "
        "{%0,%1,%2,%3},{%4,%5,%6,%7},{%8,%9},{%0,%1,%2,%3};"
        : "+f"(c[0]), "+f"(c[1]), "+f"(c[2]), "+f"(c[3])
        : "r"(a[0]), "r"(a[1]), "r"(a[2]), "r"(a[3]), "r"(b[0]), "r"(b[1]));
}

__device__ __forceinline__ void split1(float v, __nv_bfloat16& h, __nv_bfloat16& l) {
    h = __float2bfloat16(v);
    l = __float2bfloat16(v - __bfloat162float(h));
}

// ---------------------------------------------------------------------------
// Main GEMM (proj + scores): block 128x128, BK=32, 8 warps each 32(M) x 64(N).
// 2 stages x 40960B = 80KB/CTA -> 2 CTAs/SM.
// ---------------------------------------------------------------------------
#define STAGE_STRIDE 40960
#define SMEM_BYTES (2 * STAGE_STRIDE)   // 81920

struct ProjSet {
    const __nv_bfloat16* Bh;
    const __nv_bfloat16* Bl;
    const float* bias;
    __nv_bfloat16* Ch;   // bf16 hi (or fp16 hi if h16)
    __nv_bfloat16* Cl;
    int h16;             // 1: emit fp16 split (V projection)
};
struct ProjArgs { ProjSet s[3]; };

// MODE 0: C = split hi/lo + bias (merged Q/K/V projections; V as fp16 split)
// MODE 3: C = fp16 of exp(acc*scale) into Ch (as __half*), partials -> psum
template<int MODE>
__global__ void __launch_bounds__(256, 2)
gemm_mma(const __nv_bfloat16* __restrict__ Ah, const __nv_bfloat16* __restrict__ Al,
         const __nv_bfloat16* __restrict__ Bh_, const __nv_bfloat16* __restrict__ Bl_,
         ProjArgs pa,
         __nv_bfloat16* __restrict__ Ch_,
         float* __restrict__ psum,
         int K, int ldb, int ldc, float scale,
         size_t sA, size_t sB, size_t sC)
{
    extern __shared__ char smem[];
    const uint32_t sb0 = smem_u32(smem);
    const int tid  = threadIdx.x;
    const int lane = tid & 31;
    const int wid  = tid >> 5;
    const int warp_m = wid & 3;
    const int warp_n = wid >> 2;

    const __nv_bfloat16* Bh;
    const __nv_bfloat16* Bl;
    const float* bias = nullptr;
    __nv_bfloat16 *Ch = nullptr, *Cl = nullptr;
    int h16 = 0;
    if (MODE == 0) {
        const ProjSet& s = pa.s[blockIdx.z];
        Bh = s.Bh; Bl = s.Bl; bias = s.bias; Ch = s.Ch; Cl = s.Cl; h16 = s.h16;
    } else {
        Bh = Bh_ + (size_t)blockIdx.z * sB;
        Bl = Bl_ + (size_t)blockIdx.z * sB;
        Ah += (size_t)blockIdx.z * sA;
        Al += (size_t)blockIdx.z * sA;
        Ch = Ch_ + (size_t)blockIdx.z * sC;
    }

    const int row0 = blockIdx.y * 128;
    const int col0 = blockIdx.x * 128;

    float acc[2][8][4];
#pragma unroll
    for (int i = 0; i < 2; i++)
#pragma unroll
        for (int n = 0; n < 8; n++)
#pragma unroll
            for (int j = 0; j < 4; j++) acc[i][n][j] = 0.0f;

    const int nk = K >> 5;   // BK = 32

    auto load_stage = [&](int stage, int ki) {
        const uint32_t sb = sb0 + stage * STAGE_STRIDE;
        const int k0 = ki << 5;
#pragma unroll
        for (int it = 0; it < 4; it++) {
            int idx = tid + (it << 8);
            int hl  = idx >> 9;
            int e   = idx & 511;
            int r   = e >> 2;
            int c4  = e & 3;
            const __nv_bfloat16* src = hl ? Al : Ah;
            cp16(sb + hl * 10240 + r * 80 + c4 * 16,
                 src + (size_t)(row0 + r) * K + k0 + c4 * 8);
        }
#pragma unroll
        for (int it = 0; it < 4; it++) {
            int idx = tid + (it << 8);
            int hl  = idx >> 9;
            int e   = idx & 511;
            int r   = e >> 2;
            int c4  = e & 3;
            const __nv_bfloat16* src = hl ? Bl : Bh;
            cp16(sb + 20480 + hl * 10240 + r * 80 + c4 * 16,
                 src + (size_t)(col0 + r) * ldb + k0 + c4 * 8);
        }
        cp_commit();
    };

    auto load_b = [&](uint32_t sB0, int k16, int nt, uint32_t* bh2, uint32_t* bl2) {
        int n = warp_n * 64 + nt * 16 + ((lane & 16) ? 8 : 0) + (lane & 7);
        int k = k16 + (lane & 8);
        ldsm_x4(sB0 +         n * 80 + k * 2, bh2);
        ldsm_x4(sB0 + 10240 + n * 80 + k * 2, bl2);
    };

    load_stage(0, 0);
    cp_wait<0>();
    __syncthreads();

    for (int i = 0; i < nk; i++) {
        if (i + 1 < nk) load_stage((i + 1) & 1, i + 1);

        const uint32_t sA0 = sb0 + (i & 1) * STAGE_STRIDE;
        const uint32_t sB0 = sA0 + 20480;

#pragma unroll
        for (int kk = 0; kk < 2; kk++) {
            const int k16 = kk << 4;

            uint32_t ah[2][4], al[2][4];
#pragma unroll
            for (int mi = 0; mi < 2; mi++) {
                int m = warp_m * 32 + mi * 16 + (lane & 15);
                int k = k16 + ((lane & 16) ? 8 : 0);
                ldsm_x4(sA0 +         m * 80 + k * 2, ah[mi]);
                ldsm_x4(sA0 + 10240 + m * 80 + k * 2, al[mi]);
            }

            uint32_t bh[2][4], bl[2][4];
            load_b(sB0, k16, 0, bh[0], bl[0]);
#pragma unroll
            for (int nt = 0; nt < 4; nt++) {
                const int cur = nt & 1;
                if (nt < 3) load_b(sB0, k16, nt + 1, bh[cur ^ 1], bl[cur ^ 1]);
#pragma unroll
                for (int mi = 0; mi < 2; mi++)
#pragma unroll
                    for (int nn = 0; nn < 2; nn++) {
                        float* a = acc[mi][2 * nt + nn];
                        mma_bf16(a, ah[mi], bh[cur] + 2 * nn);
                        mma_bf16(a, ah[mi], bl[cur] + 2 * nn);
                        mma_bf16(a, al[mi], bh[cur] + 2 * nn);
                    }
            }
        }

        if (i + 1 < nk) {
            cp_wait<0>();
            __syncthreads();
        }
    }

    // ---------------- epilogue ----------------
    float rs[2][2] = {{0.0f, 0.0f}, {0.0f, 0.0f}};

#pragma unroll
    for (int mi = 0; mi < 2; mi++) {
        const int rbase = row0 + warp_m * 32 + mi * 16 + (lane >> 2);
#pragma unroll
        for (int n = 0; n < 8; n++) {
            const int cb = col0 + warp_n * 64 + n * 8 + 2 * (lane & 3);
            if (MODE == 3) {
                float e0 = __expf(acc[mi][n][0] * scale);
                float e1 = __expf(acc[mi][n][1] * scale);
                float e2 = __expf(acc[mi][n][2] * scale);
                float e3 = __expf(acc[mi][n][3] * scale);
                __half q0 = __float2half(e0), q1 = __float2half(e1);
                __half q2 = __float2half(e2), q3 = __float2half(e3);
                // rowsums over the ROUNDED values (exactly what PV will sum)
                rs[mi][0] += __half2float(q0) + __half2float(q1);
                rs[mi][1] += __half2float(q2) + __half2float(q3);
                __half* Pf = reinterpret_cast<__half*>(Ch);
                uint32_t p01 = (uint32_t)__half_as_ushort(q0) |
                               ((uint32_t)__half_as_ushort(q1) << 16);
                uint32_t p23 = (uint32_t)__half_as_ushort(q2) |
                               ((uint32_t)__half_as_ushort(q3) << 16);
                *reinterpret_cast<uint32_t*>(Pf + (size_t)rbase * ldc + cb) = p01;
                *reinterpret_cast<uint32_t*>(Pf + (size_t)(rbase + 8) * ldc + cb) = p23;
            } else {  // MODE 0
                float b0 = bias[cb], b1 = bias[cb + 1];
                float v0 = acc[mi][n][0] + b0;
                float v1 = acc[mi][n][1] + b1;
                float v2 = acc[mi][n][2] + b0;
                float v3 = acc[mi][n][3] + b1;
                if (!h16) {
                    __nv_bfloat16 h0, l0, h1, l1, h2, l2, h3, l3;
                    split1(v0, h0, l0); split1(v1, h1, l1);
                    split1(v2, h2, l2); split1(v3, h3, l3);
                    *reinterpret_cast<__nv_bfloat162*>(Ch + (size_t)rbase * ldc + cb)
                        = __nv_bfloat162(h0, h1);
                    *reinterpret_cast<__nv_bfloat162*>(Cl + (size_t)rbase * ldc + cb)
                        = __nv_bfloat162(l0, l1);
                    *reinterpret_cast<__nv_bfloat162*>(Ch + (size_t)(rbase + 8) * ldc + cb)
                        = __nv_bfloat162(h2, h3);
                    *reinterpret_cast<__nv_bfloat162*>(Cl + (size_t)(rbase + 8) * ldc + cb)
                        = __nv_bfloat162(l2, l3);
                } else {
                    __half h0 = __float2half(v0), h1 = __float2half(v1);
                    __half h2 = __float2half(v2), h3 = __float2half(v3);
                    __half l0 = __float2half(v0 - __half2float(h0));
                    __half l1 = __float2half(v1 - __half2float(h1));
                    __half l2 = __float2half(v2 - __half2float(h2));
                    __half l3 = __float2half(v3 - __half2float(h3));
                    __half* CH = reinterpret_cast<__half*>(Ch);
                    __half* CL = reinterpret_cast<__half*>(Cl);
                    auto pk = [](__half a, __half b) {
                        return (uint32_t)__half_as_ushort(a) |
                               ((uint32_t)__half_as_ushort(b) << 16);
                    };
                    *reinterpret_cast<uint32_t*>(CH + (size_t)rbase * ldc + cb) = pk(h0, h1);
                    *reinterpret_cast<uint32_t*>(CL + (size_t)rbase * ldc + cb) = pk(l0, l1);
                    *reinterpret_cast<uint32_t*>(CH + (size_t)(rbase + 8) * ldc + cb) = pk(h2, h3);
                    *reinterpret_cast<uint32_t*>(CL + (size_t)(rbase + 8) * ldc + cb) = pk(l2, l3);
                }
            }
        }
    }

    if (MODE == 3) {
#pragma unroll
        for (int mi = 0; mi < 2; mi++)
#pragma unroll
            for (int h = 0; h < 2; h++) {
                rs[mi][h] += __shfl_xor_sync(0xffffffffu, rs[mi][h], 1);
                rs[mi][h] += __shfl_xor_sync(0xffffffffu, rs[mi][h], 2);
            }
        if ((lane & 3) == 0) {
            const int q = lane >> 2;
            const int t = blockIdx.x * 2 + warp_n;
#pragma unroll
            for (int mi = 0; mi < 2; mi++) {
                const int rl = row0 + warp_m * 32 + mi * 16 + q;
                const size_t rb = (size_t)blockIdx.z * PS;
                psum[(rb + rl) * 64 + t]     = rs[mi][0];
                psum[(rb + rl + 8) * 64 + t] = rs[mi][1];
            }
        }
    }
}

// ---------------------------------------------------------------------------
// PV GEMM: out[128x64 tile] = (P_fp16 @ V_fp16split) * inv[row]
// 2 MMA terms (P*Vh + P*Vl). BN=64 for wave balance (2048 CTAs).
// SMEM/stage: A(P) 128x80B = 10240; B(V) trans 32x144B x2 = 9216 -> 20480.
// ---------------------------------------------------------------------------
#define PV_STAGE 20480
#define PV_SMEM (2 * PV_STAGE)   // 40960

__global__ void __launch_bounds__(256, 2)
gemm_pv(const __half* __restrict__ Pf, const __half* __restrict__ Vh16,
        const __half* __restrict__ Vl16, float* __restrict__ out,
        const float* __restrict__ inv)
{
    extern __shared__ char smem[];
    const uint32_t sb0 = smem_u32(smem);
    const int tid  = threadIdx.x;
    const int lane = tid & 31;
    const int wid  = tid >> 5;
    const int warp_m = wid & 3;        // 4 warps x 32 rows
    const int warp_n = wid >> 2;       // 2 warps x 32 cols
    const int bz = blockIdx.z;
    const int row0 = blockIdx.y * 128;
    const int col0 = blockIdx.x * 64;

    const __half* A  = Pf   + (size_t)bz * PS * PS;
    const __half* Bh = Vh16 + (size_t)bz * PS * PD;
    const __half* Bl = Vl16 + (size_t)bz * PS * PD;

    float acc[2][4][4];
#pragma unroll
    for (int i = 0; i < 2; i++)
#pragma unroll
        for (int n = 0; n < 4; n++)
#pragma unroll
            for (int j = 0; j < 4; j++) acc[i][n][j] = 0.0f;

    const int nk = PS >> 5;   // 128 chunks

    auto load_stage = [&](int stage, int ki) {
        const uint32_t sb = sb0 + stage * PV_STAGE;
        const int k0 = ki << 5;
        // A: 128 rows x 32 halves = 512 x 16B chunks, 2/thread
#pragma unroll
        for (int it = 0; it < 2; it++) {
            int idx = tid + (it << 8);
            int r = idx >> 2, c4 = idx & 3;
            cp16(sb + r * 80 + c4 * 16,
                 A + (size_t)(row0 + r) * PS + k0 + c4 * 8);
        }
        // B: hi/lo, 32 k-rows x 64 halves = 256 x 16B each, 2/thread total
#pragma unroll
        for (int it = 0; it < 2; it++) {
            int idx = tid + (it << 8);
            int hl = idx >> 8, e = idx & 255;
            int r = e >> 3, c8 = e & 7;
            const __half* src = hl ? Bl : Bh;
            cp16(sb + 10240 + hl * 4608 + r * 144 + c8 * 16,
                 src + (size_t)(k0 + r) * PD + col0 + c8 * 8);
        }
        cp_commit();
    };

    load_stage(0, 0);
    cp_wait<0>();
    __syncthreads();

    for (int i = 0; i < nk; i++) {
        if (i + 1 < nk) load_stage((i + 1) & 1, i + 1);

        const uint32_t sA0  = sb0 + (i & 1) * PV_STAGE;
        const uint32_t sB0h = sA0 + 10240;
        const uint32_t sB0l = sB0h + 4608;

#pragma unroll
        for (int kk = 0; kk < 2; kk++) {
            const int k16 = kk << 4;

            uint32_t a[2][4];
#pragma unroll
            for (int mi = 0; mi < 2; mi++) {
                int m = warp_m * 32 + mi * 16 + (lane & 15);
                int k = k16 + ((lane & 16) ? 8 : 0);
                ldsm_x4(sA0 + m * 80 + k * 2, a[mi]);
            }

            uint32_t bh2[2][4], bl2[2][4];
#pragma unroll
            for (int nt = 0; nt < 2; nt++) {
                int k = k16 + (lane & 15);
                int n = warp_n * 32 + nt * 16 + ((lane & 16) ? 8 : 0);
                ldsm_x4_t(sB0h + k * 144 + n * 2, bh2[nt]);
                ldsm_x4_t(sB0l + k * 144 + n * 2, bl2[nt]);
            }

#pragma unroll
            for (int mi = 0; mi < 2; mi++)
#pragma unroll
                for (int nt = 0; nt < 2; nt++)
#pragma unroll
                    for (int nn = 0; nn < 2; nn++) {
                        float* c = acc[mi][2 * nt + nn];
                        mma_f16(c, a[mi], bh2[nt] + 2 * nn);
                        mma_f16(c, a[mi], bl2[nt] + 2 * nn);
                    }
        }

        if (i + 1 < nk) {
            cp_wait<0>();
            __syncthreads();
        }
    }

    // epilogue: scale by 1/rowsum
#pragma unroll
    for (int mi = 0; mi < 2; mi++) {
        const int rbase = row0 + warp_m * 32 + mi * 16 + (lane >> 2);
        const float iv0 = inv[(size_t)bz * PS + rbase];
        const float iv1 = inv[(size_t)bz * PS + rbase + 8];
        float* base = out + (size_t)bz * PS * PD;
#pragma unroll
        for (int n = 0; n < 4; n++) {
            const int cb = col0 + warp_n * 32 + n * 8 + 2 * (lane & 3);
            float2 v0 = make_float2(acc[mi][n][0] * iv0, acc[mi][n][1] * iv0);
            float2 v1 = make_float2(acc[mi][n][2] * iv1, acc[mi][n][3] * iv1);
            *reinterpret_cast<float2*>(base + (size_t)rbase * PD + cb) = v0;
            *reinterpret_cast<float2*>(base + (size_t)(rbase + 8) * PD + cb) = v1;
        }
    }
}

// ---------------------------------------------------------------------------
// Merged fp32 -> bf16 hi/lo splits for x, Wq, Wk, Wv (one launch)
// ---------------------------------------------------------------------------
struct SplitArgs {
    const float* src[4];
    __nv_bfloat16* dh[4];
    __nv_bfloat16* dl[4];
};

__global__ void __launch_bounds__(256)
split_all(SplitArgs sa)
{
    int bid = blockIdx.x;
    int which, boff;
    if (bid < 16384) { which = 0; boff = bid; }
    else { which = 1 + ((bid - 16384) >> 10); boff = (bid - 16384) & 1023; }

    size_t i = (size_t)boff * 256 + threadIdx.x;
    float4 v = reinterpret_cast<const float4*>(sa.src[which])[i];
    float vv[4] = { v.x, v.y, v.z, v.w };
    uint32_t H[2], L[2];
#pragma unroll
    for (int j = 0; j < 2; j++) {
        __nv_bfloat16 h0, l0, h1, l1;
        split1(vv[2 * j],     h0, l0);
        split1(vv[2 * j + 1], h1, l1);
        H[j] = (uint32_t)__bfloat16_as_ushort(h0) |
               ((uint32_t)__bfloat16_as_ushort(h1) << 16);
        L[j] = (uint32_t)__bfloat16_as_ushort(l0) |
               ((uint32_t)__bfloat16_as_ushort(l1) << 16);
    }
    reinterpret_cast<uint2*>(sa.dh[which])[i] = make_uint2(H[0], H[1]);
    reinterpret_cast<uint2*>(sa.dl[which])[i] = make_uint2(L[0], L[1]);
}

// ---------------------------------------------------------------------------
// Rowsum reduce: one warp per row sums 64 partials -> 1/sum
// ---------------------------------------------------------------------------
__global__ void __launch_bounds__(256)
rowsum_inv(const float* __restrict__ psum, float* __restrict__ inv)
{
    const int row  = (blockIdx.x * blockDim.x + threadIdx.x) >> 5;
    const int lane = threadIdx.x & 31;
    float2 v = reinterpret_cast<const float2*>(psum + (size_t)row * 64)[lane];
    float s = v.x + v.y;
#pragma unroll
    for (int o = 16; o > 0; o >>= 1)
        s += __shfl_xor_sync(0xffffffffu, s, o);
    if (lane == 0) inv[row] = 1.0f / s;
}

// ---------------------------------------------------------------------------
// Launcher
// ---------------------------------------------------------------------------
extern "C" void kernel_launch(void* const* d_in, const int* in_sizes, int n_in,
                              void* d_out, int out_size)
{
    (void)in_sizes; (void)n_in; (void)out_size;
    const float* x  = (const float*)d_in[0];
    const float* Wq = (const float*)d_in[1];
    const float* bq = (const float*)d_in[2];
    const float* Wk = (const float*)d_in[3];
    const float* bk = (const float*)d_in[4];
    const float* Wv = (const float*)d_in[5];
    const float* bv = (const float*)d_in[6];
    float* out = (float*)d_out;

    __nv_bfloat16 *xh, *xl, *Wqh, *Wql, *Wkh, *Wkl, *Wvh, *Wvl;
    __nv_bfloat16 *Qh, *Ql, *Kh, *Kl;
    __half *V16h, *V16l, *Pf;
    float *psum, *inv;
    cudaGetSymbolAddress((void**)&xh,  g_xh);
    cudaGetSymbolAddress((void**)&xl,  g_xl);
    cudaGetSymbolAddress((void**)&Wqh, g_Wqh);
    cudaGetSymbolAddress((void**)&Wql, g_Wql);
    cudaGetSymbolAddress((void**)&Wkh, g_Wkh);
    cudaGetSymbolAddress((void**)&Wkl, g_Wkl);
    cudaGetSymbolAddress((void**)&Wvh, g_Wvh);
    cudaGetSymbolAddress((void**)&Wvl, g_Wvl);
    cudaGetSymbolAddress((void**)&Qh,  g_Qh);
    cudaGetSymbolAddress((void**)&Ql,  g_Ql);
    cudaGetSymbolAddress((void**)&Kh,  g_Kh);
    cudaGetSymbolAddress((void**)&Kl,  g_Kl);
    cudaGetSymbolAddress((void**)&V16h, g_V16h);
    cudaGetSymbolAddress((void**)&V16l, g_V16l);
    cudaGetSymbolAddress((void**)&Pf,  g_Pf);
    cudaGetSymbolAddress((void**)&psum, g_psum);
    cudaGetSymbolAddress((void**)&inv,  g_inv);

    cudaFuncSetAttribute((const void*)gemm_mma<0>,
                         cudaFuncAttributeMaxDynamicSharedMemorySize, SMEM_BYTES);
    cudaFuncSetAttribute((const void*)gemm_mma<3>,
                         cudaFuncAttributeMaxDynamicSharedMemorySize, SMEM_BYTES);
    cudaFuncSetAttribute((const void*)gemm_pv,
                         cudaFuncAttributeMaxDynamicSharedMemorySize, PV_SMEM);

    const size_t SD = (size_t)PS * PD;   // 4M elems per batch
    const size_t SS = (size_t)PS * PS;   // 16M elems per batch

    // 1) merged splits: x (16384 blocks) + Wq/Wk/Wv (1024 each)
    SplitArgs sa;
    sa.src[0] = x;  sa.dh[0] = xh;  sa.dl[0] = xl;
    sa.src[1] = Wq; sa.dh[1] = Wqh; sa.dl[1] = Wql;
    sa.src[2] = Wk; sa.dh[2] = Wkh; sa.dl[2] = Wkl;
    sa.src[3] = Wv; sa.dh[3] = Wvh; sa.dl[3] = Wvl;
    split_all<<<16384 + 3 * 1024, 256>>>(sa);

    // 2) merged projections: z=0/1/2 -> Q (bf16), K (bf16), V (fp16 split)
    ProjArgs pa;
    pa.s[0] = { Wqh, Wql, bq, Qh, Ql, 0 };
    pa.s[1] = { Wkh, Wkl, bk, Kh, Kl, 0 };
    pa.s[2] = { Wvh, Wvl, bv,
                reinterpret_cast<__nv_bfloat16*>(V16h),
                reinterpret_cast<__nv_bfloat16*>(V16l), 1 };
    ProjArgs dummy = {};
    dim3 gp(PD / 128, MROWS / 128, 3);
    gemm_mma<0><<<gp, 256, SMEM_BYTES>>>(
        xh, xl, nullptr, nullptr, pa, nullptr, nullptr,
        PD, PD, PD, 1.0f, 0, 0, 0);

    // 3) scores + fused exp -> fp16 P, psum partials
    dim3 gs(PS / 128, PS / 128, PB);
    gemm_mma<3><<<gs, 256, SMEM_BYTES>>>(
        Qh, Ql, Kh, Kl, dummy,
        reinterpret_cast<__nv_bfloat16*>(Pf), psum,
        PD, PD, PS, 0.03125f, SD, SD, SS);

    // 4) rowsum -> 1/sum
    rowsum_inv<<<(PB * PS * 32) / 256, 256>>>(psum, inv);

    // 5) out = (P @ V) * inv   (fp16 2-term, BN=64 for balance)
    dim3 go(PD / 64, PS / 128, PB);
    gemm_pv<<<go, 256, PV_SMEM>>>(Pf, V16h, V16l, out, inv);
}

// round 8
// speedup vs baseline: 1.6075x; 1.2116x over previous
#include <cuda_runtime.h>
#include <cuda_bf16.h>
#include <cuda_fp16.h>
#include <math_constants.h>
#include <cstdint>

// Problem shape (fixed): B=4, S=4096, D=1024
#define PB 4
#define PS 4096
#define PD 1024
#define MROWS (PB * PS)   // 16384

// ---------------------------------------------------------------------------
// Global scratch (allocation-guard-safe __device__ arrays)
// ---------------------------------------------------------------------------
__device__ __nv_bfloat16 g_xh[(size_t)MROWS * PD], g_xl[(size_t)MROWS * PD];
__device__ __nv_bfloat16 g_Wqh[PD * PD], g_Wql[PD * PD];
__device__ __nv_bfloat16 g_Wkh[PD * PD], g_Wkl[PD * PD];
__device__ __nv_bfloat16 g_Wvh[PD * PD], g_Wvl[PD * PD];
__device__ __half g_Q16h[(size_t)MROWS * PD], g_Q16l[(size_t)MROWS * PD];
__device__ __half g_K16[(size_t)MROWS * PD];
__device__ __half g_V16[(size_t)MROWS * PD];
__device__ __half g_Pf[(size_t)PB * PS * PS];    // exp scores, fp16
__device__ float g_psum[(size_t)PB * PS * 64];   // per-row partial expsums
__device__ float g_inv [(size_t)PB * PS];        // 1 / rowsum

// ---------------------------------------------------------------------------
// PTX helpers (baseline sm_80+ features only: compile-safe under compute_103)
// ---------------------------------------------------------------------------
__device__ __forceinline__ uint32_t smem_u32(const void* p) {
    uint32_t a;
    asm("{ .reg .u64 t; cvta.to.shared.u64 t, %1; cvt.u32.u64 %0, t; }"
        : "=r"(a) : "l"(p));
    return a;
}

__device__ __forceinline__ void cp16(uint32_t s, const void* g) {
    asm volatile("cp.async.cg.shared.global [%0], [%1], 16;" :: "r"(s), "l"(g));
}
__device__ __forceinline__ void cp_commit() {
    asm volatile("cp.async.commit_group;" ::: "memory");
}
template<int N>
__device__ __forceinline__ void cp_wait() {
    asm volatile("cp.async.wait_group %0;" :: "n"(N) : "memory");
}

__device__ __forceinline__ void ldsm_x4(uint32_t a, uint32_t* r) {
    asm volatile("ldmatrix.sync.aligned.m8n8.x4.shared.b16 {%0,%1,%2,%3}, [%4];"
                 : "=r"(r[0]), "=r"(r[1]), "=r"(r[2]), "=r"(r[3]) : "r"(a));
}
__device__ __forceinline__ void ldsm_x4_t(uint32_t a, uint32_t* r) {
    asm volatile("ldmatrix.sync.aligned.m8n8.x4.trans.shared.b16 {%0,%1,%2,%3}, [%4];"
                 : "=r"(r[0]), "=r"(r[1]), "=r"(r[2]), "=r"(r[3]) : "r"(a));
}

__device__ __forceinline__ void mma_bf16(float* c, const uint32_t* a,
                                         const uint32_t* b) {
    asm volatile(
        "mma.sync.aligned.m16n8k16.row.col.f32.bf16.bf16.f32 "
        "{%0,%1,%2,%3},{%4,%5,%6,%7},{%8,%9},{%0,%1,%2,%3};"
        : "+f"(c[0]), "+f"(c[1]), "+f"(c[2]), "+f"(c[3])
        : "r"(a[0]), "r"(a[1]), "r"(a[2]), "r"(a[3]), "r"(b[0]), "r"(b[1]));
}

__device__ __forceinline__ void mma_f16(float* c, const uint32_t* a,
                                        const uint32_t* b) {
    asm volatile(
        "mma.sync.aligned.m16n8k16.row.col.f32.f16.f16.f32 "
        "{%0,%1,%2,%3},{%4,%5,%6,%7},{%8,%9},{%0,%1,%2,%3};"
        : "+f"(c[0]), "+f"(c[1]), "+f"(c[2]), "+f"(c[3])
        : "r"(a[0]), "r"(a[1]), "r"(a[2]), "r"(a[3]), "r"(b[0]), "r"(b[1]));
}

__device__ __forceinline__ void split1(float v, __nv_bfloat16& h, __nv_bfloat16& l) {
    h = __float2bfloat16(v);
    l = __float2bfloat16(v - __bfloat162float(h));
}
__device__ __forceinline__ uint32_t pkh(__half a, __half b) {
    return (uint32_t)__half_as_ushort(a) | ((uint32_t)__half_as_ushort(b) << 16);
}

// ---------------------------------------------------------------------------
// Projection GEMM (bf16 3-term): block 128x128, BK=32, 8 warps 32(M)x64(N).
// 2 stages x 40960B = 80KB/CTA -> 2 CTAs/SM.
// Output: mode 1 = fp16 hi/lo split (Q); mode 2 = plain fp16 (K, V).
// ---------------------------------------------------------------------------
#define STAGE_STRIDE 40960
#define SMEM_BYTES (2 * STAGE_STRIDE)   // 81920

struct ProjSet {
    const __nv_bfloat16* Bh;
    const __nv_bfloat16* Bl;
    const float* bias;
    __half* Ch;
    __half* Cl;     // null for mode 2
    int mode;       // 1 = fp16 split, 2 = fp16 single
};
struct ProjArgs { ProjSet s[3]; };

__global__ void __launch_bounds__(256, 2)
gemm_proj(const __nv_bfloat16* __restrict__ Ah, const __nv_bfloat16* __restrict__ Al,
          ProjArgs pa)
{
    extern __shared__ char smem[];
    const uint32_t sb0 = smem_u32(smem);
    const int tid  = threadIdx.x;
    const int lane = tid & 31;
    const int wid  = tid >> 5;
    const int warp_m = wid & 3;
    const int warp_n = wid >> 2;

    const ProjSet& s = pa.s[blockIdx.z];
    const __nv_bfloat16* Bh = s.Bh;
    const __nv_bfloat16* Bl = s.Bl;
    const float* bias = s.bias;
    __half* Ch = s.Ch;
    __half* Cl = s.Cl;
    const int mode = s.mode;

    const int row0 = blockIdx.y * 128;
    const int col0 = blockIdx.x * 128;

    float acc[2][8][4];
#pragma unroll
    for (int i = 0; i < 2; i++)
#pragma unroll
        for (int n = 0; n < 8; n++)
#pragma unroll
            for (int j = 0; j < 4; j++) acc[i][n][j] = 0.0f;

    const int nk = PD >> 5;   // 32 chunks

    auto load_stage = [&](int stage, int ki) {
        const uint32_t sb = sb0 + stage * STAGE_STRIDE;
        const int k0 = ki << 5;
#pragma unroll
        for (int it = 0; it < 4; it++) {
            int idx = tid + (it << 8);
            int hl  = idx >> 9;
            int e   = idx & 511;
            int r   = e >> 2;
            int c4  = e & 3;
            const __nv_bfloat16* src = hl ? Al : Ah;
            cp16(sb + hl * 10240 + r * 80 + c4 * 16,
                 src + (size_t)(row0 + r) * PD + k0 + c4 * 8);
        }
#pragma unroll
        for (int it = 0; it < 4; it++) {
            int idx = tid + (it << 8);
            int hl  = idx >> 9;
            int e   = idx & 511;
            int r   = e >> 2;
            int c4  = e & 3;
            const __nv_bfloat16* src = hl ? Bl : Bh;
            cp16(sb + 20480 + hl * 10240 + r * 80 + c4 * 16,
                 src + (size_t)(col0 + r) * PD + k0 + c4 * 8);
        }
        cp_commit();
    };

    load_stage(0, 0);
    cp_wait<0>();
    __syncthreads();

    for (int i = 0; i < nk; i++) {
        if (i + 1 < nk) load_stage((i + 1) & 1, i + 1);

        const uint32_t sA0 = sb0 + (i & 1) * STAGE_STRIDE;
        const uint32_t sB0 = sA0 + 20480;

#pragma unroll
        for (int kk = 0; kk < 2; kk++) {
            const int k16 = kk << 4;

            uint32_t ah[2][4], al[2][4];
#pragma unroll
            for (int mi = 0; mi < 2; mi++) {
                int m = warp_m * 32 + mi * 16 + (lane & 15);
                int k = k16 + ((lane & 16) ? 8 : 0);
                ldsm_x4(sA0 +         m * 80 + k * 2, ah[mi]);
                ldsm_x4(sA0 + 10240 + m * 80 + k * 2, al[mi]);
            }

#pragma unroll
            for (int nt = 0; nt < 4; nt++) {
                uint32_t bh2[4], bl2[4];
                int n = warp_n * 64 + nt * 16 + ((lane & 16) ? 8 : 0) + (lane & 7);
                int k = k16 + (lane & 8);
                ldsm_x4(sB0 +         n * 80 + k * 2, bh2);
                ldsm_x4(sB0 + 10240 + n * 80 + k * 2, bl2);
#pragma unroll
                for (int mi = 0; mi < 2; mi++)
#pragma unroll
                    for (int nn = 0; nn < 2; nn++) {
                        float* a = acc[mi][2 * nt + nn];
                        mma_bf16(a, ah[mi], bh2 + 2 * nn);
                        mma_bf16(a, ah[mi], bl2 + 2 * nn);
                        mma_bf16(a, al[mi], bh2 + 2 * nn);
                    }
            }
        }

        if (i + 1 < nk) {
            cp_wait<0>();
            __syncthreads();
        }
    }

    // epilogue
#pragma unroll
    for (int mi = 0; mi < 2; mi++) {
        const int rbase = row0 + warp_m * 32 + mi * 16 + (lane >> 2);
#pragma unroll
        for (int n = 0; n < 8; n++) {
            const int cb = col0 + warp_n * 64 + n * 8 + 2 * (lane & 3);
            float b0 = bias[cb], b1 = bias[cb + 1];
            float v0 = acc[mi][n][0] + b0;
            float v1 = acc[mi][n][1] + b1;
            float v2 = acc[mi][n][2] + b0;
            float v3 = acc[mi][n][3] + b1;
            __half h0 = __float2half(v0), h1 = __float2half(v1);
            __half h2 = __float2half(v2), h3 = __float2half(v3);
            *reinterpret_cast<uint32_t*>(Ch + (size_t)rbase * PD + cb) = pkh(h0, h1);
            *reinterpret_cast<uint32_t*>(Ch + (size_t)(rbase + 8) * PD + cb) = pkh(h2, h3);
            if (mode == 1) {
                __half l0 = __float2half(v0 - __half2float(h0));
                __half l1 = __float2half(v1 - __half2float(h1));
                __half l2 = __float2half(v2 - __half2float(h2));
                __half l3 = __float2half(v3 - __half2float(h3));
                *reinterpret_cast<uint32_t*>(Cl + (size_t)rbase * PD + cb) = pkh(l0, l1);
                *reinterpret_cast<uint32_t*>(Cl + (size_t)(rbase + 8) * PD + cb) = pkh(l2, l3);
            }
        }
    }
}

// ---------------------------------------------------------------------------
// Scores GEMM (fp16 2-term): P = exp((Qh + Ql) @ K^T * scale), fp16 out + psum.
// A = Q fp16 hi/lo, B = K plain fp16 (NT, K-major).
// Stage: A 2x10240 + B 10240 = 30720; 2 stages = 61440 -> 2 CTAs/SM.
// ---------------------------------------------------------------------------
#define SC_STAGE 30720
#define SC_SMEM (2 * SC_STAGE)   // 61440

__global__ void __launch_bounds__(256, 2)
gemm_scores(const __half* __restrict__ Qh16, const __half* __restrict__ Ql16,
            const __half* __restrict__ K16,
            __half* __restrict__ Pf, float* __restrict__ psum)
{
    extern __shared__ char smem[];
    const uint32_t sb0 = smem_u32(smem);
    const int tid  = threadIdx.x;
    const int lane = tid & 31;
    const int wid  = tid >> 5;
    const int warp_m = wid & 3;
    const int warp_n = wid >> 2;
    const int bz = blockIdx.z;

    const __half* Ah = Qh16 + (size_t)bz * PS * PD;
    const __half* Al = Ql16 + (size_t)bz * PS * PD;
    const __half* Bk = K16  + (size_t)bz * PS * PD;
    __half* P = Pf + (size_t)bz * PS * PS;

    const int row0 = blockIdx.y * 128;
    const int col0 = blockIdx.x * 128;

    float acc[2][8][4];
#pragma unroll
    for (int i = 0; i < 2; i++)
#pragma unroll
        for (int n = 0; n < 8; n++)
#pragma unroll
            for (int j = 0; j < 4; j++) acc[i][n][j] = 0.0f;

    const int nk = PD >> 5;   // 32 chunks

    auto load_stage = [&](int stage, int ki) {
        const uint32_t sb = sb0 + stage * SC_STAGE;
        const int k0 = ki << 5;
        // A: Q hi/lo, 1024 x 16B chunks, 4/thread
#pragma unroll
        for (int it = 0; it < 4; it++) {
            int idx = tid + (it << 8);
            int hl  = idx >> 9;
            int e   = idx & 511;
            int r   = e >> 2;
            int c4  = e & 3;
            const __half* src = hl ? Al : Ah;
            cp16(sb + hl * 10240 + r * 80 + c4 * 16,
                 src + (size_t)(row0 + r) * PD + k0 + c4 * 8);
        }
        // B: K single, 512 x 16B chunks, 2/thread
#pragma unroll
        for (int it = 0; it < 2; it++) {
            int idx = tid + (it << 8);
            int r   = idx >> 2;
            int c4  = idx & 3;
            cp16(sb + 20480 + r * 80 + c4 * 16,
                 Bk + (size_t)(col0 + r) * PD + k0 + c4 * 8);
        }
        cp_commit();
    };

    load_stage(0, 0);
    cp_wait<0>();
    __syncthreads();

    for (int i = 0; i < nk; i++) {
        if (i + 1 < nk) load_stage((i + 1) & 1, i + 1);

        const uint32_t sA0 = sb0 + (i & 1) * SC_STAGE;
        const uint32_t sB0 = sA0 + 20480;

#pragma unroll
        for (int kk = 0; kk < 2; kk++) {
            const int k16 = kk << 4;

            uint32_t ah[2][4], al[2][4];
#pragma unroll
            for (int mi = 0; mi < 2; mi++) {
                int m = warp_m * 32 + mi * 16 + (lane & 15);
                int k = k16 + ((lane & 16) ? 8 : 0);
                ldsm_x4(sA0 +         m * 80 + k * 2, ah[mi]);
                ldsm_x4(sA0 + 10240 + m * 80 + k * 2, al[mi]);
            }

#pragma unroll
            for (int nt = 0; nt < 4; nt++) {
                uint32_t b4[4];
                int n = warp_n * 64 + nt * 16 + ((lane & 16) ? 8 : 0) + (lane & 7);
                int k = k16 + (lane & 8);
                ldsm_x4(sB0 + n * 80 + k * 2, b4);
#pragma unroll
                for (int mi = 0; mi < 2; mi++)
#pragma unroll
                    for (int nn = 0; nn < 2; nn++) {
                        float* a = acc[mi][2 * nt + nn];
                        mma_f16(a, ah[mi], b4 + 2 * nn);
                        mma_f16(a, al[mi], b4 + 2 * nn);
                    }
            }
        }

        if (i + 1 < nk) {
            cp_wait<0>();
            __syncthreads();
        }
    }

    // epilogue: exp -> fp16 P, partial rowsums
    float rs[2][2] = {{0.0f, 0.0f}, {0.0f, 0.0f}};
    const float scale = 0.03125f;

#pragma unroll
    for (int mi = 0; mi < 2; mi++) {
        const int rbase = row0 + warp_m * 32 + mi * 16 + (lane >> 2);
#pragma unroll
        for (int n = 0; n < 8; n++) {
            const int cb = col0 + warp_n * 64 + n * 8 + 2 * (lane & 3);
            float e0 = __expf(acc[mi][n][0] * scale);
            float e1 = __expf(acc[mi][n][1] * scale);
            float e2 = __expf(acc[mi][n][2] * scale);
            float e3 = __expf(acc[mi][n][3] * scale);
            __half q0 = __float2half(e0), q1 = __float2half(e1);
            __half q2 = __float2half(e2), q3 = __float2half(e3);
            rs[mi][0] += __half2float(q0) + __half2float(q1);
            rs[mi][1] += __half2float(q2) + __half2float(q3);
            *reinterpret_cast<uint32_t*>(P + (size_t)rbase * PS + cb) = pkh(q0, q1);
            *reinterpret_cast<uint32_t*>(P + (size_t)(rbase + 8) * PS + cb) = pkh(q2, q3);
        }
    }

#pragma unroll
    for (int mi = 0; mi < 2; mi++)
#pragma unroll
        for (int h = 0; h < 2; h++) {
            rs[mi][h] += __shfl_xor_sync(0xffffffffu, rs[mi][h], 1);
            rs[mi][h] += __shfl_xor_sync(0xffffffffu, rs[mi][h], 2);
        }
    if ((lane & 3) == 0) {
        const int q = lane >> 2;
        const int t = blockIdx.x * 2 + warp_n;
#pragma unroll
        for (int mi = 0; mi < 2; mi++) {
            const int rl = row0 + warp_m * 32 + mi * 16 + q;
            const size_t rb = (size_t)bz * PS;
            psum[(rb + rl) * 64 + t]     = rs[mi][0];
            psum[(rb + rl + 8) * 64 + t] = rs[mi][1];
        }
    }
}

// ---------------------------------------------------------------------------
// PV GEMM (fp16 1-term): out[128x64] = (P @ V) * inv[row].
// Stage: A(P) 10240 + B(V) 4608 = 14848; 2 stages = 29696.
// ---------------------------------------------------------------------------
#define PV_STAGE 14848
#define PV_SMEM (2 * PV_STAGE)   // 29696

__global__ void __launch_bounds__(256, 2)
gemm_pv(const __half* __restrict__ Pf, const __half* __restrict__ V16,
        float* __restrict__ out, const float* __restrict__ inv)
{
    extern __shared__ char smem[];
    const uint32_t sb0 = smem_u32(smem);
    const int tid  = threadIdx.x;
    const int lane = tid & 31;
    const int wid  = tid >> 5;
    const int warp_m = wid & 3;
    const int warp_n = wid >> 2;
    const int bz = blockIdx.z;
    const int row0 = blockIdx.y * 128;
    const int col0 = blockIdx.x * 64;

    const __half* A = Pf  + (size_t)bz * PS * PS;
    const __half* B = V16 + (size_t)bz * PS * PD;

    float acc[2][4][4];
#pragma unroll
    for (int i = 0; i < 2; i++)
#pragma unroll
        for (int n = 0; n < 4; n++)
#pragma unroll
            for (int j = 0; j < 4; j++) acc[i][n][j] = 0.0f;

    const int nk = PS >> 5;   // 128 chunks

    auto load_stage = [&](int stage, int ki) {
        const uint32_t sb = sb0 + stage * PV_STAGE;
        const int k0 = ki << 5;
        // A: 512 x 16B chunks, 2/thread
#pragma unroll
        for (int it = 0; it < 2; it++) {
            int idx = tid + (it << 8);
            int r = idx >> 2, c4 = idx & 3;
            cp16(sb + r * 80 + c4 * 16,
                 A + (size_t)(row0 + r) * PS + k0 + c4 * 8);
        }
        // B: 32 k-rows x 64 halves = 256 x 16B, 1/thread, rows padded 144B
        {
            int r = tid >> 3, c8 = tid & 7;
            cp16(sb + 10240 + r * 144 + c8 * 16,
                 B + (size_t)(k0 + r) * PD + col0 + c8 * 8);
        }
        cp_commit();
    };

    load_stage(0, 0);
    cp_wait<0>();
    __syncthreads();

    for (int i = 0; i < nk; i++) {
        if (i + 1 < nk) load_stage((i + 1) & 1, i + 1);

        const uint32_t sA0 = sb0 + (i & 1) * PV_STAGE;
        const uint32_t sB0 = sA0 + 10240;

#pragma unroll
        for (int kk = 0; kk < 2; kk++) {
            const int k16 = kk << 4;

            uint32_t a[2][4];
#pragma unroll
            for (int mi = 0; mi < 2; mi++) {
                int m = warp_m * 32 + mi * 16 + (lane & 15);
                int k = k16 + ((lane & 16) ? 8 : 0);
                ldsm_x4(sA0 + m * 80 + k * 2, a[mi]);
            }

#pragma unroll
            for (int nt = 0; nt < 2; nt++) {
                uint32_t b4[4];
                int k = k16 + (lane & 15);
                int n = warp_n * 32 + nt * 16 + ((lane & 16) ? 8 : 0);
                ldsm_x4_t(sB0 + k * 144 + n * 2, b4);
#pragma unroll
                for (int mi = 0; mi < 2; mi++)
#pragma unroll
                    for (int nn = 0; nn < 2; nn++)
                        mma_f16(acc[mi][2 * nt + nn], a[mi], b4 + 2 * nn);
            }
        }

        if (i + 1 < nk) {
            cp_wait<0>();
            __syncthreads();
        }
    }

    // epilogue: scale by 1/rowsum
#pragma unroll
    for (int mi = 0; mi < 2; mi++) {
        const int rbase = row0 + warp_m * 32 + mi * 16 + (lane >> 2);
        const float iv0 = inv[(size_t)bz * PS + rbase];
        const float iv1 = inv[(size_t)bz * PS + rbase + 8];
        float* base = out + (size_t)bz * PS * PD;
#pragma unroll
        for (int n = 0; n < 4; n++) {
            const int cb = col0 + warp_n * 32 + n * 8 + 2 * (lane & 3);
            float2 v0 = make_float2(acc[mi][n][0] * iv0, acc[mi][n][1] * iv0);
            float2 v1 = make_float2(acc[mi][n][2] * iv1, acc[mi][n][3] * iv1);
            *reinterpret_cast<float2*>(base + (size_t)rbase * PD + cb) = v0;
            *reinterpret_cast<float2*>(base + (size_t)(rbase + 8) * PD + cb) = v1;
        }
    }
}

// ---------------------------------------------------------------------------
// Merged fp32 -> bf16 hi/lo splits for x, Wq, Wk, Wv (one launch)
// ---------------------------------------------------------------------------
struct SplitArgs {
    const float* src[4];
    __nv_bfloat16* dh[4];
    __nv_bfloat16* dl[4];
};

__global__ void __launch_bounds__(256)
split_all(SplitArgs sa)
{
    int bid = blockIdx.x;
    int which, boff;
    if (bid < 16384) { which = 0; boff = bid; }
    else { which = 1 + ((bid - 16384) >> 10); boff = (bid - 16384) & 1023; }

    size_t i = (size_t)boff * 256 + threadIdx.x;
    float4 v = reinterpret_cast<const float4*>(sa.src[which])[i];
    float vv[4] = { v.x, v.y, v.z, v.w };
    uint32_t H[2], L[2];
#pragma unroll
    for (int j = 0; j < 2; j++) {
        __nv_bfloat16 h0, l0, h1, l1;
        split1(vv[2 * j],     h0, l0);
        split1(vv[2 * j + 1], h1, l1);
        H[j] = (uint32_t)__bfloat16_as_ushort(h0) |
               ((uint32_t)__bfloat16_as_ushort(h1) << 16);
        L[j] = (uint32_t)__bfloat16_as_ushort(l0) |
               ((uint32_t)__bfloat16_as_ushort(l1) << 16);
    }
    reinterpret_cast<uint2*>(sa.dh[which])[i] = make_uint2(H[0], H[1]);
    reinterpret_cast<uint2*>(sa.dl[which])[i] = make_uint2(L[0], L[1]);
}

// ---------------------------------------------------------------------------
// Rowsum reduce: one warp per row sums 64 partials -> 1/sum
// ---------------------------------------------------------------------------
__global__ void __launch_bounds__(256)
rowsum_inv(const float* __restrict__ psum, float* __restrict__ inv)
{
    const int row  = (blockIdx.x * blockDim.x + threadIdx.x) >> 5;
    const int lane = threadIdx.x & 31;
    float2 v = reinterpret_cast<const float2*>(psum + (size_t)row * 64)[lane];
    float s = v.x + v.y;
#pragma unroll
    for (int o = 16; o > 0; o >>= 1)
        s += __shfl_xor_sync(0xffffffffu, s, o);
    if (lane == 0) inv[row] = 1.0f / s;
}

// ---------------------------------------------------------------------------
// Launcher
// ---------------------------------------------------------------------------
extern "C" void kernel_launch(void* const* d_in, const int* in_sizes, int n_in,
                              void* d_out, int out_size)
{
    (void)in_sizes; (void)n_in; (void)out_size;
    const float* x  = (const float*)d_in[0];
    const float* Wq = (const float*)d_in[1];
    const float* bq = (const float*)d_in[2];
    const float* Wk = (const float*)d_in[3];
    const float* bk = (const float*)d_in[4];
    const float* Wv = (const float*)d_in[5];
    const float* bv = (const float*)d_in[6];
    float* out = (float*)d_out;

    __nv_bfloat16 *xh, *xl, *Wqh, *Wql, *Wkh, *Wkl, *Wvh, *Wvl;
    __half *Q16h, *Q16l, *K16, *V16, *Pf;
    float *psum, *inv;
    cudaGetSymbolAddress((void**)&xh,  g_xh);
    cudaGetSymbolAddress((void**)&xl,  g_xl);
    cudaGetSymbolAddress((void**)&Wqh, g_Wqh);
    cudaGetSymbolAddress((void**)&Wql, g_Wql);
    cudaGetSymbolAddress((void**)&Wkh, g_Wkh);
    cudaGetSymbolAddress((void**)&Wkl, g_Wkl);
    cudaGetSymbolAddress((void**)&Wvh, g_Wvh);
    cudaGetSymbolAddress((void**)&Wvl, g_Wvl);
    cudaGetSymbolAddress((void**)&Q16h, g_Q16h);
    cudaGetSymbolAddress((void**)&Q16l, g_Q16l);
    cudaGetSymbolAddress((void**)&K16,  g_K16);
    cudaGetSymbolAddress((void**)&V16,  g_V16);
    cudaGetSymbolAddress((void**)&Pf,   g_Pf);
    cudaGetSymbolAddress((void**)&psum, g_psum);
    cudaGetSymbolAddress((void**)&inv,  g_inv);

    cudaFuncSetAttribute((const void*)gemm_proj,
                         cudaFuncAttributeMaxDynamicSharedMemorySize, SMEM_BYTES);
    cudaFuncSetAttribute((const void*)gemm_scores,
                         cudaFuncAttributeMaxDynamicSharedMemorySize, SC_SMEM);
    cudaFuncSetAttribute((const void*)gemm_pv,
                         cudaFuncAttributeMaxDynamicSharedMemorySize, PV_SMEM);

    // 1) merged splits: x (16384 blocks) + Wq/Wk/Wv (1024 each)
    SplitArgs sa;
    sa.src[0] = x;  sa.dh[0] = xh;  sa.dl[0] = xl;
    sa.src[1] = Wq; sa.dh[1] = Wqh; sa.dl[1] = Wql;
    sa.src[2] = Wk; sa.dh[2] = Wkh; sa.dl[2] = Wkl;
    sa.src[3] = Wv; sa.dh[3] = Wvh; sa.dl[3] = Wvl;
    split_all<<<16384 + 3 * 1024, 256>>>(sa);

    // 2) merged projections: Q -> fp16 split, K/V -> plain fp16
    ProjArgs pa;
    pa.s[0] = { Wqh, Wql, bq, Q16h, Q16l, 1 };
    pa.s[1] = { Wkh, Wkl, bk, K16,  nullptr, 2 };
    pa.s[2] = { Wvh, Wvl, bv, V16,  nullptr, 2 };
    dim3 gp(PD / 128, MROWS / 128, 3);
    gemm_proj<<<gp, 256, SMEM_BYTES>>>(xh, xl, pa);

    // 3) scores + fused exp (fp16 2-term) -> fp16 P, psum partials
    dim3 gs(PS / 128, PS / 128, PB);
    gemm_scores<<<gs, 256, SC_SMEM>>>(Q16h, Q16l, K16, Pf, psum);

    // 4) rowsum -> 1/sum
    rowsum_inv<<<(PB * PS * 32) / 256, 256>>>(psum, inv);

    // 5) out = (P @ V) * inv   (fp16 1-term, BN=64)
    dim3 go(PD / 64, PS / 128, PB);
    gemm_pv<<<go, 256, PV_SMEM>>>(Pf, V16, out, inv);
}

// round 9
// speedup vs baseline: 2.1489x; 1.3368x over previous
#include <cuda_runtime.h>
#include <cuda_fp16.h>
#include <math_constants.h>
#include <cstdint>

// Problem shape (fixed): B=4, S=4096, D=1024
#define PB 4
#define PS 4096
#define PD 1024
#define MROWS (PB * PS)   // 16384

// ---------------------------------------------------------------------------
// Global scratch (allocation-guard-safe __device__ arrays)
// ---------------------------------------------------------------------------
__device__ __half g_xh[(size_t)MROWS * PD], g_xl[(size_t)MROWS * PD];
__device__ __half g_Wq16[PD * PD], g_Wk16[PD * PD], g_Wv16[PD * PD];
__device__ __half g_Q16[(size_t)MROWS * PD];
__device__ __half g_K16[(size_t)MROWS * PD];
__device__ __half g_V16[(size_t)MROWS * PD];
__device__ __half g_Pf[(size_t)PB * PS * PS];    // exp scores, fp16
__device__ float g_psum[(size_t)PB * PS * 64];   // per-row partial expsums
__device__ float g_inv [(size_t)PB * PS];        // 1 / rowsum

// ---------------------------------------------------------------------------
// PTX helpers (baseline sm_80+ features only: compile-safe under compute_103)
// ---------------------------------------------------------------------------
__device__ __forceinline__ uint32_t smem_u32(const void* p) {
    uint32_t a;
    asm("{ .reg .u64 t; cvta.to.shared.u64 t, %1; cvt.u32.u64 %0, t; }"
        : "=r"(a) : "l"(p));
    return a;
}

__device__ __forceinline__ void cp16(uint32_t s, const void* g) {
    asm volatile("cp.async.cg.shared.global [%0], [%1], 16;" :: "r"(s), "l"(g));
}
__device__ __forceinline__ void cp_commit() {
    asm volatile("cp.async.commit_group;" ::: "memory");
}
template<int N>
__device__ __forceinline__ void cp_wait() {
    asm volatile("cp.async.wait_group %0;" :: "n"(N) : "memory");
}

__device__ __forceinline__ void ldsm_x4(uint32_t a, uint32_t* r) {
    asm volatile("ldmatrix.sync.aligned.m8n8.x4.shared.b16 {%0,%1,%2,%3}, [%4];"
                 : "=r"(r[0]), "=r"(r[1]), "=r"(r[2]), "=r"(r[3]) : "r"(a));
}
__device__ __forceinline__ void ldsm_x4_t(uint32_t a, uint32_t* r) {
    asm volatile("ldmatrix.sync.aligned.m8n8.x4.trans.shared.b16 {%0,%1,%2,%3}, [%4];"
                 : "=r"(r[0]), "=r"(r[1]), "=r"(r[2]), "=r"(r[3]) : "r"(a));
}

__device__ __forceinline__ void mma_f16(float* c, const uint32_t* a,
                                        const uint32_t* b) {
    asm volatile(
        "mma.sync.aligned.m16n8k16.row.col.f32.f16.f16.f32 "
        "{%0,%1,%2,%3},{%4,%5,%6,%7},{%8,%9},{%0,%1,%2,%3};"
        : "+f"(c[0]), "+f"(c[1]), "+f"(c[2]), "+f"(c[3])
        : "r"(a[0]), "r"(a[1]), "r"(a[2]), "r"(a[3]), "r"(b[0]), "r"(b[1]));
}

__device__ __forceinline__ uint32_t pkh(__half a, __half b) {
    return (uint32_t)__half_as_ushort(a) | ((uint32_t)__half_as_ushort(b) << 16);
}

// ---------------------------------------------------------------------------
// Projection GEMM (fp16 2-term): C = (xh + xl) @ W^T + b, plain fp16 out.
// Block 128x128, BK=32, 8 warps 32(M)x64(N).
// Stage: A hi/lo 2x10240 + B 10240 = 30720; 2 stages = 61440 -> 2 CTAs/SM.
// ---------------------------------------------------------------------------
#define PJ_STAGE 30720
#define PJ_SMEM (2 * PJ_STAGE)   // 61440

struct ProjSet {
    const __half* W16;
    const float* bias;
    __half* C16;
};
struct ProjArgs { ProjSet s[3]; };

__global__ void __launch_bounds__(256, 2)
gemm_proj(const __half* __restrict__ Ah, const __half* __restrict__ Al,
          ProjArgs pa)
{
    extern __shared__ char smem[];
    const uint32_t sb0 = smem_u32(smem);
    const int tid  = threadIdx.x;
    const int lane = tid & 31;
    const int wid  = tid >> 5;
    const int warp_m = wid & 3;
    const int warp_n = wid >> 2;

    const ProjSet& s = pa.s[blockIdx.z];
    const __half* Bw = s.W16;
    const float* bias = s.bias;
    __half* C = s.C16;

    const int row0 = blockIdx.y * 128;
    const int col0 = blockIdx.x * 128;

    float acc[2][8][4];
#pragma unroll
    for (int i = 0; i < 2; i++)
#pragma unroll
        for (int n = 0; n < 8; n++)
#pragma unroll
            for (int j = 0; j < 4; j++) acc[i][n][j] = 0.0f;

    const int nk = PD >> 5;   // 32 chunks

    auto load_stage = [&](int stage, int ki) {
        const uint32_t sb = sb0 + stage * PJ_STAGE;
        const int k0 = ki << 5;
        // A: x hi/lo, 1024 x 16B chunks, 4/thread
#pragma unroll
        for (int it = 0; it < 4; it++) {
            int idx = tid + (it << 8);
            int hl  = idx >> 9;
            int e   = idx & 511;
            int r   = e >> 2;
            int c4  = e & 3;
            const __half* src = hl ? Al : Ah;
            cp16(sb + hl * 10240 + r * 80 + c4 * 16,
                 src + (size_t)(row0 + r) * PD + k0 + c4 * 8);
        }
        // B: W single, 512 x 16B chunks, 2/thread
#pragma unroll
        for (int it = 0; it < 2; it++) {
            int idx = tid + (it << 8);
            int r   = idx >> 2;
            int c4  = idx & 3;
            cp16(sb + 20480 + r * 80 + c4 * 16,
                 Bw + (size_t)(col0 + r) * PD + k0 + c4 * 8);
        }
        cp_commit();
    };

    load_stage(0, 0);
    cp_wait<0>();
    __syncthreads();

    for (int i = 0; i < nk; i++) {
        if (i + 1 < nk) load_stage((i + 1) & 1, i + 1);

        const uint32_t sA0 = sb0 + (i & 1) * PJ_STAGE;
        const uint32_t sB0 = sA0 + 20480;

#pragma unroll
        for (int kk = 0; kk < 2; kk++) {
            const int k16 = kk << 4;

            uint32_t ah[2][4], al[2][4];
#pragma unroll
            for (int mi = 0; mi < 2; mi++) {
                int m = warp_m * 32 + mi * 16 + (lane & 15);
                int k = k16 + ((lane & 16) ? 8 : 0);
                ldsm_x4(sA0 +         m * 80 + k * 2, ah[mi]);
                ldsm_x4(sA0 + 10240 + m * 80 + k * 2, al[mi]);
            }

#pragma unroll
            for (int nt = 0; nt < 4; nt++) {
                uint32_t b4[4];
                int n = warp_n * 64 + nt * 16 + ((lane & 16) ? 8 : 0) + (lane & 7);
                int k = k16 + (lane & 8);
                ldsm_x4(sB0 + n * 80 + k * 2, b4);
#pragma unroll
                for (int mi = 0; mi < 2; mi++)
#pragma unroll
                    for (int nn = 0; nn < 2; nn++) {
                        float* a = acc[mi][2 * nt + nn];
                        mma_f16(a, ah[mi], b4 + 2 * nn);
                        mma_f16(a, al[mi], b4 + 2 * nn);
                    }
            }
        }

        if (i + 1 < nk) {
            cp_wait<0>();
            __syncthreads();
        }
    }

    // epilogue: +bias, plain fp16
#pragma unroll
    for (int mi = 0; mi < 2; mi++) {
        const int rbase = row0 + warp_m * 32 + mi * 16 + (lane >> 2);
#pragma unroll
        for (int n = 0; n < 8; n++) {
            const int cb = col0 + warp_n * 64 + n * 8 + 2 * (lane & 3);
            float b0 = bias[cb], b1 = bias[cb + 1];
            __half h0 = __float2half(acc[mi][n][0] + b0);
            __half h1 = __float2half(acc[mi][n][1] + b1);
            __half h2 = __float2half(acc[mi][n][2] + b0);
            __half h3 = __float2half(acc[mi][n][3] + b1);
            *reinterpret_cast<uint32_t*>(C + (size_t)rbase * PD + cb) = pkh(h0, h1);
            *reinterpret_cast<uint32_t*>(C + (size_t)(rbase + 8) * PD + cb) = pkh(h2, h3);
        }
    }
}

// ---------------------------------------------------------------------------
// Scores GEMM (fp16 1-term): P = exp(Q @ K^T * scale), fp16 out + psum.
// Stage: A 10240 + B 10240 = 20480; 2 stages = 40960 -> 2 CTAs/SM.
// ---------------------------------------------------------------------------
#define SC_STAGE 20480
#define SC_SMEM (2 * SC_STAGE)   // 40960

__global__ void __launch_bounds__(256, 2)
gemm_scores(const __half* __restrict__ Q16, const __half* __restrict__ K16,
            __half* __restrict__ Pf, float* __restrict__ psum)
{
    extern __shared__ char smem[];
    const uint32_t sb0 = smem_u32(smem);
    const int tid  = threadIdx.x;
    const int lane = tid & 31;
    const int wid  = tid >> 5;
    const int warp_m = wid & 3;
    const int warp_n = wid >> 2;
    const int bz = blockIdx.z;

    const __half* A  = Q16 + (size_t)bz * PS * PD;
    const __half* Bk = K16 + (size_t)bz * PS * PD;
    __half* P = Pf + (size_t)bz * PS * PS;

    const int row0 = blockIdx.y * 128;
    const int col0 = blockIdx.x * 128;

    float acc[2][8][4];
#pragma unroll
    for (int i = 0; i < 2; i++)
#pragma unroll
        for (int n = 0; n < 8; n++)
#pragma unroll
            for (int j = 0; j < 4; j++) acc[i][n][j] = 0.0f;

    const int nk = PD >> 5;   // 32 chunks

    auto load_stage = [&](int stage, int ki) {
        const uint32_t sb = sb0 + stage * SC_STAGE;
        const int k0 = ki << 5;
#pragma unroll
        for (int it = 0; it < 2; it++) {
            int idx = tid + (it << 8);
            int r = idx >> 2, c4 = idx & 3;
            cp16(sb + r * 80 + c4 * 16,
                 A + (size_t)(row0 + r) * PD + k0 + c4 * 8);
        }
#pragma unroll
        for (int it = 0; it < 2; it++) {
            int idx = tid + (it << 8);
            int r = idx >> 2, c4 = idx & 3;
            cp16(sb + 10240 + r * 80 + c4 * 16,
                 Bk + (size_t)(col0 + r) * PD + k0 + c4 * 8);
        }
        cp_commit();
    };

    load_stage(0, 0);
    cp_wait<0>();
    __syncthreads();

    for (int i = 0; i < nk; i++) {
        if (i + 1 < nk) load_stage((i + 1) & 1, i + 1);

        const uint32_t sA0 = sb0 + (i & 1) * SC_STAGE;
        const uint32_t sB0 = sA0 + 10240;

#pragma unroll
        for (int kk = 0; kk < 2; kk++) {
            const int k16 = kk << 4;

            uint32_t a[2][4];
#pragma unroll
            for (int mi = 0; mi < 2; mi++) {
                int m = warp_m * 32 + mi * 16 + (lane & 15);
                int k = k16 + ((lane & 16) ? 8 : 0);
                ldsm_x4(sA0 + m * 80 + k * 2, a[mi]);
            }

#pragma unroll
            for (int nt = 0; nt < 4; nt++) {
                uint32_t b4[4];
                int n = warp_n * 64 + nt * 16 + ((lane & 16) ? 8 : 0) + (lane & 7);
                int k = k16 + (lane & 8);
                ldsm_x4(sB0 + n * 80 + k * 2, b4);
#pragma unroll
                for (int mi = 0; mi < 2; mi++)
#pragma unroll
                    for (int nn = 0; nn < 2; nn++)
                        mma_f16(acc[mi][2 * nt + nn], a[mi], b4 + 2 * nn);
            }
        }

        if (i + 1 < nk) {
            cp_wait<0>();
            __syncthreads();
        }
    }

    // epilogue: exp -> fp16 P, partial rowsums
    float rs[2][2] = {{0.0f, 0.0f}, {0.0f, 0.0f}};
    const float scale = 0.03125f;

#pragma unroll
    for (int mi = 0; mi < 2; mi++) {
        const int rbase = row0 + warp_m * 32 + mi * 16 + (lane >> 2);
#pragma unroll
        for (int n = 0; n < 8; n++) {
            const int cb = col0 + warp_n * 64 + n * 8 + 2 * (lane & 3);
            float e0 = __expf(acc[mi][n][0] * scale);
            float e1 = __expf(acc[mi][n][1] * scale);
            float e2 = __expf(acc[mi][n][2] * scale);
            float e3 = __expf(acc[mi][n][3] * scale);
            __half q0 = __float2half(e0), q1 = __float2half(e1);
            __half q2 = __float2half(e2), q3 = __float2half(e3);
            rs[mi][0] += __half2float(q0) + __half2float(q1);
            rs[mi][1] += __half2float(q2) + __half2float(q3);
            *reinterpret_cast<uint32_t*>(P + (size_t)rbase * PS + cb) = pkh(q0, q1);
            *reinterpret_cast<uint32_t*>(P + (size_t)(rbase + 8) * PS + cb) = pkh(q2, q3);
        }
    }

#pragma unroll
    for (int mi = 0; mi < 2; mi++)
#pragma unroll
        for (int h = 0; h < 2; h++) {
            rs[mi][h] += __shfl_xor_sync(0xffffffffu, rs[mi][h], 1);
            rs[mi][h] += __shfl_xor_sync(0xffffffffu, rs[mi][h], 2);
        }
    if ((lane & 3) == 0) {
        const int q = lane >> 2;
        const int t = blockIdx.x * 2 + warp_n;
#pragma unroll
        for (int mi = 0; mi < 2; mi++) {
            const int rl = row0 + warp_m * 32 + mi * 16 + q;
            const size_t rb = (size_t)bz * PS;
            psum[(rb + rl) * 64 + t]     = rs[mi][0];
            psum[(rb + rl + 8) * 64 + t] = rs[mi][1];
        }
    }
}

// ---------------------------------------------------------------------------
// PV GEMM (fp16 1-term): out[128x64] = (P @ V) * inv[row].
// Stage: A(P) 10240 + B(V) 4608 = 14848; 2 stages = 29696.
// ---------------------------------------------------------------------------
#define PV_STAGE 14848
#define PV_SMEM (2 * PV_STAGE)   // 29696

__global__ void __launch_bounds__(256, 2)
gemm_pv(const __half* __restrict__ Pf, const __half* __restrict__ V16,
        float* __restrict__ out, const float* __restrict__ inv)
{
    extern __shared__ char smem[];
    const uint32_t sb0 = smem_u32(smem);
    const int tid  = threadIdx.x;
    const int lane = tid & 31;
    const int wid  = tid >> 5;
    const int warp_m = wid & 3;
    const int warp_n = wid >> 2;
    const int bz = blockIdx.z;
    const int row0 = blockIdx.y * 128;
    const int col0 = blockIdx.x * 64;

    const __half* A = Pf  + (size_t)bz * PS * PS;
    const __half* B = V16 + (size_t)bz * PS * PD;

    float acc[2][4][4];
#pragma unroll
    for (int i = 0; i < 2; i++)
#pragma unroll
        for (int n = 0; n < 4; n++)
#pragma unroll
            for (int j = 0; j < 4; j++) acc[i][n][j] = 0.0f;

    const int nk = PS >> 5;   // 128 chunks

    auto load_stage = [&](int stage, int ki) {
        const uint32_t sb = sb0 + stage * PV_STAGE;
        const int k0 = ki << 5;
#pragma unroll
        for (int it = 0; it < 2; it++) {
            int idx = tid + (it << 8);
            int r = idx >> 2, c4 = idx & 3;
            cp16(sb + r * 80 + c4 * 16,
                 A + (size_t)(row0 + r) * PS + k0 + c4 * 8);
        }
        {
            int r = tid >> 3, c8 = tid & 7;
            cp16(sb + 10240 + r * 144 + c8 * 16,
                 B + (size_t)(k0 + r) * PD + col0 + c8 * 8);
        }
        cp_commit();
    };

    load_stage(0, 0);
    cp_wait<0>();
    __syncthreads();

    for (int i = 0; i < nk; i++) {
        if (i + 1 < nk) load_stage((i + 1) & 1, i + 1);

        const uint32_t sA0 = sb0 + (i & 1) * PV_STAGE;
        const uint32_t sB0 = sA0 + 10240;

#pragma unroll
        for (int kk = 0; kk < 2; kk++) {
            const int k16 = kk << 4;

            uint32_t a[2][4];
#pragma unroll
            for (int mi = 0; mi < 2; mi++) {
                int m = warp_m * 32 + mi * 16 + (lane & 15);
                int k = k16 + ((lane & 16) ? 8 : 0);
                ldsm_x4(sA0 + m * 80 + k * 2, a[mi]);
            }

#pragma unroll
            for (int nt = 0; nt < 2; nt++) {
                uint32_t b4[4];
                int k = k16 + (lane & 15);
                int n = warp_n * 32 + nt * 16 + ((lane & 16) ? 8 : 0);
                ldsm_x4_t(sB0 + k * 144 + n * 2, b4);
#pragma unroll
                for (int mi = 0; mi < 2; mi++)
#pragma unroll
                    for (int nn = 0; nn < 2; nn++)
                        mma_f16(acc[mi][2 * nt + nn], a[mi], b4 + 2 * nn);
            }
        }

        if (i + 1 < nk) {
            cp_wait<0>();
            __syncthreads();
        }
    }

    // epilogue: scale by 1/rowsum
#pragma unroll
    for (int mi = 0; mi < 2; mi++) {
        const int rbase = row0 + warp_m * 32 + mi * 16 + (lane >> 2);
        const float iv0 = inv[(size_t)bz * PS + rbase];
        const float iv1 = inv[(size_t)bz * PS + rbase + 8];
        float* base = out + (size_t)bz * PS * PD;
#pragma unroll
        for (int n = 0; n < 4; n++) {
            const int cb = col0 + warp_n * 32 + n * 8 + 2 * (lane & 3);
            float2 v0 = make_float2(acc[mi][n][0] * iv0, acc[mi][n][1] * iv0);
            float2 v1 = make_float2(acc[mi][n][2] * iv1, acc[mi][n][3] * iv1);
            *reinterpret_cast<float2*>(base + (size_t)rbase * PD + cb) = v0;
            *reinterpret_cast<float2*>(base + (size_t)(rbase + 8) * PD + cb) = v1;
        }
    }
}

// ---------------------------------------------------------------------------
// Merged splits: x -> fp16 hi/lo; Wq/Wk/Wv -> plain fp16 (one launch)
// ---------------------------------------------------------------------------
struct SplitArgs {
    const float* x;
    __half* xh;
    __half* xl;
    const float* W[3];
    __half* W16[3];
};

__global__ void __launch_bounds__(256)
split_all(SplitArgs sa)
{
    int bid = blockIdx.x;
    if (bid < 16384) {
        size_t i = (size_t)bid * 256 + threadIdx.x;
        float4 v = reinterpret_cast<const float4*>(sa.x)[i];
        float vv[4] = { v.x, v.y, v.z, v.w };
        __half h[4], l[4];
#pragma unroll
        for (int j = 0; j < 4; j++) {
            h[j] = __float2half(vv[j]);
            l[j] = __float2half(vv[j] - __half2float(h[j]));
        }
        reinterpret_cast<uint2*>(sa.xh)[i] = make_uint2(pkh(h[0], h[1]), pkh(h[2], h[3]));
        reinterpret_cast<uint2*>(sa.xl)[i] = make_uint2(pkh(l[0], l[1]), pkh(l[2], l[3]));
    } else {
        int which = (bid - 16384) >> 10;
        int boff  = (bid - 16384) & 1023;
        size_t i = (size_t)boff * 256 + threadIdx.x;
        float4 v = reinterpret_cast<const float4*>(sa.W[which])[i];
        __half h0 = __float2half(v.x), h1 = __float2half(v.y);
        __half h2 = __float2half(v.z), h3 = __float2half(v.w);
        reinterpret_cast<uint2*>(sa.W16[which])[i] =
            make_uint2(pkh(h0, h1), pkh(h2, h3));
    }
}

// ---------------------------------------------------------------------------
// Rowsum reduce: one warp per row sums 64 partials -> 1/sum
// ---------------------------------------------------------------------------
__global__ void __launch_bounds__(256)
rowsum_inv(const float* __restrict__ psum, float* __restrict__ inv)
{
    const int row  = (blockIdx.x * blockDim.x + threadIdx.x) >> 5;
    const int lane = threadIdx.x & 31;
    float2 v = reinterpret_cast<const float2*>(psum + (size_t)row * 64)[lane];
    float s = v.x + v.y;
#pragma unroll
    for (int o = 16; o > 0; o >>= 1)
        s += __shfl_xor_sync(0xffffffffu, s, o);
    if (lane == 0) inv[row] = 1.0f / s;
}

// ---------------------------------------------------------------------------
// Launcher
// ---------------------------------------------------------------------------
extern "C" void kernel_launch(void* const* d_in, const int* in_sizes, int n_in,
                              void* d_out, int out_size)
{
    (void)in_sizes; (void)n_in; (void)out_size;
    const float* x  = (const float*)d_in[0];
    const float* Wq = (const float*)d_in[1];
    const float* bq = (const float*)d_in[2];
    const float* Wk = (const float*)d_in[3];
    const float* bk = (const float*)d_in[4];
    const float* Wv = (const float*)d_in[5];
    const float* bv = (const float*)d_in[6];
    float* out = (float*)d_out;

    __half *xh, *xl, *Wq16, *Wk16, *Wv16, *Q16, *K16, *V16, *Pf;
    float *psum, *inv;
    cudaGetSymbolAddress((void**)&xh,   g_xh);
    cudaGetSymbolAddress((void**)&xl,   g_xl);
    cudaGetSymbolAddress((void**)&Wq16, g_Wq16);
    cudaGetSymbolAddress((void**)&Wk16, g_Wk16);
    cudaGetSymbolAddress((void**)&Wv16, g_Wv16);
    cudaGetSymbolAddress((void**)&Q16,  g_Q16);
    cudaGetSymbolAddress((void**)&K16,  g_K16);
    cudaGetSymbolAddress((void**)&V16,  g_V16);
    cudaGetSymbolAddress((void**)&Pf,   g_Pf);
    cudaGetSymbolAddress((void**)&psum, g_psum);
    cudaGetSymbolAddress((void**)&inv,  g_inv);

    cudaFuncSetAttribute((const void*)gemm_proj,
                         cudaFuncAttributeMaxDynamicSharedMemorySize, PJ_SMEM);
    cudaFuncSetAttribute((const void*)gemm_scores,
                         cudaFuncAttributeMaxDynamicSharedMemorySize, SC_SMEM);
    cudaFuncSetAttribute((const void*)gemm_pv,
                         cudaFuncAttributeMaxDynamicSharedMemorySize, PV_SMEM);

    // 1) merged splits
    SplitArgs sa;
    sa.x = x; sa.xh = xh; sa.xl = xl;
    sa.W[0] = Wq; sa.W16[0] = Wq16;
    sa.W[1] = Wk; sa.W16[1] = Wk16;
    sa.W[2] = Wv; sa.W16[2] = Wv16;
    split_all<<<16384 + 3 * 1024, 256>>>(sa);

    // 2) merged projections (fp16 2-term): z=0/1/2 -> Q/K/V plain fp16
    ProjArgs pa;
    pa.s[0] = { Wq16, bq, Q16 };
    pa.s[1] = { Wk16, bk, K16 };
    pa.s[2] = { Wv16, bv, V16 };
    dim3 gp(PD / 128, MROWS / 128, 3);
    gemm_proj<<<gp, 256, PJ_SMEM>>>(xh, xl, pa);

    // 3) scores + fused exp (fp16 1-term) -> fp16 P, psum partials
    dim3 gs(PS / 128, PS / 128, PB);
    gemm_scores<<<gs, 256, SC_SMEM>>>(Q16, K16, Pf, psum);

    // 4) rowsum -> 1/sum
    rowsum_inv<<<(PB * PS * 32) / 256, 256>>>(psum, inv);

    // 5) out = (P @ V) * inv   (fp16 1-term, BN=64)
    dim3 go(PD / 64, PS / 128, PB);
    gemm_pv<<<go, 256, PV_SMEM>>>(Pf, V16, out, inv);
}

// round 10
// speedup vs baseline: 2.3115x; 1.0756x over previous
#include <cuda_runtime.h>
#include <cuda_fp16.h>
#include <math_constants.h>
#include <cstdint>

// Problem shape (fixed): B=4, S=4096, D=1024
#define PB 4
#define PS 4096
#define PD 1024
#define MROWS (PB * PS)   // 16384

// ---------------------------------------------------------------------------
// Global scratch (allocation-guard-safe __device__ arrays)
// ---------------------------------------------------------------------------
__device__ __half g_xh[(size_t)MROWS * PD], g_xl[(size_t)MROWS * PD];
__device__ __half g_Wq16[PD * PD], g_Wk16[PD * PD], g_Wv16[PD * PD];
__device__ __half g_Q16[(size_t)MROWS * PD];
__device__ __half g_K16[(size_t)MROWS * PD];
__device__ __half g_V16[(size_t)MROWS * PD];
__device__ __half g_Pf[(size_t)PB * PS * PS];    // exp scores, fp16
__device__ float g_psum[(size_t)PB * PS * 64];   // per-row partial expsums
__device__ float g_inv [(size_t)PB * PS];        // 1 / rowsum

// ---------------------------------------------------------------------------
// PTX helpers (baseline sm_80+ features only: compile-safe under compute_103)
// ---------------------------------------------------------------------------
__device__ __forceinline__ uint32_t smem_u32(const void* p) {
    uint32_t a;
    asm("{ .reg .u64 t; cvta.to.shared.u64 t, %1; cvt.u32.u64 %0, t; }"
        : "=r"(a) : "l"(p));
    return a;
}

__device__ __forceinline__ void cp16(uint32_t s, const void* g) {
    asm volatile("cp.async.cg.shared.global [%0], [%1], 16;" :: "r"(s), "l"(g));
}
__device__ __forceinline__ void cp_commit() {
    asm volatile("cp.async.commit_group;" ::: "memory");
}
template<int N>
__device__ __forceinline__ void cp_wait() {
    asm volatile("cp.async.wait_group %0;" :: "n"(N) : "memory");
}

__device__ __forceinline__ void ldsm_x4(uint32_t a, uint32_t* r) {
    asm volatile("ldmatrix.sync.aligned.m8n8.x4.shared.b16 {%0,%1,%2,%3}, [%4];"
                 : "=r"(r[0]), "=r"(r[1]), "=r"(r[2]), "=r"(r[3]) : "r"(a));
}
__device__ __forceinline__ void ldsm_x4_t(uint32_t a, uint32_t* r) {
    asm volatile("ldmatrix.sync.aligned.m8n8.x4.trans.shared.b16 {%0,%1,%2,%3}, [%4];"
                 : "=r"(r[0]), "=r"(r[1]), "=r"(r[2]), "=r"(r[3]) : "r"(a));
}

__device__ __forceinline__ void mma_f16(float* c, const uint32_t* a,
                                        const uint32_t* b) {
    asm volatile(
        "mma.sync.aligned.m16n8k16.row.col.f32.f16.f16.f32 "
        "{%0,%1,%2,%3},{%4,%5,%6,%7},{%8,%9},{%0,%1,%2,%3};"
        : "+f"(c[0]), "+f"(c[1]), "+f"(c[2]), "+f"(c[3])
        : "r"(a[0]), "r"(a[1]), "r"(a[2]), "r"(a[3]), "r"(b[0]), "r"(b[1]));
}

__device__ __forceinline__ uint32_t pkh(__half a, __half b) {
    return (uint32_t)__half_as_ushort(a) | ((uint32_t)__half_as_ushort(b) << 16);
}

// ---------------------------------------------------------------------------
// Projection GEMM (fp16 2-term): C = (xh + xl) @ W^T + b, plain fp16 out.
// CTA 128x128, BK=32, 4 warps (2m x 2n), warp tile 64x64, 128 threads.
// Stage: A hi/lo 2x10240 + B 10240 = 30720; 2 stages = 61440 -> 2 CTAs/SM.
// ---------------------------------------------------------------------------
#define PJ_STAGE 30720
#define PJ_SMEM (2 * PJ_STAGE)   // 61440

struct ProjSet {
    const __half* W16;
    const float* bias;
    __half* C16;
};
struct ProjArgs { ProjSet s[3]; };

__global__ void __launch_bounds__(128, 2)
gemm_proj(const __half* __restrict__ Ah, const __half* __restrict__ Al,
          ProjArgs pa)
{
    extern __shared__ char smem[];
    const uint32_t sb0 = smem_u32(smem);
    const int tid  = threadIdx.x;
    const int lane = tid & 31;
    const int wid  = tid >> 5;
    const int warp_m = wid & 1;     // 2 warps along M (64 rows)
    const int warp_n = wid >> 1;    // 2 warps along N (64 cols)

    const ProjSet& s = pa.s[blockIdx.z];
    const __half* Bw = s.W16;
    const float* bias = s.bias;
    __half* C = s.C16;

    const int row0 = blockIdx.y * 128;
    const int col0 = blockIdx.x * 128;

    float acc[4][8][4];
#pragma unroll
    for (int i = 0; i < 4; i++)
#pragma unroll
        for (int n = 0; n < 8; n++)
#pragma unroll
            for (int j = 0; j < 4; j++) acc[i][n][j] = 0.0f;

    const int nk = PD >> 5;   // 32 chunks

    auto load_stage = [&](int stage, int ki) {
        const uint32_t sb = sb0 + stage * PJ_STAGE;
        const int k0 = ki << 5;
        // A: x hi/lo, 1024 x 16B chunks, 8/thread (128 threads)
#pragma unroll
        for (int it = 0; it < 8; it++) {
            int idx = tid + (it << 7);
            int hl  = idx >> 9;
            int e   = idx & 511;
            int r   = e >> 2;
            int c4  = e & 3;
            const __half* src = hl ? Al : Ah;
            cp16(sb + hl * 10240 + r * 80 + c4 * 16,
                 src + (size_t)(row0 + r) * PD + k0 + c4 * 8);
        }
        // B: W single, 512 x 16B chunks, 4/thread
#pragma unroll
        for (int it = 0; it < 4; it++) {
            int idx = tid + (it << 7);
            int r   = idx >> 2;
            int c4  = idx & 3;
            cp16(sb + 20480 + r * 80 + c4 * 16,
                 Bw + (size_t)(col0 + r) * PD + k0 + c4 * 8);
        }
        cp_commit();
    };

    load_stage(0, 0);
    cp_wait<0>();
    __syncthreads();

    for (int i = 0; i < nk; i++) {
        if (i + 1 < nk) load_stage((i + 1) & 1, i + 1);

        const uint32_t sA0 = sb0 + (i & 1) * PJ_STAGE;
        const uint32_t sB0 = sA0 + 20480;

#pragma unroll
        for (int kk = 0; kk < 2; kk++) {
            const int k16 = kk << 4;

            uint32_t ah[4][4], al[4][4];
#pragma unroll
            for (int mi = 0; mi < 4; mi++) {
                int m = warp_m * 64 + mi * 16 + (lane & 15);
                int k = k16 + ((lane & 16) ? 8 : 0);
                ldsm_x4(sA0 +         m * 80 + k * 2, ah[mi]);
                ldsm_x4(sA0 + 10240 + m * 80 + k * 2, al[mi]);
            }

#pragma unroll
            for (int nt = 0; nt < 4; nt++) {
                uint32_t b4[4];
                int n = warp_n * 64 + nt * 16 + ((lane & 16) ? 8 : 0) + (lane & 7);
                int k = k16 + (lane & 8);
                ldsm_x4(sB0 + n * 80 + k * 2, b4);
#pragma unroll
                for (int mi = 0; mi < 4; mi++)
#pragma unroll
                    for (int nn = 0; nn < 2; nn++) {
                        float* a = acc[mi][2 * nt + nn];
                        mma_f16(a, ah[mi], b4 + 2 * nn);
                        mma_f16(a, al[mi], b4 + 2 * nn);
                    }
            }
        }

        if (i + 1 < nk) {
            cp_wait<0>();
            __syncthreads();
        }
    }

    // epilogue: +bias, plain fp16
#pragma unroll
    for (int mi = 0; mi < 4; mi++) {
        const int rbase = row0 + warp_m * 64 + mi * 16 + (lane >> 2);
#pragma unroll
        for (int n = 0; n < 8; n++) {
            const int cb = col0 + warp_n * 64 + n * 8 + 2 * (lane & 3);
            float b0 = bias[cb], b1 = bias[cb + 1];
            __half h0 = __float2half(acc[mi][n][0] + b0);
            __half h1 = __float2half(acc[mi][n][1] + b1);
            __half h2 = __float2half(acc[mi][n][2] + b0);
            __half h3 = __float2half(acc[mi][n][3] + b1);
            *reinterpret_cast<uint32_t*>(C + (size_t)rbase * PD + cb) = pkh(h0, h1);
            *reinterpret_cast<uint32_t*>(C + (size_t)(rbase + 8) * PD + cb) = pkh(h2, h3);
        }
    }
}

// ---------------------------------------------------------------------------
// Scores GEMM (fp16 1-term): P = exp(Q @ K^T * scale), fp16 out + psum.
// CTA 128x128, 4 warps (2m x 2n), warp 64x64, 128 threads.
// Stage: A 10240 + B 10240 = 20480; 2 stages = 40960 -> 2 CTAs/SM.
// ---------------------------------------------------------------------------
#define SC_STAGE 20480
#define SC_SMEM (2 * SC_STAGE)   // 40960

__global__ void __launch_bounds__(128, 2)
gemm_scores(const __half* __restrict__ Q16, const __half* __restrict__ K16,
            __half* __restrict__ Pf, float* __restrict__ psum)
{
    extern __shared__ char smem[];
    const uint32_t sb0 = smem_u32(smem);
    const int tid  = threadIdx.x;
    const int lane = tid & 31;
    const int wid  = tid >> 5;
    const int warp_m = wid & 1;
    const int warp_n = wid >> 1;
    const int bz = blockIdx.z;

    const __half* A  = Q16 + (size_t)bz * PS * PD;
    const __half* Bk = K16 + (size_t)bz * PS * PD;
    __half* P = Pf + (size_t)bz * PS * PS;

    const int row0 = blockIdx.y * 128;
    const int col0 = blockIdx.x * 128;

    float acc[4][8][4];
#pragma unroll
    for (int i = 0; i < 4; i++)
#pragma unroll
        for (int n = 0; n < 8; n++)
#pragma unroll
            for (int j = 0; j < 4; j++) acc[i][n][j] = 0.0f;

    const int nk = PD >> 5;   // 32 chunks

    auto load_stage = [&](int stage, int ki) {
        const uint32_t sb = sb0 + stage * SC_STAGE;
        const int k0 = ki << 5;
#pragma unroll
        for (int it = 0; it < 4; it++) {
            int idx = tid + (it << 7);
            int r = idx >> 2, c4 = idx & 3;
            cp16(sb + r * 80 + c4 * 16,
                 A + (size_t)(row0 + r) * PD + k0 + c4 * 8);
        }
#pragma unroll
        for (int it = 0; it < 4; it++) {
            int idx = tid + (it << 7);
            int r = idx >> 2, c4 = idx & 3;
            cp16(sb + 10240 + r * 80 + c4 * 16,
                 Bk + (size_t)(col0 + r) * PD + k0 + c4 * 8);
        }
        cp_commit();
    };

    load_stage(0, 0);
    cp_wait<0>();
    __syncthreads();

    for (int i = 0; i < nk; i++) {
        if (i + 1 < nk) load_stage((i + 1) & 1, i + 1);

        const uint32_t sA0 = sb0 + (i & 1) * SC_STAGE;
        const uint32_t sB0 = sA0 + 10240;

#pragma unroll
        for (int kk = 0; kk < 2; kk++) {
            const int k16 = kk << 4;

            uint32_t a[4][4];
#pragma unroll
            for (int mi = 0; mi < 4; mi++) {
                int m = warp_m * 64 + mi * 16 + (lane & 15);
                int k = k16 + ((lane & 16) ? 8 : 0);
                ldsm_x4(sA0 + m * 80 + k * 2, a[mi]);
            }

#pragma unroll
            for (int nt = 0; nt < 4; nt++) {
                uint32_t b4[4];
                int n = warp_n * 64 + nt * 16 + ((lane & 16) ? 8 : 0) + (lane & 7);
                int k = k16 + (lane & 8);
                ldsm_x4(sB0 + n * 80 + k * 2, b4);
#pragma unroll
                for (int mi = 0; mi < 4; mi++)
#pragma unroll
                    for (int nn = 0; nn < 2; nn++)
                        mma_f16(acc[mi][2 * nt + nn], a[mi], b4 + 2 * nn);
            }
        }

        if (i + 1 < nk) {
            cp_wait<0>();
            __syncthreads();
        }
    }

    // epilogue: exp -> fp16 P, partial rowsums
    float rs[4][2] = {{0,0},{0,0},{0,0},{0,0}};
    const float scale = 0.03125f;

#pragma unroll
    for (int mi = 0; mi < 4; mi++) {
        const int rbase = row0 + warp_m * 64 + mi * 16 + (lane >> 2);
#pragma unroll
        for (int n = 0; n < 8; n++) {
            const int cb = col0 + warp_n * 64 + n * 8 + 2 * (lane & 3);
            float e0 = __expf(acc[mi][n][0] * scale);
            float e1 = __expf(acc[mi][n][1] * scale);
            float e2 = __expf(acc[mi][n][2] * scale);
            float e3 = __expf(acc[mi][n][3] * scale);
            __half q0 = __float2half(e0), q1 = __float2half(e1);
            __half q2 = __float2half(e2), q3 = __float2half(e3);
            rs[mi][0] += __half2float(q0) + __half2float(q1);
            rs[mi][1] += __half2float(q2) + __half2float(q3);
            *reinterpret_cast<uint32_t*>(P + (size_t)rbase * PS + cb) = pkh(q0, q1);
            *reinterpret_cast<uint32_t*>(P + (size_t)(rbase + 8) * PS + cb) = pkh(q2, q3);
        }
    }

#pragma unroll
    for (int mi = 0; mi < 4; mi++)
#pragma unroll
        for (int h = 0; h < 2; h++) {
            rs[mi][h] += __shfl_xor_sync(0xffffffffu, rs[mi][h], 1);
            rs[mi][h] += __shfl_xor_sync(0xffffffffu, rs[mi][h], 2);
        }
    if ((lane & 3) == 0) {
        const int q = lane >> 2;
        const int t = blockIdx.x * 2 + warp_n;   // 64 col-spans of 64
#pragma unroll
        for (int mi = 0; mi < 4; mi++) {
            const int rl = row0 + warp_m * 64 + mi * 16 + q;
            const size_t rb = (size_t)bz * PS;
            psum[(rb + rl) * 64 + t]     = rs[mi][0];
            psum[(rb + rl + 8) * 64 + t] = rs[mi][1];
        }
    }
}

// ---------------------------------------------------------------------------
// PV GEMM (fp16 1-term): out[128x64] = (P @ V) * inv[row].
// CTA 128x64, 4 warps (4m x 1n), warp 32x64, 128 threads.
// Stage: A(P) 10240 + B(V) 4608 = 14848; 2 stages = 29696 -> 2 CTAs/SM.
// ---------------------------------------------------------------------------
#define PV_STAGE 14848
#define PV_SMEM (2 * PV_STAGE)   // 29696

__global__ void __launch_bounds__(128, 2)
gemm_pv(const __half* __restrict__ Pf, const __half* __restrict__ V16,
        float* __restrict__ out, const float* __restrict__ inv)
{
    extern __shared__ char smem[];
    const uint32_t sb0 = smem_u32(smem);
    const int tid  = threadIdx.x;
    const int lane = tid & 31;
    const int wid  = tid >> 5;      // warp_m = wid (4 warps x 32 rows)
    const int bz = blockIdx.z;
    const int row0 = blockIdx.y * 128;
    const int col0 = blockIdx.x * 64;

    const __half* A = Pf  + (size_t)bz * PS * PS;
    const __half* B = V16 + (size_t)bz * PS * PD;

    float acc[2][8][4];
#pragma unroll
    for (int i = 0; i < 2; i++)
#pragma unroll
        for (int n = 0; n < 8; n++)
#pragma unroll
            for (int j = 0; j < 4; j++) acc[i][n][j] = 0.0f;

    const int nk = PS >> 5;   // 128 chunks

    auto load_stage = [&](int stage, int ki) {
        const uint32_t sb = sb0 + stage * PV_STAGE;
        const int k0 = ki << 5;
        // A: 512 x 16B chunks, 4/thread
#pragma unroll
        for (int it = 0; it < 4; it++) {
            int idx = tid + (it << 7);
            int r = idx >> 2, c4 = idx & 3;
            cp16(sb + r * 80 + c4 * 16,
                 A + (size_t)(row0 + r) * PS + k0 + c4 * 8);
        }
        // B: 256 x 16B chunks, 2/thread, rows padded 144B
#pragma unroll
        for (int it = 0; it < 2; it++) {
            int idx = tid + (it << 7);
            int r = idx >> 3, c8 = idx & 7;
            cp16(sb + 10240 + r * 144 + c8 * 16,
                 B + (size_t)(k0 + r) * PD + col0 + c8 * 8);
        }
        cp_commit();
    };

    load_stage(0, 0);
    cp_wait<0>();
    __syncthreads();

    for (int i = 0; i < nk; i++) {
        if (i + 1 < nk) load_stage((i + 1) & 1, i + 1);

        const uint32_t sA0 = sb0 + (i & 1) * PV_STAGE;
        const uint32_t sB0 = sA0 + 10240;

#pragma unroll
        for (int kk = 0; kk < 2; kk++) {
            const int k16 = kk << 4;

            uint32_t a[2][4];
#pragma unroll
            for (int mi = 0; mi < 2; mi++) {
                int m = wid * 32 + mi * 16 + (lane & 15);
                int k = k16 + ((lane & 16) ? 8 : 0);
                ldsm_x4(sA0 + m * 80 + k * 2, a[mi]);
            }

#pragma unroll
            for (int nt = 0; nt < 4; nt++) {
                uint32_t b4[4];
                int k = k16 + (lane & 15);
                int n = nt * 16 + ((lane & 16) ? 8 : 0);
                ldsm_x4_t(sB0 + k * 144 + n * 2, b4);
#pragma unroll
                for (int mi = 0; mi < 2; mi++)
#pragma unroll
                    for (int nn = 0; nn < 2; nn++)
                        mma_f16(acc[mi][2 * nt + nn], a[mi], b4 + 2 * nn);
            }
        }

        if (i + 1 < nk) {
            cp_wait<0>();
            __syncthreads();
        }
    }

    // epilogue: scale by 1/rowsum
#pragma unroll
    for (int mi = 0; mi < 2; mi++) {
        const int rbase = row0 + wid * 32 + mi * 16 + (lane >> 2);
        const float iv0 = inv[(size_t)bz * PS + rbase];
        const float iv1 = inv[(size_t)bz * PS + rbase + 8];
        float* base = out + (size_t)bz * PS * PD;
#pragma unroll
        for (int n = 0; n < 8; n++) {
            const int cb = col0 + n * 8 + 2 * (lane & 3);
            float2 v0 = make_float2(acc[mi][n][0] * iv0, acc[mi][n][1] * iv0);
            float2 v1 = make_float2(acc[mi][n][2] * iv1, acc[mi][n][3] * iv1);
            *reinterpret_cast<float2*>(base + (size_t)rbase * PD + cb) = v0;
            *reinterpret_cast<float2*>(base + (size_t)(rbase + 8) * PD + cb) = v1;
        }
    }
}

// ---------------------------------------------------------------------------
// Merged splits: x -> fp16 hi/lo; Wq/Wk/Wv -> plain fp16 (one launch)
// ---------------------------------------------------------------------------
struct SplitArgs {
    const float* x;
    __half* xh;
    __half* xl;
    const float* W[3];
    __half* W16[3];
};

__global__ void __launch_bounds__(256)
split_all(SplitArgs sa)
{
    int bid = blockIdx.x;
    if (bid < 16384) {
        size_t i = (size_t)bid * 256 + threadIdx.x;
        float4 v = reinterpret_cast<const float4*>(sa.x)[i];
        float vv[4] = { v.x, v.y, v.z, v.w };
        __half h[4], l[4];
#pragma unroll
        for (int j = 0; j < 4; j++) {
            h[j] = __float2half(vv[j]);
            l[j] = __float2half(vv[j] - __half2float(h[j]));
        }
        reinterpret_cast<uint2*>(sa.xh)[i] = make_uint2(pkh(h[0], h[1]), pkh(h[2], h[3]));
        reinterpret_cast<uint2*>(sa.xl)[i] = make_uint2(pkh(l[0], l[1]), pkh(l[2], l[3]));
    } else {
        int which = (bid - 16384) >> 10;
        int boff  = (bid - 16384) & 1023;
        size_t i = (size_t)boff * 256 + threadIdx.x;
        float4 v = reinterpret_cast<const float4*>(sa.W[which])[i];
        __half h0 = __float2half(v.x), h1 = __float2half(v.y);
        __half h2 = __float2half(v.z), h3 = __float2half(v.w);
        reinterpret_cast<uint2*>(sa.W16[which])[i] =
            make_uint2(pkh(h0, h1), pkh(h2, h3));
    }
}

// ---------------------------------------------------------------------------
// Rowsum reduce: one warp per row sums 64 partials -> 1/sum
// ---------------------------------------------------------------------------
__global__ void __launch_bounds__(256)
rowsum_inv(const float* __restrict__ psum, float* __restrict__ inv)
{
    const int row  = (blockIdx.x * blockDim.x + threadIdx.x) >> 5;
    const int lane = threadIdx.x & 31;
    float2 v = reinterpret_cast<const float2*>(psum + (size_t)row * 64)[lane];
    float s = v.x + v.y;
#pragma unroll
    for (int o = 16; o > 0; o >>= 1)
        s += __shfl_xor_sync(0xffffffffu, s, o);
    if (lane == 0) inv[row] = 1.0f / s;
}

// ---------------------------------------------------------------------------
// Launcher
// ---------------------------------------------------------------------------
extern "C" void kernel_launch(void* const* d_in, const int* in_sizes, int n_in,
                              void* d_out, int out_size)
{
    (void)in_sizes; (void)n_in; (void)out_size;
    const float* x  = (const float*)d_in[0];
    const float* Wq = (const float*)d_in[1];
    const float* bq = (const float*)d_in[2];
    const float* Wk = (const float*)d_in[3];
    const float* bk = (const float*)d_in[4];
    const float* Wv = (const float*)d_in[5];
    const float* bv = (const float*)d_in[6];
    float* out = (float*)d_out;

    __half *xh, *xl, *Wq16, *Wk16, *Wv16, *Q16, *K16, *V16, *Pf;
    float *psum, *inv;
    cudaGetSymbolAddress((void**)&xh,   g_xh);
    cudaGetSymbolAddress((void**)&xl,   g_xl);
    cudaGetSymbolAddress((void**)&Wq16, g_Wq16);
    cudaGetSymbolAddress((void**)&Wk16, g_Wk16);
    cudaGetSymbolAddress((void**)&Wv16, g_Wv16);
    cudaGetSymbolAddress((void**)&Q16,  g_Q16);
    cudaGetSymbolAddress((void**)&K16,  g_K16);
    cudaGetSymbolAddress((void**)&V16,  g_V16);
    cudaGetSymbolAddress((void**)&Pf,   g_Pf);
    cudaGetSymbolAddress((void**)&psum, g_psum);
    cudaGetSymbolAddress((void**)&inv,  g_inv);

    cudaFuncSetAttribute((const void*)gemm_proj,
                         cudaFuncAttributeMaxDynamicSharedMemorySize, PJ_SMEM);
    cudaFuncSetAttribute((const void*)gemm_scores,
                         cudaFuncAttributeMaxDynamicSharedMemorySize, SC_SMEM);
    cudaFuncSetAttribute((const void*)gemm_pv,
                         cudaFuncAttributeMaxDynamicSharedMemorySize, PV_SMEM);

    // 1) merged splits
    SplitArgs sa;
    sa.x = x; sa.xh = xh; sa.xl = xl;
    sa.W[0] = Wq; sa.W16[0] = Wq16;
    sa.W[1] = Wk; sa.W16[1] = Wk16;
    sa.W[2] = Wv; sa.W16[2] = Wv16;
    split_all<<<16384 + 3 * 1024, 256>>>(sa);

    // 2) merged projections (fp16 2-term): z=0/1/2 -> Q/K/V plain fp16
    ProjArgs pa;
    pa.s[0] = { Wq16, bq, Q16 };
    pa.s[1] = { Wk16, bk, K16 };
    pa.s[2] = { Wv16, bv, V16 };
    dim3 gp(PD / 128, MROWS / 128, 3);
    gemm_proj<<<gp, 128, PJ_SMEM>>>(xh, xl, pa);

    // 3) scores + fused exp (fp16 1-term) -> fp16 P, psum partials
    dim3 gs(PS / 128, PS / 128, PB);
    gemm_scores<<<gs, 128, SC_SMEM>>>(Q16, K16, Pf, psum);

    // 4) rowsum -> 1/sum
    rowsum_inv<<<(PB * PS * 32) / 256, 256>>>(psum, inv);

    // 5) out = (P @ V) * inv   (fp16 1-term, BN=64)
    dim3 go(PD / 64, PS / 128, PB);
    gemm_pv<<<go, 128, PV_SMEM>>>(Pf, V16, out, inv);
}

// round 11
// speedup vs baseline: 3.1438x; 1.3601x over previous
#include <cuda_runtime.h>
#include <cuda_fp16.h>
#include <math_constants.h>
#include <cstdint>

// Problem shape (fixed): B=4, S=4096, D=1024
#define PB 4
#define PS 4096
#define PD 1024
#define MROWS (PB * PS)   // 16384

// ---------------------------------------------------------------------------
// Global scratch (allocation-guard-safe __device__ arrays)
// ---------------------------------------------------------------------------
__device__ __half g_x16[(size_t)MROWS * PD];
__device__ __half g_Wq16[PD * PD], g_Wk16[PD * PD], g_Wv16[PD * PD];
__device__ __half g_Q16[(size_t)MROWS * PD];
__device__ __half g_K16[(size_t)MROWS * PD];
__device__ __half g_V16[(size_t)MROWS * PD];
__device__ __half g_Pf[(size_t)PB * PS * PS];    // exp scores, fp16
__device__ float g_psum[(size_t)PB * PS * 64];   // per-row partial expsums
__device__ float g_inv [(size_t)PB * PS];        // 1 / rowsum

// ---------------------------------------------------------------------------
// PTX helpers (baseline sm_80+ features only: compile-safe under compute_103)
// ---------------------------------------------------------------------------
__device__ __forceinline__ uint32_t smem_u32(const void* p) {
    uint32_t a;
    asm("{ .reg .u64 t; cvta.to.shared.u64 t, %1; cvt.u32.u64 %0, t; }"
        : "=r"(a) : "l"(p));
    return a;
}

__device__ __forceinline__ void cp16(uint32_t s, const void* g) {
    asm volatile("cp.async.cg.shared.global [%0], [%1], 16;" :: "r"(s), "l"(g));
}
__device__ __forceinline__ void cp_commit() {
    asm volatile("cp.async.commit_group;" ::: "memory");
}
template<int N>
__device__ __forceinline__ void cp_wait() {
    asm volatile("cp.async.wait_group %0;" :: "n"(N) : "memory");
}

__device__ __forceinline__ void ldsm_x4(uint32_t a, uint32_t* r) {
    asm volatile("ldmatrix.sync.aligned.m8n8.x4.shared.b16 {%0,%1,%2,%3}, [%4];"
                 : "=r"(r[0]), "=r"(r[1]), "=r"(r[2]), "=r"(r[3]) : "r"(a));
}
__device__ __forceinline__ void ldsm_x4_t(uint32_t a, uint32_t* r) {
    asm volatile("ldmatrix.sync.aligned.m8n8.x4.trans.shared.b16 {%0,%1,%2,%3}, [%4];"
                 : "=r"(r[0]), "=r"(r[1]), "=r"(r[2]), "=r"(r[3]) : "r"(a));
}

__device__ __forceinline__ void mma_f16(float* c, const uint32_t* a,
                                        const uint32_t* b) {
    asm volatile(
        "mma.sync.aligned.m16n8k16.row.col.f32.f16.f16.f32 "
        "{%0,%1,%2,%3},{%4,%5,%6,%7},{%8,%9},{%0,%1,%2,%3};"
        : "+f"(c[0]), "+f"(c[1]), "+f"(c[2]), "+f"(c[3])
        : "r"(a[0]), "r"(a[1]), "r"(a[2]), "r"(a[3]), "r"(b[0]), "r"(b[1]));
}

__device__ __forceinline__ uint32_t pkh(__half a, __half b) {
    return (uint32_t)__half_as_ushort(a) | ((uint32_t)__half_as_ushort(b) << 16);
}

// ---------------------------------------------------------------------------
// NT GEMM core (fp16 1-term): CTA 128x128, BK=64, 4 warps (2m x 2n) 64x64.
// SMEM rows padded to 144B (64 fp16 + 16B pad); conflict-free for ldmatrix
// 8-lane phases (144/4 mod 32 = 4 bank step).
// Stage: A 128x144 + B 128x144 = 36864; 2 stages = 73728 -> 2 CTAs/SM.
// Used for projections (EPI=0: +bias, fp16 store) and scores (EPI=1: exp,
// fp16 P + psum).
// ---------------------------------------------------------------------------
#define NT_STAGE 36864
#define NT_SMEM (2 * NT_STAGE)   // 73728

struct ProjSet {
    const __half* W16;
    const float* bias;
    __half* C16;
};
struct ProjArgs { ProjSet s[3]; };

template<int EPI>
__global__ void __launch_bounds__(128, 2)
gemm_nt(const __half* __restrict__ A_, const __half* __restrict__ B_,
        ProjArgs pa, __half* __restrict__ Pf, float* __restrict__ psum)
{
    extern __shared__ char smem[];
    const uint32_t sb0 = smem_u32(smem);
    const int tid  = threadIdx.x;
    const int lane = tid & 31;
    const int wid  = tid >> 5;
    const int warp_m = wid & 1;
    const int warp_n = wid >> 1;
    const int bz = blockIdx.z;

    const __half* A;
    const __half* B;
    const float* bias = nullptr;
    __half* C = nullptr;
    if (EPI == 0) {
        A = A_;                       // x, shared across z
        const ProjSet& s = pa.s[bz];
        B = s.W16; bias = s.bias; C = s.C16;
    } else {
        A = A_ + (size_t)bz * PS * PD;   // Q batch
        B = B_ + (size_t)bz * PS * PD;   // K batch
        C = Pf + (size_t)bz * PS * PS;
    }

    const int row0 = blockIdx.y * 128;
    const int col0 = blockIdx.x * 128;
    const int ldc  = (EPI == 0) ? PD : PS;

    float acc[4][8][4];
#pragma unroll
    for (int i = 0; i < 4; i++)
#pragma unroll
        for (int n = 0; n < 8; n++)
#pragma unroll
            for (int j = 0; j < 4; j++) acc[i][n][j] = 0.0f;

    const int nk = PD >> 6;   // 16 chunks of BK=64

    auto load_stage = [&](int stage, int ki) {
        const uint32_t sb = sb0 + stage * NT_STAGE;
        const int k0 = ki << 6;
        // A: 128 rows x 128B = 1024 x 16B chunks, 8/thread
#pragma unroll
        for (int it = 0; it < 8; it++) {
            int idx = tid + (it << 7);
            int r = idx >> 3, c8 = idx & 7;
            cp16(sb + r * 144 + c8 * 16,
                 A + (size_t)(row0 + r) * PD + k0 + c8 * 8);
        }
        // B: same shape
#pragma unroll
        for (int it = 0; it < 8; it++) {
            int idx = tid + (it << 7);
            int r = idx >> 3, c8 = idx & 7;
            cp16(sb + 18432 + r * 144 + c8 * 16,
                 B + (size_t)(col0 + r) * PD + k0 + c8 * 8);
        }
        cp_commit();
    };

    load_stage(0, 0);
    cp_wait<0>();
    __syncthreads();

    for (int i = 0; i < nk; i++) {
        if (i + 1 < nk) load_stage((i + 1) & 1, i + 1);

        const uint32_t sA0 = sb0 + (i & 1) * NT_STAGE;
        const uint32_t sB0 = sA0 + 18432;

#pragma unroll
        for (int kk = 0; kk < 4; kk++) {
            const int k16 = kk << 4;

            uint32_t a[4][4];
#pragma unroll
            for (int mi = 0; mi < 4; mi++) {
                int m = warp_m * 64 + mi * 16 + (lane & 15);
                int k = k16 + ((lane & 16) ? 8 : 0);
                ldsm_x4(sA0 + m * 144 + k * 2, a[mi]);
            }

#pragma unroll
            for (int nt = 0; nt < 4; nt++) {
                uint32_t b4[4];
                int n = warp_n * 64 + nt * 16 + ((lane & 16) ? 8 : 0) + (lane & 7);
                int k = k16 + (lane & 8);
                ldsm_x4(sB0 + n * 144 + k * 2, b4);
#pragma unroll
                for (int mi = 0; mi < 4; mi++)
#pragma unroll
                    for (int nn = 0; nn < 2; nn++)
                        mma_f16(acc[mi][2 * nt + nn], a[mi], b4 + 2 * nn);
            }
        }

        if (i + 1 < nk) {
            cp_wait<0>();
            __syncthreads();
        }
    }

    // ---------------- epilogue ----------------
    if (EPI == 0) {
#pragma unroll
        for (int mi = 0; mi < 4; mi++) {
            const int rbase = row0 + warp_m * 64 + mi * 16 + (lane >> 2);
#pragma unroll
            for (int n = 0; n < 8; n++) {
                const int cb = col0 + warp_n * 64 + n * 8 + 2 * (lane & 3);
                float b0 = bias[cb], b1 = bias[cb + 1];
                __half h0 = __float2half(acc[mi][n][0] + b0);
                __half h1 = __float2half(acc[mi][n][1] + b1);
                __half h2 = __float2half(acc[mi][n][2] + b0);
                __half h3 = __float2half(acc[mi][n][3] + b1);
                *reinterpret_cast<uint32_t*>(C + (size_t)rbase * ldc + cb) = pkh(h0, h1);
                *reinterpret_cast<uint32_t*>(C + (size_t)(rbase + 8) * ldc + cb) = pkh(h2, h3);
            }
        }
    } else {
        float rs[4][2] = {{0,0},{0,0},{0,0},{0,0}};
        const float scale = 0.03125f;
#pragma unroll
        for (int mi = 0; mi < 4; mi++) {
            const int rbase = row0 + warp_m * 64 + mi * 16 + (lane >> 2);
#pragma unroll
            for (int n = 0; n < 8; n++) {
                const int cb = col0 + warp_n * 64 + n * 8 + 2 * (lane & 3);
                float e0 = __expf(acc[mi][n][0] * scale);
                float e1 = __expf(acc[mi][n][1] * scale);
                float e2 = __expf(acc[mi][n][2] * scale);
                float e3 = __expf(acc[mi][n][3] * scale);
                __half q0 = __float2half(e0), q1 = __float2half(e1);
                __half q2 = __float2half(e2), q3 = __float2half(e3);
                rs[mi][0] += __half2float(q0) + __half2float(q1);
                rs[mi][1] += __half2float(q2) + __half2float(q3);
                *reinterpret_cast<uint32_t*>(C + (size_t)rbase * ldc + cb) = pkh(q0, q1);
                *reinterpret_cast<uint32_t*>(C + (size_t)(rbase + 8) * ldc + cb) = pkh(q2, q3);
            }
        }
#pragma unroll
        for (int mi = 0; mi < 4; mi++)
#pragma unroll
            for (int h = 0; h < 2; h++) {
                rs[mi][h] += __shfl_xor_sync(0xffffffffu, rs[mi][h], 1);
                rs[mi][h] += __shfl_xor_sync(0xffffffffu, rs[mi][h], 2);
            }
        if ((lane & 3) == 0) {
            const int q = lane >> 2;
            const int t = blockIdx.x * 2 + warp_n;
#pragma unroll
            for (int mi = 0; mi < 4; mi++) {
                const int rl = row0 + warp_m * 64 + mi * 16 + q;
                const size_t rb = (size_t)bz * PS;
                psum[(rb + rl) * 64 + t]     = rs[mi][0];
                psum[(rb + rl + 8) * 64 + t] = rs[mi][1];
            }
        }
    }
}

// ---------------------------------------------------------------------------
// PV GEMM (fp16 1-term, NN): out[128x128] = (P @ V) * inv[row].
// CTA 128x128, BK=64, 4 warps (2m x 2n) 64x64.
// A(P): 128x144 = 18432; B(V) trans: 64 k-rows x 272B = 17408.
// Stage 35840; 2 stages = 71680 -> 2 CTAs/SM.
// ---------------------------------------------------------------------------
#define PV_STAGE 35840
#define PV_SMEM (2 * PV_STAGE)   // 71680

__global__ void __launch_bounds__(128, 2)
gemm_pv(const __half* __restrict__ Pf, const __half* __restrict__ V16,
        float* __restrict__ out, const float* __restrict__ inv)
{
    extern __shared__ char smem[];
    const uint32_t sb0 = smem_u32(smem);
    const int tid  = threadIdx.x;
    const int lane = tid & 31;
    const int wid  = tid >> 5;
    const int warp_m = wid & 1;
    const int warp_n = wid >> 1;
    const int bz = blockIdx.z;
    const int row0 = blockIdx.y * 128;
    const int col0 = blockIdx.x * 128;

    const __half* A = Pf  + (size_t)bz * PS * PS;
    const __half* B = V16 + (size_t)bz * PS * PD;

    float acc[4][8][4];
#pragma unroll
    for (int i = 0; i < 4; i++)
#pragma unroll
        for (int n = 0; n < 8; n++)
#pragma unroll
            for (int j = 0; j < 4; j++) acc[i][n][j] = 0.0f;

    const int nk = PS >> 6;   // 64 chunks of BK=64

    auto load_stage = [&](int stage, int ki) {
        const uint32_t sb = sb0 + stage * PV_STAGE;
        const int k0 = ki << 6;
        // A: 128 rows x 128B = 1024 x 16B chunks, 8/thread
#pragma unroll
        for (int it = 0; it < 8; it++) {
            int idx = tid + (it << 7);
            int r = idx >> 3, c8 = idx & 7;
            cp16(sb + r * 144 + c8 * 16,
                 A + (size_t)(row0 + r) * PS + k0 + c8 * 8);
        }
        // B: 64 k-rows x 256B = 1024 x 16B chunks, 8/thread, 272B row stride
#pragma unroll
        for (int it = 0; it < 8; it++) {
            int idx = tid + (it << 7);
            int r = idx >> 4, c16 = idx & 15;
            cp16(sb + 18432 + r * 272 + c16 * 16,
                 B + (size_t)(k0 + r) * PD + col0 + c16 * 8);
        }
        cp_commit();
    };

    load_stage(0, 0);
    cp_wait<0>();
    __syncthreads();

    for (int i = 0; i < nk; i++) {
        if (i + 1 < nk) load_stage((i + 1) & 1, i + 1);

        const uint32_t sA0 = sb0 + (i & 1) * PV_STAGE;
        const uint32_t sB0 = sA0 + 18432;

#pragma unroll
        for (int kk = 0; kk < 4; kk++) {
            const int k16 = kk << 4;

            uint32_t a[4][4];
#pragma unroll
            for (int mi = 0; mi < 4; mi++) {
                int m = warp_m * 64 + mi * 16 + (lane & 15);
                int k = k16 + ((lane & 16) ? 8 : 0);
                ldsm_x4(sA0 + m * 144 + k * 2, a[mi]);
            }

#pragma unroll
            for (int nt = 0; nt < 4; nt++) {
                uint32_t b4[4];
                int k = k16 + (lane & 15);
                int n = warp_n * 64 + nt * 16 + ((lane & 16) ? 8 : 0);
                ldsm_x4_t(sB0 + k * 272 + n * 2, b4);
#pragma unroll
                for (int mi = 0; mi < 4; mi++)
#pragma unroll
                    for (int nn = 0; nn < 2; nn++)
                        mma_f16(acc[mi][2 * nt + nn], a[mi], b4 + 2 * nn);
            }
        }

        if (i + 1 < nk) {
            cp_wait<0>();
            __syncthreads();
        }
    }

    // epilogue: scale by 1/rowsum
#pragma unroll
    for (int mi = 0; mi < 4; mi++) {
        const int rbase = row0 + warp_m * 64 + mi * 16 + (lane >> 2);
        const float iv0 = inv[(size_t)bz * PS + rbase];
        const float iv1 = inv[(size_t)bz * PS + rbase + 8];
        float* base = out + (size_t)bz * PS * PD;
#pragma unroll
        for (int n = 0; n < 8; n++) {
            const int cb = col0 + warp_n * 64 + n * 8 + 2 * (lane & 3);
            float2 v0 = make_float2(acc[mi][n][0] * iv0, acc[mi][n][1] * iv0);
            float2 v1 = make_float2(acc[mi][n][2] * iv1, acc[mi][n][3] * iv1);
            *reinterpret_cast<float2*>(base + (size_t)rbase * PD + cb) = v0;
            *reinterpret_cast<float2*>(base + (size_t)(rbase + 8) * PD + cb) = v1;
        }
    }
}

// ---------------------------------------------------------------------------
// Merged splits: x, Wq, Wk, Wv -> plain fp16 (one launch)
// ---------------------------------------------------------------------------
struct SplitArgs {
    const float* src[4];
    __half* dst[4];
};

__global__ void __launch_bounds__(256)
split_all(SplitArgs sa)
{
    int bid = blockIdx.x;
    int which, boff;
    if (bid < 16384) { which = 0; boff = bid; }
    else { which = 1 + ((bid - 16384) >> 10); boff = (bid - 16384) & 1023; }

    size_t i = (size_t)boff * 256 + threadIdx.x;
    float4 v = reinterpret_cast<const float4*>(sa.src[which])[i];
    __half h0 = __float2half(v.x), h1 = __float2half(v.y);
    __half h2 = __float2half(v.z), h3 = __float2half(v.w);
    reinterpret_cast<uint2*>(sa.dst[which])[i] = make_uint2(pkh(h0, h1), pkh(h2, h3));
}

// ---------------------------------------------------------------------------
// Rowsum reduce: one warp per row sums 64 partials -> 1/sum
// ---------------------------------------------------------------------------
__global__ void __launch_bounds__(256)
rowsum_inv(const float* __restrict__ psum, float* __restrict__ inv)
{
    const int row  = (blockIdx.x * blockDim.x + threadIdx.x) >> 5;
    const int lane = threadIdx.x & 31;
    float2 v = reinterpret_cast<const float2*>(psum + (size_t)row * 64)[lane];
    float s = v.x + v.y;
#pragma unroll
    for (int o = 16; o > 0; o >>= 1)
        s += __shfl_xor_sync(0xffffffffu, s, o);
    if (lane == 0) inv[row] = 1.0f / s;
}

// ---------------------------------------------------------------------------
// Launcher
// ---------------------------------------------------------------------------
extern "C" void kernel_launch(void* const* d_in, const int* in_sizes, int n_in,
                              void* d_out, int out_size)
{
    (void)in_sizes; (void)n_in; (void)out_size;
    const float* x  = (const float*)d_in[0];
    const float* Wq = (const float*)d_in[1];
    const float* bq = (const float*)d_in[2];
    const float* Wk = (const float*)d_in[3];
    const float* bk = (const float*)d_in[4];
    const float* Wv = (const float*)d_in[5];
    const float* bv = (const float*)d_in[6];
    float* out = (float*)d_out;

    __half *x16, *Wq16, *Wk16, *Wv16, *Q16, *K16, *V16, *Pf;
    float *psum, *inv;
    cudaGetSymbolAddress((void**)&x16,  g_x16);
    cudaGetSymbolAddress((void**)&Wq16, g_Wq16);
    cudaGetSymbolAddress((void**)&Wk16, g_Wk16);
    cudaGetSymbolAddress((void**)&Wv16, g_Wv16);
    cudaGetSymbolAddress((void**)&Q16,  g_Q16);
    cudaGetSymbolAddress((void**)&K16,  g_K16);
    cudaGetSymbolAddress((void**)&V16,  g_V16);
    cudaGetSymbolAddress((void**)&Pf,   g_Pf);
    cudaGetSymbolAddress((void**)&psum, g_psum);
    cudaGetSymbolAddress((void**)&inv,  g_inv);

    cudaFuncSetAttribute((const void*)gemm_nt<0>,
                         cudaFuncAttributeMaxDynamicSharedMemorySize, NT_SMEM);
    cudaFuncSetAttribute((const void*)gemm_nt<1>,
                         cudaFuncAttributeMaxDynamicSharedMemorySize, NT_SMEM);
    cudaFuncSetAttribute((const void*)gemm_pv,
                         cudaFuncAttributeMaxDynamicSharedMemorySize, PV_SMEM);

    // 1) merged splits: x + Wq/Wk/Wv -> plain fp16
    SplitArgs sa;
    sa.src[0] = x;  sa.dst[0] = x16;
    sa.src[1] = Wq; sa.dst[1] = Wq16;
    sa.src[2] = Wk; sa.dst[2] = Wk16;
    sa.src[3] = Wv; sa.dst[3] = Wv16;
    split_all<<<16384 + 3 * 1024, 256>>>(sa);

    // 2) merged projections (fp16 1-term): z=0/1/2 -> Q/K/V plain fp16
    ProjArgs pa;
    pa.s[0] = { Wq16, bq, Q16 };
    pa.s[1] = { Wk16, bk, K16 };
    pa.s[2] = { Wv16, bv, V16 };
    ProjArgs dummy = {};
    dim3 gp(PD / 128, MROWS / 128, 3);
    gemm_nt<0><<<gp, 128, NT_SMEM>>>(x16, nullptr, pa, nullptr, nullptr);

    // 3) scores + fused exp (fp16 1-term) -> fp16 P, psum partials
    dim3 gs(PS / 128, PS / 128, PB);
    gemm_nt<1><<<gs, 128, NT_SMEM>>>(Q16, K16, dummy, Pf, psum);

    // 4) rowsum -> 1/sum
    rowsum_inv<<<(PB * PS * 32) / 256, 256>>>(psum, inv);

    // 5) out = (P @ V) * inv   (fp16 1-term, CTA 128x128, BK=64)
    dim3 go(PD / 128, PS / 128, PB);
    gemm_pv<<<go, 128, PV_SMEM>>>(Pf, V16, out, inv);
}

// round 12
// speedup vs baseline: 3.1495x; 1.0018x over previous
#include <cuda_runtime.h>
#include <cuda_fp16.h>
#include <math_constants.h>
#include <cstdint>

// Problem shape (fixed): B=4, S=4096, D=1024
#define PB 4
#define PS 4096
#define PD 1024
#define MROWS (PB * PS)   // 16384

// ---------------------------------------------------------------------------
// Global scratch (allocation-guard-safe __device__ arrays)
// ---------------------------------------------------------------------------
__device__ __half g_x16[(size_t)MROWS * PD];
__device__ __half g_Wq16[PD * PD], g_Wk16[PD * PD], g_Wv16[PD * PD];
__device__ __half g_Q16[(size_t)MROWS * PD];
__device__ __half g_K16[(size_t)MROWS * PD];
__device__ __half g_V16[(size_t)MROWS * PD];
__device__ __half g_Pf[(size_t)PB * PS * PS];    // exp scores, fp16
__device__ float g_psum[(size_t)PB * PS * 64];   // per-row partial expsums
__device__ float g_inv [(size_t)PB * PS];        // 1 / rowsum

// ---------------------------------------------------------------------------
// PTX helpers (baseline sm_80+ features only: compile-safe under compute_103)
// ---------------------------------------------------------------------------
__device__ __forceinline__ uint32_t smem_u32(const void* p) {
    uint32_t a;
    asm("{ .reg .u64 t; cvta.to.shared.u64 t, %1; cvt.u32.u64 %0, t; }"
        : "=r"(a) : "l"(p));
    return a;
}

__device__ __forceinline__ void cp16(uint32_t s, const void* g) {
    asm volatile("cp.async.cg.shared.global [%0], [%1], 16;" :: "r"(s), "l"(g));
}
__device__ __forceinline__ void cp_commit() {
    asm volatile("cp.async.commit_group;" ::: "memory");
}
template<int N>
__device__ __forceinline__ void cp_wait() {
    asm volatile("cp.async.wait_group %0;" :: "n"(N) : "memory");
}

__device__ __forceinline__ void ldsm_x4(uint32_t a, uint32_t* r) {
    asm volatile("ldmatrix.sync.aligned.m8n8.x4.shared.b16 {%0,%1,%2,%3}, [%4];"
                 : "=r"(r[0]), "=r"(r[1]), "=r"(r[2]), "=r"(r[3]) : "r"(a));
}
__device__ __forceinline__ void ldsm_x4_t(uint32_t a, uint32_t* r) {
    asm volatile("ldmatrix.sync.aligned.m8n8.x4.trans.shared.b16 {%0,%1,%2,%3}, [%4];"
                 : "=r"(r[0]), "=r"(r[1]), "=r"(r[2]), "=r"(r[3]) : "r"(a));
}

__device__ __forceinline__ void mma_f16(float* c, const uint32_t* a,
                                        const uint32_t* b) {
    asm volatile(
        "mma.sync.aligned.m16n8k16.row.col.f32.f16.f16.f32 "
        "{%0,%1,%2,%3},{%4,%5,%6,%7},{%8,%9},{%0,%1,%2,%3};"
        : "+f"(c[0]), "+f"(c[1]), "+f"(c[2]), "+f"(c[3])
        : "r"(a[0]), "r"(a[1]), "r"(a[2]), "r"(a[3]), "r"(b[0]), "r"(b[1]));
}

__device__ __forceinline__ uint32_t pkh(__half a, __half b) {
    return (uint32_t)__half_as_ushort(a) | ((uint32_t)__half_as_ushort(b) << 16);
}

// ---------------------------------------------------------------------------
// NT GEMM core (fp16 1-term): CTA 128x128, BK=64, 4 warps (2m x 2n) 64x64.
// 144B-padded rows, conflict-free. Stage 36864 x2 -> 2 CTAs/SM.
// Fragment-level software pipelining: A double-buffered across kk,
// B double-buffered across nt (hides ~29cyc LDSM latency behind MMA groups).
// EPI=0: +bias, fp16 store (projections). EPI=1: exp, fp16 P + psum (scores).
// ---------------------------------------------------------------------------
#define NT_STAGE 36864
#define NT_SMEM (2 * NT_STAGE)   // 73728

struct ProjSet {
    const __half* W16;
    const float* bias;
    __half* C16;
};
struct ProjArgs { ProjSet s[3]; };

template<int EPI>
__global__ void __launch_bounds__(128, 2)
gemm_nt(const __half* __restrict__ A_, const __half* __restrict__ B_,
        ProjArgs pa, __half* __restrict__ Pf, float* __restrict__ psum)
{
    extern __shared__ char smem[];
    const uint32_t sb0 = smem_u32(smem);
    const int tid  = threadIdx.x;
    const int lane = tid & 31;
    const int wid  = tid >> 5;
    const int warp_m = wid & 1;
    const int warp_n = wid >> 1;
    const int bz = blockIdx.z;

    const __half* A;
    const __half* B;
    const float* bias = nullptr;
    __half* C = nullptr;
    if (EPI == 0) {
        A = A_;
        const ProjSet& s = pa.s[bz];
        B = s.W16; bias = s.bias; C = s.C16;
    } else {
        A = A_ + (size_t)bz * PS * PD;
        B = B_ + (size_t)bz * PS * PD;
        C = Pf + (size_t)bz * PS * PS;
    }

    const int row0 = blockIdx.y * 128;
    const int col0 = blockIdx.x * 128;
    const int ldc  = (EPI == 0) ? PD : PS;

    float acc[4][8][4];
#pragma unroll
    for (int i = 0; i < 4; i++)
#pragma unroll
        for (int n = 0; n < 8; n++)
#pragma unroll
            for (int j = 0; j < 4; j++) acc[i][n][j] = 0.0f;

    const int nk = PD >> 6;   // 16 chunks of BK=64

    auto load_stage = [&](int stage, int ki) {
        const uint32_t sb = sb0 + stage * NT_STAGE;
        const int k0 = ki << 6;
#pragma unroll
        for (int it = 0; it < 8; it++) {
            int idx = tid + (it << 7);
            int r = idx >> 3, c8 = idx & 7;
            cp16(sb + r * 144 + c8 * 16,
                 A + (size_t)(row0 + r) * PD + k0 + c8 * 8);
        }
#pragma unroll
        for (int it = 0; it < 8; it++) {
            int idx = tid + (it << 7);
            int r = idx >> 3, c8 = idx & 7;
            cp16(sb + 18432 + r * 144 + c8 * 16,
                 B + (size_t)(col0 + r) * PD + k0 + c8 * 8);
        }
        cp_commit();
    };

    load_stage(0, 0);
    cp_wait<0>();
    __syncthreads();

    for (int i = 0; i < nk; i++) {
        if (i + 1 < nk) load_stage((i + 1) & 1, i + 1);

        const uint32_t sA0 = sb0 + (i & 1) * NT_STAGE;
        const uint32_t sB0 = sA0 + 18432;

        uint32_t afr[2][4][4];
        uint32_t bfr[2][4];

        auto load_a = [&](int buf, int kkv) {
#pragma unroll
            for (int mi = 0; mi < 4; mi++) {
                int m = warp_m * 64 + mi * 16 + (lane & 15);
                int k = (kkv << 4) + ((lane & 16) ? 8 : 0);
                ldsm_x4(sA0 + m * 144 + k * 2, afr[buf][mi]);
            }
        };
        auto load_b = [&](int buf, int kkv, int ntv) {
            int n = warp_n * 64 + ntv * 16 + ((lane & 16) ? 8 : 0) + (lane & 7);
            int k = (kkv << 4) + (lane & 8);
            ldsm_x4(sB0 + n * 144 + k * 2, bfr[buf]);
        };

        load_a(0, 0);
        load_b(0, 0, 0);

#pragma unroll
        for (int kk = 0; kk < 4; kk++) {
            const int ab = kk & 1;
#pragma unroll
            for (int nt = 0; nt < 4; nt++) {
                const int bb = (kk * 4 + nt) & 1;
                if (nt < 3)        load_b(bb ^ 1, kk, nt + 1);
                else if (kk < 3) { load_a(ab ^ 1, kk + 1); load_b(bb ^ 1, kk + 1, 0); }
#pragma unroll
                for (int mi = 0; mi < 4; mi++)
#pragma unroll
                    for (int nn = 0; nn < 2; nn++)
                        mma_f16(acc[mi][2 * nt + nn], afr[ab][mi], bfr[bb] + 2 * nn);
            }
        }

        if (i + 1 < nk) {
            cp_wait<0>();
            __syncthreads();
        }
    }

    // ---------------- epilogue ----------------
    if (EPI == 0) {
#pragma unroll
        for (int mi = 0; mi < 4; mi++) {
            const int rbase = row0 + warp_m * 64 + mi * 16 + (lane >> 2);
#pragma unroll
            for (int n = 0; n < 8; n++) {
                const int cb = col0 + warp_n * 64 + n * 8 + 2 * (lane & 3);
                float b0 = bias[cb], b1 = bias[cb + 1];
                __half h0 = __float2half(acc[mi][n][0] + b0);
                __half h1 = __float2half(acc[mi][n][1] + b1);
                __half h2 = __float2half(acc[mi][n][2] + b0);
                __half h3 = __float2half(acc[mi][n][3] + b1);
                *reinterpret_cast<uint32_t*>(C + (size_t)rbase * ldc + cb) = pkh(h0, h1);
                *reinterpret_cast<uint32_t*>(C + (size_t)(rbase + 8) * ldc + cb) = pkh(h2, h3);
            }
        }
    } else {
        float rs[4][2] = {{0,0},{0,0},{0,0},{0,0}};
        const float scale = 0.03125f;
#pragma unroll
        for (int mi = 0; mi < 4; mi++) {
            const int rbase = row0 + warp_m * 64 + mi * 16 + (lane >> 2);
#pragma unroll
            for (int n = 0; n < 8; n++) {
                const int cb = col0 + warp_n * 64 + n * 8 + 2 * (lane & 3);
                float e0 = __expf(acc[mi][n][0] * scale);
                float e1 = __expf(acc[mi][n][1] * scale);
                float e2 = __expf(acc[mi][n][2] * scale);
                float e3 = __expf(acc[mi][n][3] * scale);
                __half q0 = __float2half(e0), q1 = __float2half(e1);
                __half q2 = __float2half(e2), q3 = __float2half(e3);
                rs[mi][0] += __half2float(q0) + __half2float(q1);
                rs[mi][1] += __half2float(q2) + __half2float(q3);
                *reinterpret_cast<uint32_t*>(C + (size_t)rbase * ldc + cb) = pkh(q0, q1);
                *reinterpret_cast<uint32_t*>(C + (size_t)(rbase + 8) * ldc + cb) = pkh(q2, q3);
            }
        }
#pragma unroll
        for (int mi = 0; mi < 4; mi++)
#pragma unroll
            for (int h = 0; h < 2; h++) {
                rs[mi][h] += __shfl_xor_sync(0xffffffffu, rs[mi][h], 1);
                rs[mi][h] += __shfl_xor_sync(0xffffffffu, rs[mi][h], 2);
            }
        if ((lane & 3) == 0) {
            const int q = lane >> 2;
            const int t = blockIdx.x * 2 + warp_n;
#pragma unroll
            for (int mi = 0; mi < 4; mi++) {
                const int rl = row0 + warp_m * 64 + mi * 16 + q;
                const size_t rb = (size_t)bz * PS;
                psum[(rb + rl) * 64 + t]     = rs[mi][0];
                psum[(rb + rl + 8) * 64 + t] = rs[mi][1];
            }
        }
    }
}

// ---------------------------------------------------------------------------
// PV GEMM (fp16 1-term, NN): out[128x128] = (P @ V) * inv[row].
// CTA 128x128, BK=64, 4 warps (2m x 2n) 64x64. Same fragment pipelining.
// Stage 35840 x2 -> 2 CTAs/SM.
// ---------------------------------------------------------------------------
#define PV_STAGE 35840
#define PV_SMEM (2 * PV_STAGE)   // 71680

__global__ void __launch_bounds__(128, 2)
gemm_pv(const __half* __restrict__ Pf, const __half* __restrict__ V16,
        float* __restrict__ out, const float* __restrict__ inv)
{
    extern __shared__ char smem[];
    const uint32_t sb0 = smem_u32(smem);
    const int tid  = threadIdx.x;
    const int lane = tid & 31;
    const int wid  = tid >> 5;
    const int warp_m = wid & 1;
    const int warp_n = wid >> 1;
    const int bz = blockIdx.z;
    const int row0 = blockIdx.y * 128;
    const int col0 = blockIdx.x * 128;

    const __half* A = Pf  + (size_t)bz * PS * PS;
    const __half* B = V16 + (size_t)bz * PS * PD;

    float acc[4][8][4];
#pragma unroll
    for (int i = 0; i < 4; i++)
#pragma unroll
        for (int n = 0; n < 8; n++)
#pragma unroll
            for (int j = 0; j < 4; j++) acc[i][n][j] = 0.0f;

    const int nk = PS >> 6;   // 64 chunks of BK=64

    auto load_stage = [&](int stage, int ki) {
        const uint32_t sb = sb0 + stage * PV_STAGE;
        const int k0 = ki << 6;
#pragma unroll
        for (int it = 0; it < 8; it++) {
            int idx = tid + (it << 7);
            int r = idx >> 3, c8 = idx & 7;
            cp16(sb + r * 144 + c8 * 16,
                 A + (size_t)(row0 + r) * PS + k0 + c8 * 8);
        }
#pragma unroll
        for (int it = 0; it < 8; it++) {
            int idx = tid + (it << 7);
            int r = idx >> 4, c16 = idx & 15;
            cp16(sb + 18432 + r * 272 + c16 * 16,
                 B + (size_t)(k0 + r) * PD + col0 + c16 * 8);
        }
        cp_commit();
    };

    load_stage(0, 0);
    cp_wait<0>();
    __syncthreads();

    for (int i = 0; i < nk; i++) {
        if (i + 1 < nk) load_stage((i + 1) & 1, i + 1);

        const uint32_t sA0 = sb0 + (i & 1) * PV_STAGE;
        const uint32_t sB0 = sA0 + 18432;

        uint32_t afr[2][4][4];
        uint32_t bfr[2][4];

        auto load_a = [&](int buf, int kkv) {
#pragma unroll
            for (int mi = 0; mi < 4; mi++) {
                int m = warp_m * 64 + mi * 16 + (lane & 15);
                int k = (kkv << 4) + ((lane & 16) ? 8 : 0);
                ldsm_x4(sA0 + m * 144 + k * 2, afr[buf][mi]);
            }
        };
        auto load_b = [&](int buf, int kkv, int ntv) {
            int k = (kkv << 4) + (lane & 15);
            int n = warp_n * 64 + ntv * 16 + ((lane & 16) ? 8 : 0);
            ldsm_x4_t(sB0 + k * 272 + n * 2, bfr[buf]);
        };

        load_a(0, 0);
        load_b(0, 0, 0);

#pragma unroll
        for (int kk = 0; kk < 4; kk++) {
            const int ab = kk & 1;
#pragma unroll
            for (int nt = 0; nt < 4; nt++) {
                const int bb = (kk * 4 + nt) & 1;
                if (nt < 3)        load_b(bb ^ 1, kk, nt + 1);
                else if (kk < 3) { load_a(ab ^ 1, kk + 1); load_b(bb ^ 1, kk + 1, 0); }
#pragma unroll
                for (int mi = 0; mi < 4; mi++)
#pragma unroll
                    for (int nn = 0; nn < 2; nn++)
                        mma_f16(acc[mi][2 * nt + nn], afr[ab][mi], bfr[bb] + 2 * nn);
            }
        }

        if (i + 1 < nk) {
            cp_wait<0>();
            __syncthreads();
        }
    }

    // epilogue: scale by 1/rowsum
#pragma unroll
    for (int mi = 0; mi < 4; mi++) {
        const int rbase = row0 + warp_m * 64 + mi * 16 + (lane >> 2);
        const float iv0 = inv[(size_t)bz * PS + rbase];
        const float iv1 = inv[(size_t)bz * PS + rbase + 8];
        float* base = out + (size_t)bz * PS * PD;
#pragma unroll
        for (int n = 0; n < 8; n++) {
            const int cb = col0 + warp_n * 64 + n * 8 + 2 * (lane & 3);
            float2 v0 = make_float2(acc[mi][n][0] * iv0, acc[mi][n][1] * iv0);
            float2 v1 = make_float2(acc[mi][n][2] * iv1, acc[mi][n][3] * iv1);
            *reinterpret_cast<float2*>(base + (size_t)rbase * PD + cb) = v0;
            *reinterpret_cast<float2*>(base + (size_t)(rbase + 8) * PD + cb) = v1;
        }
    }
}

// ---------------------------------------------------------------------------
// Merged splits: x, Wq, Wk, Wv -> plain fp16 (one launch)
// ---------------------------------------------------------------------------
struct SplitArgs {
    const float* src[4];
    __half* dst[4];
};

__global__ void __launch_bounds__(256)
split_all(SplitArgs sa)
{
    int bid = blockIdx.x;
    int which, boff;
    if (bid < 16384) { which = 0; boff = bid; }
    else { which = 1 + ((bid - 16384) >> 10); boff = (bid - 16384) & 1023; }

    size_t i = (size_t)boff * 256 + threadIdx.x;
    float4 v = reinterpret_cast<const float4*>(sa.src[which])[i];
    __half h0 = __float2half(v.x), h1 = __float2half(v.y);
    __half h2 = __float2half(v.z), h3 = __float2half(v.w);
    reinterpret_cast<uint2*>(sa.dst[which])[i] = make_uint2(pkh(h0, h1), pkh(h2, h3));
}

// ---------------------------------------------------------------------------
// Rowsum reduce: one warp per row sums 64 partials -> 1/sum
// ---------------------------------------------------------------------------
__global__ void __launch_bounds__(256)
rowsum_inv(const float* __restrict__ psum, float* __restrict__ inv)
{
    const int row  = (blockIdx.x * blockDim.x + threadIdx.x) >> 5;
    const int lane = threadIdx.x & 31;
    float2 v = reinterpret_cast<const float2*>(psum + (size_t)row * 64)[lane];
    float s = v.x + v.y;
#pragma unroll
    for (int o = 16; o > 0; o >>= 1)
        s += __shfl_xor_sync(0xffffffffu, s, o);
    if (lane == 0) inv[row] = 1.0f / s;
}

// ---------------------------------------------------------------------------
// Launcher
// ---------------------------------------------------------------------------
extern "C" void kernel_launch(void* const* d_in, const int* in_sizes, int n_in,
                              void* d_out, int out_size)
{
    (void)in_sizes; (void)n_in; (void)out_size;
    const float* x  = (const float*)d_in[0];
    const float* Wq = (const float*)d_in[1];
    const float* bq = (const float*)d_in[2];
    const float* Wk = (const float*)d_in[3];
    const float* bk = (const float*)d_in[4];
    const float* Wv = (const float*)d_in[5];
    const float* bv = (const float*)d_in[6];
    float* out = (float*)d_out;

    __half *x16, *Wq16, *Wk16, *Wv16, *Q16, *K16, *V16, *Pf;
    float *psum, *inv;
    cudaGetSymbolAddress((void**)&x16,  g_x16);
    cudaGetSymbolAddress((void**)&Wq16, g_Wq16);
    cudaGetSymbolAddress((void**)&Wk16, g_Wk16);
    cudaGetSymbolAddress((void**)&Wv16, g_Wv16);
    cudaGetSymbolAddress((void**)&Q16,  g_Q16);
    cudaGetSymbolAddress((void**)&K16,  g_K16);
    cudaGetSymbolAddress((void**)&V16,  g_V16);
    cudaGetSymbolAddress((void**)&Pf,   g_Pf);
    cudaGetSymbolAddress((void**)&psum, g_psum);
    cudaGetSymbolAddress((void**)&inv,  g_inv);

    cudaFuncSetAttribute((const void*)gemm_nt<0>,
                         cudaFuncAttributeMaxDynamicSharedMemorySize, NT_SMEM);
    cudaFuncSetAttribute((const void*)gemm_nt<1>,
                         cudaFuncAttributeMaxDynamicSharedMemorySize, NT_SMEM);
    cudaFuncSetAttribute((const void*)gemm_pv,
                         cudaFuncAttributeMaxDynamicSharedMemorySize, PV_SMEM);

    // 1) merged splits: x + Wq/Wk/Wv -> plain fp16
    SplitArgs sa;
    sa.src[0] = x;  sa.dst[0] = x16;
    sa.src[1] = Wq; sa.dst[1] = Wq16;
    sa.src[2] = Wk; sa.dst[2] = Wk16;
    sa.src[3] = Wv; sa.dst[3] = Wv16;
    split_all<<<16384 + 3 * 1024, 256>>>(sa);

    // 2) merged projections (fp16 1-term): z=0/1/2 -> Q/K/V plain fp16
    ProjArgs pa;
    pa.s[0] = { Wq16, bq, Q16 };
    pa.s[1] = { Wk16, bk, K16 };
    pa.s[2] = { Wv16, bv, V16 };
    ProjArgs dummy = {};
    dim3 gp(PD / 128, MROWS / 128, 3);
    gemm_nt<0><<<gp, 128, NT_SMEM>>>(x16, nullptr, pa, nullptr, nullptr);

    // 3) scores + fused exp (fp16 1-term) -> fp16 P, psum partials
    dim3 gs(PS / 128, PS / 128, PB);
    gemm_nt<1><<<gs, 128, NT_SMEM>>>(Q16, K16, dummy, Pf, psum);

    // 4) rowsum -> 1/sum
    rowsum_inv<<<(PB * PS * 32) / 256, 256>>>(psum, inv);

    // 5) out = (P @ V) * inv   (fp16 1-term, CTA 128x128, BK=64)
    dim3 go(PD / 128, PS / 128, PB);
    gemm_pv<<<go, 128, PV_SMEM>>>(Pf, V16, out, inv);
}

// round 13
// speedup vs baseline: 3.4190x; 1.0855x over previous
#include <cuda_runtime.h>
#include <cuda_fp16.h>
#include <math_constants.h>
#include <cstdint>

// Problem shape (fixed): B=4, S=4096, D=1024
#define PB 4
#define PS 4096
#define PD 1024
#define MROWS (PB * PS)   // 16384

// ---------------------------------------------------------------------------
// Global scratch (allocation-guard-safe __device__ arrays)
// ---------------------------------------------------------------------------
__device__ __half g_x16[(size_t)MROWS * PD];
__device__ __half g_Wq16[PD * PD], g_Wk16[PD * PD], g_Wv16[PD * PD];
__device__ __half g_Q16[(size_t)MROWS * PD];
__device__ __half g_K16[(size_t)MROWS * PD];
__device__ __half g_V16[(size_t)MROWS * PD];
__device__ __half g_Pf[(size_t)PB * PS * PS];    // exp scores, fp16
__device__ float g_psum[(size_t)PB * PS * 64];   // per-row partial expsums

// ---------------------------------------------------------------------------
// PTX helpers (baseline sm_80+ features only: compile-safe under compute_103)
// ---------------------------------------------------------------------------
__device__ __forceinline__ uint32_t smem_u32(const void* p) {
    uint32_t a;
    asm("{ .reg .u64 t; cvta.to.shared.u64 t, %1; cvt.u32.u64 %0, t; }"
        : "=r"(a) : "l"(p));
    return a;
}

__device__ __forceinline__ void cp16(uint32_t s, const void* g) {
    asm volatile("cp.async.cg.shared.global [%0], [%1], 16;" :: "r"(s), "l"(g));
}
__device__ __forceinline__ void cp_commit() {
    asm volatile("cp.async.commit_group;" ::: "memory");
}
template<int N>
__device__ __forceinline__ void cp_wait() {
    asm volatile("cp.async.wait_group %0;" :: "n"(N) : "memory");
}

__device__ __forceinline__ void ldsm_x4(uint32_t a, uint32_t* r) {
    asm volatile("ldmatrix.sync.aligned.m8n8.x4.shared.b16 {%0,%1,%2,%3}, [%4];"
                 : "=r"(r[0]), "=r"(r[1]), "=r"(r[2]), "=r"(r[3]) : "r"(a));
}
__device__ __forceinline__ void ldsm_x4_t(uint32_t a, uint32_t* r) {
    asm volatile("ldmatrix.sync.aligned.m8n8.x4.trans.shared.b16 {%0,%1,%2,%3}, [%4];"
                 : "=r"(r[0]), "=r"(r[1]), "=r"(r[2]), "=r"(r[3]) : "r"(a));
}

__device__ __forceinline__ void mma_f16(float* c, const uint32_t* a,
                                        const uint32_t* b) {
    asm volatile(
        "mma.sync.aligned.m16n8k16.row.col.f32.f16.f16.f32 "
        "{%0,%1,%2,%3},{%4,%5,%6,%7},{%8,%9},{%0,%1,%2,%3};"
        : "+f"(c[0]), "+f"(c[1]), "+f"(c[2]), "+f"(c[3])
        : "r"(a[0]), "r"(a[1]), "r"(a[2]), "r"(a[3]), "r"(b[0]), "r"(b[1]));
}

__device__ __forceinline__ uint32_t pkh(__half a, __half b) {
    return (uint32_t)__half_as_ushort(a) | ((uint32_t)__half_as_ushort(b) << 16);
}

// ---------------------------------------------------------------------------
// NT GEMM core (fp16 1-term): CTA 128x128, BK=64, 4 warps (2m x 2n) 64x64.
// 144B-padded rows, conflict-free. Stage 36864 x2; occupancy 3 CTAs/SM.
// EPI=0: +bias, fp16 store (projections). EPI=1: exp, fp16 P + psum (scores).
// ---------------------------------------------------------------------------
#define NT_STAGE 36864
#define NT_SMEM (2 * NT_STAGE)   // 73728

struct ProjSet {
    const __half* W16;
    const float* bias;
    __half* C16;
};
struct ProjArgs { ProjSet s[3]; };

template<int EPI>
__global__ void __launch_bounds__(128, 3)
gemm_nt(const __half* __restrict__ A_, const __half* __restrict__ B_,
        ProjArgs pa, __half* __restrict__ Pf, float* __restrict__ psum)
{
    extern __shared__ char smem[];
    const uint32_t sb0 = smem_u32(smem);
    const int tid  = threadIdx.x;
    const int lane = tid & 31;
    const int wid  = tid >> 5;
    const int warp_m = wid & 1;
    const int warp_n = wid >> 1;
    const int bz = blockIdx.z;

    const __half* A;
    const __half* B;
    const float* bias = nullptr;
    __half* C = nullptr;
    if (EPI == 0) {
        A = A_;
        const ProjSet& s = pa.s[bz];
        B = s.W16; bias = s.bias; C = s.C16;
    } else {
        A = A_ + (size_t)bz * PS * PD;
        B = B_ + (size_t)bz * PS * PD;
        C = Pf + (size_t)bz * PS * PS;
    }

    const int row0 = blockIdx.y * 128;
    const int col0 = blockIdx.x * 128;
    const int ldc  = (EPI == 0) ? PD : PS;

    float acc[4][8][4];
#pragma unroll
    for (int i = 0; i < 4; i++)
#pragma unroll
        for (int n = 0; n < 8; n++)
#pragma unroll
            for (int j = 0; j < 4; j++) acc[i][n][j] = 0.0f;

    const int nk = PD >> 6;   // 16 chunks of BK=64

    auto load_stage = [&](int stage, int ki) {
        const uint32_t sb = sb0 + stage * NT_STAGE;
        const int k0 = ki << 6;
#pragma unroll
        for (int it = 0; it < 8; it++) {
            int idx = tid + (it << 7);
            int r = idx >> 3, c8 = idx & 7;
            cp16(sb + r * 144 + c8 * 16,
                 A + (size_t)(row0 + r) * PD + k0 + c8 * 8);
        }
#pragma unroll
        for (int it = 0; it < 8; it++) {
            int idx = tid + (it << 7);
            int r = idx >> 3, c8 = idx & 7;
            cp16(sb + 18432 + r * 144 + c8 * 16,
                 B + (size_t)(col0 + r) * PD + k0 + c8 * 8);
        }
        cp_commit();
    };

    load_stage(0, 0);
    cp_wait<0>();
    __syncthreads();

    for (int i = 0; i < nk; i++) {
        if (i + 1 < nk) load_stage((i + 1) & 1, i + 1);

        const uint32_t sA0 = sb0 + (i & 1) * NT_STAGE;
        const uint32_t sB0 = sA0 + 18432;

#pragma unroll
        for (int kk = 0; kk < 4; kk++) {
            const int k16 = kk << 4;

            uint32_t a[4][4];
#pragma unroll
            for (int mi = 0; mi < 4; mi++) {
                int m = warp_m * 64 + mi * 16 + (lane & 15);
                int k = k16 + ((lane & 16) ? 8 : 0);
                ldsm_x4(sA0 + m * 144 + k * 2, a[mi]);
            }

#pragma unroll
            for (int nt = 0; nt < 4; nt++) {
                uint32_t b4[4];
                int n = warp_n * 64 + nt * 16 + ((lane & 16) ? 8 : 0) + (lane & 7);
                int k = k16 + (lane & 8);
                ldsm_x4(sB0 + n * 144 + k * 2, b4);
#pragma unroll
                for (int mi = 0; mi < 4; mi++)
#pragma unroll
                    for (int nn = 0; nn < 2; nn++)
                        mma_f16(acc[mi][2 * nt + nn], a[mi], b4 + 2 * nn);
            }
        }

        if (i + 1 < nk) {
            cp_wait<0>();
            __syncthreads();
        }
    }

    // ---------------- epilogue ----------------
    if (EPI == 0) {
#pragma unroll
        for (int mi = 0; mi < 4; mi++) {
            const int rbase = row0 + warp_m * 64 + mi * 16 + (lane >> 2);
#pragma unroll
            for (int n = 0; n < 8; n++) {
                const int cb = col0 + warp_n * 64 + n * 8 + 2 * (lane & 3);
                float b0 = bias[cb], b1 = bias[cb + 1];
                __half h0 = __float2half(acc[mi][n][0] + b0);
                __half h1 = __float2half(acc[mi][n][1] + b1);
                __half h2 = __float2half(acc[mi][n][2] + b0);
                __half h3 = __float2half(acc[mi][n][3] + b1);
                *reinterpret_cast<uint32_t*>(C + (size_t)rbase * ldc + cb) = pkh(h0, h1);
                *reinterpret_cast<uint32_t*>(C + (size_t)(rbase + 8) * ldc + cb) = pkh(h2, h3);
            }
        }
    } else {
        float rs[4][2] = {{0,0},{0,0},{0,0},{0,0}};
        const float scale = 0.03125f;
#pragma unroll
        for (int mi = 0; mi < 4; mi++) {
            const int rbase = row0 + warp_m * 64 + mi * 16 + (lane >> 2);
#pragma unroll
            for (int n = 0; n < 8; n++) {
                const int cb = col0 + warp_n * 64 + n * 8 + 2 * (lane & 3);
                float e0 = __expf(acc[mi][n][0] * scale);
                float e1 = __expf(acc[mi][n][1] * scale);
                float e2 = __expf(acc[mi][n][2] * scale);
                float e3 = __expf(acc[mi][n][3] * scale);
                __half q0 = __float2half(e0), q1 = __float2half(e1);
                __half q2 = __float2half(e2), q3 = __float2half(e3);
                rs[mi][0] += __half2float(q0) + __half2float(q1);
                rs[mi][1] += __half2float(q2) + __half2float(q3);
                *reinterpret_cast<uint32_t*>(C + (size_t)rbase * ldc + cb) = pkh(q0, q1);
                *reinterpret_cast<uint32_t*>(C + (size_t)(rbase + 8) * ldc + cb) = pkh(q2, q3);
            }
        }
#pragma unroll
        for (int mi = 0; mi < 4; mi++)
#pragma unroll
            for (int h = 0; h < 2; h++) {
                rs[mi][h] += __shfl_xor_sync(0xffffffffu, rs[mi][h], 1);
                rs[mi][h] += __shfl_xor_sync(0xffffffffu, rs[mi][h], 2);
            }
        if ((lane & 3) == 0) {
            const int q = lane >> 2;
            const int t = blockIdx.x * 2 + warp_n;
#pragma unroll
            for (int mi = 0; mi < 4; mi++) {
                const int rl = row0 + warp_m * 64 + mi * 16 + q;
                const size_t rb = (size_t)bz * PS;
                psum[(rb + rl) * 64 + t]     = rs[mi][0];
                psum[(rb + rl + 8) * 64 + t] = rs[mi][1];
            }
        }
    }
}

// ---------------------------------------------------------------------------
// PV GEMM (fp16 1-term, NN): out[128x128] = (P @ V) * (1/rowsum).
// CTA 128x128, BK=64, 4 warps (2m x 2n). Rowsum reduction folded in:
// thread t computes inv for row row0+t from psum at kernel start (hidden
// behind the prologue load), stored in smem beyond the two stages.
// Stage 35840 x2 + 512B inv = 72192; 3 CTAs/SM.
// ---------------------------------------------------------------------------
#define PV_STAGE 35840
#define PV_SMEM (2 * PV_STAGE + 512)   // 72192

__global__ void __launch_bounds__(128, 3)
gemm_pv(const __half* __restrict__ Pf, const __half* __restrict__ V16,
        float* __restrict__ out, const float* __restrict__ psum)
{
    extern __shared__ char smem[];
    const uint32_t sb0 = smem_u32(smem);
    float* inv_s = reinterpret_cast<float*>(smem + 2 * PV_STAGE);
    const int tid  = threadIdx.x;
    const int lane = tid & 31;
    const int wid  = tid >> 5;
    const int warp_m = wid & 1;
    const int warp_n = wid >> 1;
    const int bz = blockIdx.z;
    const int row0 = blockIdx.y * 128;
    const int col0 = blockIdx.x * 128;

    const __half* A = Pf  + (size_t)bz * PS * PS;
    const __half* B = V16 + (size_t)bz * PS * PD;

    float acc[4][8][4];
#pragma unroll
    for (int i = 0; i < 4; i++)
#pragma unroll
        for (int n = 0; n < 8; n++)
#pragma unroll
            for (int j = 0; j < 4; j++) acc[i][n][j] = 0.0f;

    const int nk = PS >> 6;   // 64 chunks of BK=64

    auto load_stage = [&](int stage, int ki) {
        const uint32_t sb = sb0 + stage * PV_STAGE;
        const int k0 = ki << 6;
#pragma unroll
        for (int it = 0; it < 8; it++) {
            int idx = tid + (it << 7);
            int r = idx >> 3, c8 = idx & 7;
            cp16(sb + r * 144 + c8 * 16,
                 A + (size_t)(row0 + r) * PS + k0 + c8 * 8);
        }
#pragma unroll
        for (int it = 0; it < 8; it++) {
            int idx = tid + (it << 7);
            int r = idx >> 4, c16 = idx & 15;
            cp16(sb + 18432 + r * 272 + c16 * 16,
                 B + (size_t)(k0 + r) * PD + col0 + c16 * 8);
        }
        cp_commit();
    };

    load_stage(0, 0);

    // rowsum -> 1/sum for this CTA's 128 rows (overlapped with prologue load)
    {
        const float* pr = psum + ((size_t)bz * PS + row0 + tid) * 64;
        float s = 0.0f;
#pragma unroll
        for (int j = 0; j < 16; j++) {
            float4 v = reinterpret_cast<const float4*>(pr)[j];
            s += (v.x + v.y) + (v.z + v.w);
        }
        inv_s[tid] = 1.0f / s;
    }

    cp_wait<0>();
    __syncthreads();   // covers both stage 0 and inv_s visibility

    for (int i = 0; i < nk; i++) {
        if (i + 1 < nk) load_stage((i + 1) & 1, i + 1);

        const uint32_t sA0 = sb0 + (i & 1) * PV_STAGE;
        const uint32_t sB0 = sA0 + 18432;

#pragma unroll
        for (int kk = 0; kk < 4; kk++) {
            const int k16 = kk << 4;

            uint32_t a[4][4];
#pragma unroll
            for (int mi = 0; mi < 4; mi++) {
                int m = warp_m * 64 + mi * 16 + (lane & 15);
                int k = k16 + ((lane & 16) ? 8 : 0);
                ldsm_x4(sA0 + m * 144 + k * 2, a[mi]);
            }

#pragma unroll
            for (int nt = 0; nt < 4; nt++) {
                uint32_t b4[4];
                int k = k16 + (lane & 15);
                int n = warp_n * 64 + nt * 16 + ((lane & 16) ? 8 : 0);
                ldsm_x4_t(sB0 + k * 272 + n * 2, b4);
#pragma unroll
                for (int mi = 0; mi < 4; mi++)
#pragma unroll
                    for (int nn = 0; nn < 2; nn++)
                        mma_f16(acc[mi][2 * nt + nn], a[mi], b4 + 2 * nn);
            }
        }

        if (i + 1 < nk) {
            cp_wait<0>();
            __syncthreads();
        }
    }

    // epilogue: scale by 1/rowsum
#pragma unroll
    for (int mi = 0; mi < 4; mi++) {
        const int rloc = warp_m * 64 + mi * 16 + (lane >> 2);
        const int rbase = row0 + rloc;
        const float iv0 = inv_s[rloc];
        const float iv1 = inv_s[rloc + 8];
        float* base = out + (size_t)bz * PS * PD;
#pragma unroll
        for (int n = 0; n < 8; n++) {
            const int cb = col0 + warp_n * 64 + n * 8 + 2 * (lane & 3);
            float2 v0 = make_float2(acc[mi][n][0] * iv0, acc[mi][n][1] * iv0);
            float2 v1 = make_float2(acc[mi][n][2] * iv1, acc[mi][n][3] * iv1);
            *reinterpret_cast<float2*>(base + (size_t)rbase * PD + cb) = v0;
            *reinterpret_cast<float2*>(base + (size_t)(rbase + 8) * PD + cb) = v1;
        }
    }
}

// ---------------------------------------------------------------------------
// Merged splits: x, Wq, Wk, Wv -> plain fp16 (one launch)
// ---------------------------------------------------------------------------
struct SplitArgs {
    const float* src[4];
    __half* dst[4];
};

__global__ void __launch_bounds__(256)
split_all(SplitArgs sa)
{
    int bid = blockIdx.x;
    int which, boff;
    if (bid < 16384) { which = 0; boff = bid; }
    else { which = 1 + ((bid - 16384) >> 10); boff = (bid - 16384) & 1023; }

    size_t i = (size_t)boff * 256 + threadIdx.x;
    float4 v = reinterpret_cast<const float4*>(sa.src[which])[i];
    __half h0 = __float2half(v.x), h1 = __float2half(v.y);
    __half h2 = __float2half(v.z), h3 = __float2half(v.w);
    reinterpret_cast<uint2*>(sa.dst[which])[i] = make_uint2(pkh(h0, h1), pkh(h2, h3));
}

// ---------------------------------------------------------------------------
// Launcher
// ---------------------------------------------------------------------------
extern "C" void kernel_launch(void* const* d_in, const int* in_sizes, int n_in,
                              void* d_out, int out_size)
{
    (void)in_sizes; (void)n_in; (void)out_size;
    const float* x  = (const float*)d_in[0];
    const float* Wq = (const float*)d_in[1];
    const float* bq = (const float*)d_in[2];
    const float* Wk = (const float*)d_in[3];
    const float* bk = (const float*)d_in[4];
    const float* Wv = (const float*)d_in[5];
    const float* bv = (const float*)d_in[6];
    float* out = (float*)d_out;

    __half *x16, *Wq16, *Wk16, *Wv16, *Q16, *K16, *V16, *Pf;
    float *psum;
    cudaGetSymbolAddress((void**)&x16,  g_x16);
    cudaGetSymbolAddress((void**)&Wq16, g_Wq16);
    cudaGetSymbolAddress((void**)&Wk16, g_Wk16);
    cudaGetSymbolAddress((void**)&Wv16, g_Wv16);
    cudaGetSymbolAddress((void**)&Q16,  g_Q16);
    cudaGetSymbolAddress((void**)&K16,  g_K16);
    cudaGetSymbolAddress((void**)&V16,  g_V16);
    cudaGetSymbolAddress((void**)&Pf,   g_Pf);
    cudaGetSymbolAddress((void**)&psum, g_psum);

    cudaFuncSetAttribute((const void*)gemm_nt<0>,
                         cudaFuncAttributeMaxDynamicSharedMemorySize, NT_SMEM);
    cudaFuncSetAttribute((const void*)gemm_nt<1>,
                         cudaFuncAttributeMaxDynamicSharedMemorySize, NT_SMEM);
    cudaFuncSetAttribute((const void*)gemm_pv,
                         cudaFuncAttributeMaxDynamicSharedMemorySize, PV_SMEM);

    // 1) merged splits: x + Wq/Wk/Wv -> plain fp16
    SplitArgs sa;
    sa.src[0] = x;  sa.dst[0] = x16;
    sa.src[1] = Wq; sa.dst[1] = Wq16;
    sa.src[2] = Wk; sa.dst[2] = Wk16;
    sa.src[3] = Wv; sa.dst[3] = Wv16;
    split_all<<<16384 + 3 * 1024, 256>>>(sa);

    // 2) merged projections (fp16 1-term): z=0/1/2 -> Q/K/V plain fp16
    ProjArgs pa;
    pa.s[0] = { Wq16, bq, Q16 };
    pa.s[1] = { Wk16, bk, K16 };
    pa.s[2] = { Wv16, bv, V16 };
    ProjArgs dummy = {};
    dim3 gp(PD / 128, MROWS / 128, 3);
    gemm_nt<0><<<gp, 128, NT_SMEM>>>(x16, nullptr, pa, nullptr, nullptr);

    // 3) scores + fused exp (fp16 1-term) -> fp16 P, psum partials
    dim3 gs(PS / 128, PS / 128, PB);
    gemm_nt<1><<<gs, 128, NT_SMEM>>>(Q16, K16, dummy, Pf, psum);

    // 4) out = (P @ V) * inv   (rowsum folded into PV prologue)
    dim3 go(PD / 128, PS / 128, PB);
    gemm_pv<<<go, 128, PV_SMEM>>>(Pf, V16, out, psum);
}